// round 1
// baseline (speedup 1.0000x reference)
#include <cuda_runtime.h>
#include <math.h>

#define Bsz   32
#define Lseq  577
#define Dm    192
#define DIn   384
#define DSt   8
#define RK    12
#define NPJ   28
#define Mrows (Bsz*Lseq)   // 18464

// ---- scratch (static device allocations; no cudaMalloc allowed) ----
__device__ float g_xz[2][Mrows][2*DIn];   // in-proj output (x_part | z)
__device__ float g_xc[2][Mrows][DIn];     // conv+silu output
__device__ float g_dt[2][Mrows][DIn];     // dt after softplus
__device__ float g_bc[2][Mrows][16];      // tanh(B) (8) | tanh(C) (8)
__device__ float g_ys[2][Mrows][DIn];     // scan output * silu(z)

// =====================================================================
// K1: xz = x @ in_w.T   (per direction; bw reads x time-reversed)
// 128x128 tile, TK=16, 256 threads, 8x8 per thread
// =====================================================================
__global__ void k_gemm_in(const float* __restrict__ x,
                          const float* __restrict__ w_fw,
                          const float* __restrict__ w_bw)
{
    const int dir = blockIdx.z;
    const float* __restrict__ W = dir ? w_bw : w_fw;   // [768][192]
    const int m0 = blockIdx.x * 128;
    const int n0 = blockIdx.y * 128;

    __shared__ float As[16][128];
    __shared__ float Bs[16][128];

    const int tid = threadIdx.x;
    const int tx = tid & 15, ty = tid >> 4;

    float acc[8][8];
    #pragma unroll
    for (int i = 0; i < 8; i++)
        #pragma unroll
        for (int j = 0; j < 8; j++) acc[i][j] = 0.f;

    for (int k0 = 0; k0 < Dm; k0 += 16) {
        #pragma unroll
        for (int rep = 0; rep < 2; rep++) {
            int idx = tid + rep * 256;          // 0..511
            int r   = idx >> 2;                 // 0..127
            int kq  = (idx & 3) * 4;
            int m   = m0 + r;
            float4 v = make_float4(0.f, 0.f, 0.f, 0.f);
            if (m < Mrows) {
                int b = m / Lseq, l = m % Lseq;
                int ls = dir ? (Lseq - 1 - l) : l;
                v = *(const float4*)(x + ((size_t)b * Lseq + ls) * Dm + k0 + kq);
            }
            As[kq+0][r] = v.x; As[kq+1][r] = v.y; As[kq+2][r] = v.z; As[kq+3][r] = v.w;

            float4 w = *(const float4*)(W + (size_t)(n0 + r) * Dm + k0 + kq);
            Bs[kq+0][r] = w.x; Bs[kq+1][r] = w.y; Bs[kq+2][r] = w.z; Bs[kq+3][r] = w.w;
        }
        __syncthreads();

        #pragma unroll
        for (int kk = 0; kk < 16; kk++) {
            float a[8], bb[8];
            #pragma unroll
            for (int i = 0; i < 8; i++) a[i]  = As[kk][ty*8 + i];
            #pragma unroll
            for (int j = 0; j < 8; j++) bb[j] = Bs[kk][tx*8 + j];
            #pragma unroll
            for (int i = 0; i < 8; i++)
                #pragma unroll
                for (int j = 0; j < 8; j++)
                    acc[i][j] = fmaf(a[i], bb[j], acc[i][j]);
        }
        __syncthreads();
    }

    #pragma unroll
    for (int i = 0; i < 8; i++) {
        int m = m0 + ty*8 + i;
        if (m >= Mrows) continue;
        float* op = &g_xz[dir][m][n0 + tx*8];
        #pragma unroll
        for (int j = 0; j < 8; j++) op[j] = acc[i][j];
    }
}

// =====================================================================
// K2: causal depthwise conv (k=4) + bias + SiLU.
// One block per (chunk-of-128-channels, batch, dir), sliding window in regs.
// =====================================================================
__global__ void k_conv(const float* __restrict__ cw_fw, const float* __restrict__ cb_fw,
                       const float* __restrict__ cw_bw, const float* __restrict__ cb_bw)
{
    const int ch  = blockIdx.x * 128 + threadIdx.x;   // < 384
    const int b   = blockIdx.y;
    const int dir = blockIdx.z;

    const float* cw = (dir ? cw_bw : cw_fw) + ch * 4;
    const float w0 = cw[0], w1 = cw[1], w2 = cw[2], w3 = cw[3];
    const float bias = (dir ? cb_bw : cb_fw)[ch];

    const float* __restrict__ src = &g_xz[dir][(size_t)b * Lseq][0];  // stride 768
    float*       __restrict__ dst = &g_xc[dir][(size_t)b * Lseq][0];  // stride 384

    float x0 = 0.f, x1 = 0.f, x2 = 0.f;
    for (int l = 0; l < Lseq; l++) {
        float x3 = src[(size_t)l * (2*DIn) + ch];
        float v = fmaf(w0, x0, fmaf(w1, x1, fmaf(w2, x2, fmaf(w3, x3, bias))));
        v = v / (1.f + __expf(-v));   // silu
        dst[(size_t)l * DIn + ch] = v;
        x0 = x1; x1 = x2; x2 = x3;
    }
}

// =====================================================================
// K3: dt_bc = xc @ xproj_w.T (28 outputs); split; tanh B/C;
//     dt = softplus(dt_part @ dt_w.T + dt_b) + 1e-4.
// One warp per row; 8 warps per block.
// =====================================================================
__device__ __forceinline__ float softplus_stable(float v) {
    return v > 20.f ? v : log1pf(expf(v));
}

__global__ void k_proj(const float* __restrict__ xp_fw, const float* __restrict__ dw_fw,
                       const float* __restrict__ db_fw,
                       const float* __restrict__ xp_bw, const float* __restrict__ dw_bw,
                       const float* __restrict__ db_bw)
{
    const int warp = threadIdx.x >> 5, lane = threadIdx.x & 31;
    const long row = (long)blockIdx.x * 8 + warp;        // < 2*Mrows
    if (row >= 2L * Mrows) return;
    const int dir = row >= Mrows;
    const int m   = (int)(row - (long)dir * Mrows);

    const float* __restrict__ xpw = dir ? xp_bw : xp_fw;  // [28][384]
    const float* __restrict__ dw  = dir ? dw_bw : dw_fw;  // [384][12]
    const float* __restrict__ db  = dir ? db_bw : db_fw;  // [384]
    const float* __restrict__ rowp = g_xc[dir][m];

    float xv[12];
    #pragma unroll
    for (int i = 0; i < 12; i++) xv[i] = rowp[lane + 32*i];

    float dtp[RK];
    #pragma unroll
    for (int j = 0; j < NPJ; j++) {
        const float* wj = xpw + (size_t)j * DIn;
        float s = 0.f;
        #pragma unroll
        for (int i = 0; i < 12; i++) s = fmaf(xv[i], wj[lane + 32*i], s);
        #pragma unroll
        for (int o = 16; o; o >>= 1) s += __shfl_xor_sync(0xffffffffu, s, o);
        if (j < RK) {
            dtp[j] = s;
        } else {
            if (lane == 0) g_bc[dir][m][j - RK] = tanhf(s);
        }
    }

    // dt: each lane handles channels lane + 32*i (coalesced stores)
    #pragma unroll
    for (int i = 0; i < 12; i++) {
        int ch = lane + 32*i;
        const float* wr = dw + (size_t)ch * RK;
        float s = db[ch];
        #pragma unroll
        for (int r = 0; r < RK; r++) s = fmaf(dtp[r], wr[r], s);
        g_dt[dir][m][ch] = softplus_stable(s) + 1e-4f;
    }
}

// =====================================================================
// K4: sequential selective scan over L, fused with silu(z) gating.
// One thread per (dir, b, channel); 8 states in registers.
// =====================================================================
__global__ void k_scan(const float* __restrict__ Al_fw, const float* __restrict__ Dk_fw,
                       const float* __restrict__ Al_bw, const float* __restrict__ Dk_bw)
{
    const int ch  = blockIdx.x * 128 + threadIdx.x;   // < 384
    const int b   = blockIdx.y;
    const int dir = blockIdx.z;

    const float* Alog = (dir ? Al_bw : Al_fw) + (size_t)ch * DSt;
    float a[DSt];
    #pragma unroll
    for (int s = 0; s < DSt; s++) a[s] = -expf(Alog[s]);
    const float Dsk = (dir ? Dk_bw : Dk_fw)[ch];

    const size_t rbase = (size_t)b * Lseq;
    const float* __restrict__ dtp = &g_dt[dir][rbase][0];
    const float* __restrict__ xcp = &g_xc[dir][rbase][0];
    const float* __restrict__ zp  = &g_xz[dir][rbase][DIn];   // z half, stride 768
    const float4* __restrict__ bc4 = (const float4*)&g_bc[dir][rbase][0];
    float*       __restrict__ ysp = &g_ys[dir][rbase][0];

    float st[DSt];
    #pragma unroll
    for (int s = 0; s < DSt; s++) st[s] = 0.f;

    for (int l = 0; l < Lseq; l++) {
        const size_t off = (size_t)l * DIn + ch;
        const float dt = dtp[off];
        const float xx = xcp[off];
        float4 b0 = bc4[(size_t)l*4 + 0];
        float4 b1 = bc4[(size_t)l*4 + 1];
        float4 c0 = bc4[(size_t)l*4 + 2];
        float4 c1 = bc4[(size_t)l*4 + 3];
        const float bv[DSt] = {b0.x,b0.y,b0.z,b0.w,b1.x,b1.y,b1.z,b1.w};
        const float cv[DSt] = {c0.x,c0.y,c0.z,c0.w,c1.x,c1.y,c1.z,c1.w};

        float acc = 0.f;
        #pragma unroll
        for (int s = 0; s < DSt; s++) {
            float da = __expf(dt * a[s]);
            float db = (1.f - da) * bv[s] * xx;
            st[s] = fmaf(da, st[s], db);
            acc = fmaf(st[s], cv[s], acc);
        }
        float y = fmaf(Dsk, xx, acc);
        float z = zp[(size_t)l * (2*DIn) + ch];
        float sz = z / (1.f + __expf(-z));
        ysp[off] = y * sz;
    }
}

// =====================================================================
// K5: out = 0.5 * ( ys_fw @ ow_fw.T + flip(ys_bw) @ ow_bw.T )
// 128x64 tile, TK=16, 256 threads, 8x4 per thread; both dirs accumulated.
// =====================================================================
__global__ void k_gemm_out(const float* __restrict__ ow_fw,
                           const float* __restrict__ ow_bw,
                           float* __restrict__ out)
{
    const int m0 = blockIdx.x * 128;
    const int n0 = blockIdx.y * 64;

    __shared__ float As[16][128];
    __shared__ float Bs[16][64];

    const int tid = threadIdx.x;
    const int tx = tid & 15, ty = tid >> 4;

    float acc[8][4];
    #pragma unroll
    for (int i = 0; i < 8; i++)
        #pragma unroll
        for (int j = 0; j < 4; j++) acc[i][j] = 0.f;

    for (int dir = 0; dir < 2; dir++) {
        const float* __restrict__ A = &g_ys[dir][0][0];
        const float* __restrict__ W = dir ? ow_bw : ow_fw;  // [192][384]

        for (int k0 = 0; k0 < DIn; k0 += 16) {
            #pragma unroll
            for (int rep = 0; rep < 2; rep++) {
                int idx = tid + rep * 256;
                int r   = idx >> 2;
                int kq  = (idx & 3) * 4;
                int m   = m0 + r;
                float4 v = make_float4(0.f, 0.f, 0.f, 0.f);
                if (m < Mrows) {
                    int b = m / Lseq, l = m % Lseq;
                    int ls = dir ? (Lseq - 1 - l) : l;
                    v = *(const float4*)(A + ((size_t)b * Lseq + ls) * DIn + k0 + kq);
                }
                As[kq+0][r] = v.x; As[kq+1][r] = v.y; As[kq+2][r] = v.z; As[kq+3][r] = v.w;
            }
            {
                int r  = tid >> 2;          // 0..63
                int kq = (tid & 3) * 4;
                float4 w = *(const float4*)(W + (size_t)(n0 + r) * DIn + k0 + kq);
                Bs[kq+0][r] = w.x; Bs[kq+1][r] = w.y; Bs[kq+2][r] = w.z; Bs[kq+3][r] = w.w;
            }
            __syncthreads();

            #pragma unroll
            for (int kk = 0; kk < 16; kk++) {
                float a[8], bb[4];
                #pragma unroll
                for (int i = 0; i < 8; i++) a[i]  = As[kk][ty*8 + i];
                #pragma unroll
                for (int j = 0; j < 4; j++) bb[j] = Bs[kk][tx*4 + j];
                #pragma unroll
                for (int i = 0; i < 8; i++)
                    #pragma unroll
                    for (int j = 0; j < 4; j++)
                        acc[i][j] = fmaf(a[i], bb[j], acc[i][j]);
            }
            __syncthreads();
        }
    }

    #pragma unroll
    for (int i = 0; i < 8; i++) {
        int m = m0 + ty*8 + i;
        if (m >= Mrows) continue;
        float* op = out + (size_t)m * Dm + n0 + tx*4;
        #pragma unroll
        for (int j = 0; j < 4; j++) op[j] = 0.5f * acc[i][j];
    }
}

// =====================================================================
extern "C" void kernel_launch(void* const* d_in, const int* in_sizes, int n_in,
                              void* d_out, int out_size)
{
    const float* x        = (const float*)d_in[0];
    const float* fw_in_w  = (const float*)d_in[1];
    const float* fw_cw    = (const float*)d_in[2];
    const float* fw_cb    = (const float*)d_in[3];
    const float* fw_xpw   = (const float*)d_in[4];
    const float* fw_dtw   = (const float*)d_in[5];
    const float* fw_dtb   = (const float*)d_in[6];
    const float* fw_Alog  = (const float*)d_in[7];
    const float* fw_D     = (const float*)d_in[8];
    const float* fw_ow    = (const float*)d_in[9];
    const float* bw_in_w  = (const float*)d_in[10];
    const float* bw_cw    = (const float*)d_in[11];
    const float* bw_cb    = (const float*)d_in[12];
    const float* bw_xpw   = (const float*)d_in[13];
    const float* bw_dtw   = (const float*)d_in[14];
    const float* bw_dtb   = (const float*)d_in[15];
    const float* bw_Alog  = (const float*)d_in[16];
    const float* bw_D     = (const float*)d_in[17];
    const float* bw_ow    = (const float*)d_in[18];
    float* out = (float*)d_out;

    dim3 g1((Mrows + 127) / 128, (2*DIn) / 128, 2);     // 145 x 6 x 2
    k_gemm_in<<<g1, 256>>>(x, fw_in_w, bw_in_w);

    dim3 g2(DIn / 128, Bsz, 2);                          // 3 x 32 x 2
    k_conv<<<g2, 128>>>(fw_cw, fw_cb, bw_cw, bw_cb);

    int nrows = 2 * Mrows;
    k_proj<<<(nrows + 7) / 8, 256>>>(fw_xpw, fw_dtw, fw_dtb,
                                     bw_xpw, bw_dtw, bw_dtb);

    dim3 g4(DIn / 128, Bsz, 2);                          // 3 x 32 x 2
    k_scan<<<g4, 128>>>(fw_Alog, fw_D, bw_Alog, bw_D);

    dim3 g5((Mrows + 127) / 128, Dm / 64, 1);            // 145 x 3
    k_gemm_out<<<g5, 256>>>(fw_ow, bw_ow, out);
}

// round 2
// speedup vs baseline: 1.1383x; 1.1383x over previous
#include <cuda_runtime.h>
#include <math.h>

#define Bsz   32
#define Lseq  577
#define Dm    192
#define DIn   384
#define DSt   8
#define RK    12
#define NPJ   28
#define Mrows (Bsz*Lseq)   // 18464

// ---- scratch (static device allocations; no cudaMalloc allowed) ----
__device__ float g_xz[2][Mrows][2*DIn];   // in-proj output (x_part | z)
__device__ float g_xc[2][Mrows][DIn];     // conv+silu output
__device__ float g_dt[2][Mrows][DIn];     // dt after softplus
__device__ float g_bc[2][Mrows][16];      // tanh(B) (8) | tanh(C) (8)
__device__ float g_ys[2][Mrows][DIn];     // scan output * silu(z)

// FMA-only exp for x <= 0 (keeps MUFU free). |err| ~ 2e-8 rel.
__device__ __forceinline__ float fexp_neg(float x)
{
    x = fmaxf(x, -80.f);
    float z  = x * 1.4426950408889634f;          // x * log2(e)
    float fi = (z + 12582912.0f) - 12582912.0f;  // round-to-nearest int (magic)
    float f  = z - fi;                           // f in [-0.5, 0.5]
    float p  = 1.5403530e-4f;
    p = fmaf(p, f, 1.3333558e-3f);
    p = fmaf(p, f, 9.6181291e-3f);
    p = fmaf(p, f, 5.5504109e-2f);
    p = fmaf(p, f, 2.4022651e-1f);
    p = fmaf(p, f, 6.9314718e-1f);
    p = fmaf(p, f, 1.0f);                        // 2^f
    int ie = (int)fi;
    return __int_as_float(__float_as_int(p) + (ie << 23));
}

// =====================================================================
// K1: xz = x @ in_w.T   (per direction; bw reads x time-reversed)
// =====================================================================
__global__ void k_gemm_in(const float* __restrict__ x,
                          const float* __restrict__ w_fw,
                          const float* __restrict__ w_bw)
{
    const int dir = blockIdx.z;
    const float* __restrict__ W = dir ? w_bw : w_fw;   // [768][192]
    const int m0 = blockIdx.x * 128;
    const int n0 = blockIdx.y * 128;

    __shared__ float As[16][128];
    __shared__ float Bs[16][128];

    const int tid = threadIdx.x;
    const int tx = tid & 15, ty = tid >> 4;

    float acc[8][8];
    #pragma unroll
    for (int i = 0; i < 8; i++)
        #pragma unroll
        for (int j = 0; j < 8; j++) acc[i][j] = 0.f;

    for (int k0 = 0; k0 < Dm; k0 += 16) {
        #pragma unroll
        for (int rep = 0; rep < 2; rep++) {
            int idx = tid + rep * 256;          // 0..511
            int r   = idx >> 2;                 // 0..127
            int kq  = (idx & 3) * 4;
            int m   = m0 + r;
            float4 v = make_float4(0.f, 0.f, 0.f, 0.f);
            if (m < Mrows) {
                int b = m / Lseq, l = m % Lseq;
                int ls = dir ? (Lseq - 1 - l) : l;
                v = *(const float4*)(x + ((size_t)b * Lseq + ls) * Dm + k0 + kq);
            }
            As[kq+0][r] = v.x; As[kq+1][r] = v.y; As[kq+2][r] = v.z; As[kq+3][r] = v.w;

            float4 w = *(const float4*)(W + (size_t)(n0 + r) * Dm + k0 + kq);
            Bs[kq+0][r] = w.x; Bs[kq+1][r] = w.y; Bs[kq+2][r] = w.z; Bs[kq+3][r] = w.w;
        }
        __syncthreads();

        #pragma unroll
        for (int kk = 0; kk < 16; kk++) {
            float a[8], bb[8];
            #pragma unroll
            for (int i = 0; i < 8; i++) a[i]  = As[kk][ty*8 + i];
            #pragma unroll
            for (int j = 0; j < 8; j++) bb[j] = Bs[kk][tx*8 + j];
            #pragma unroll
            for (int i = 0; i < 8; i++)
                #pragma unroll
                for (int j = 0; j < 8; j++)
                    acc[i][j] = fmaf(a[i], bb[j], acc[i][j]);
        }
        __syncthreads();
    }

    #pragma unroll
    for (int i = 0; i < 8; i++) {
        int m = m0 + ty*8 + i;
        if (m >= Mrows) continue;
        float* op = &g_xz[dir][m][n0 + tx*8];
        #pragma unroll
        for (int j = 0; j < 8; j++) op[j] = acc[i][j];
    }
}

// =====================================================================
// K2: causal depthwise conv (k=4) + bias + SiLU, parallel over L.
// Each thread: one channel, 8 consecutive timesteps (register window).
// grid (3, ceil(577/8)=73, 64=b*dir), block 128.
// =====================================================================
#define LCH 8
__global__ void k_conv(const float* __restrict__ cw_fw, const float* __restrict__ cb_fw,
                       const float* __restrict__ cw_bw, const float* __restrict__ cb_bw)
{
    const int ch  = blockIdx.x * 128 + threadIdx.x;   // < 384
    const int l0  = blockIdx.y * LCH;
    const int b   = blockIdx.z & 31;
    const int dir = blockIdx.z >> 5;

    const float* cw = (dir ? cw_bw : cw_fw) + ch * 4;
    const float w0 = cw[0], w1 = cw[1], w2 = cw[2], w3 = cw[3];
    const float bias = (dir ? cb_bw : cb_fw)[ch];

    const float* __restrict__ src = &g_xz[dir][(size_t)b * Lseq][0];  // stride 768
    float*       __restrict__ dst = &g_xc[dir][(size_t)b * Lseq][0];  // stride 384

    float x0 = (l0 >= 3) ? src[(size_t)(l0-3) * (2*DIn) + ch] : 0.f;
    float x1 = (l0 >= 2) ? src[(size_t)(l0-2) * (2*DIn) + ch] : 0.f;
    float x2 = (l0 >= 1) ? src[(size_t)(l0-1) * (2*DIn) + ch] : 0.f;

    #pragma unroll
    for (int i = 0; i < LCH; i++) {
        int l = l0 + i;
        if (l >= Lseq) break;
        float x3 = src[(size_t)l * (2*DIn) + ch];
        float v = fmaf(w0, x0, fmaf(w1, x1, fmaf(w2, x2, fmaf(w3, x3, bias))));
        v = v / (1.f + __expf(-v));   // silu
        dst[(size_t)l * DIn + ch] = v;
        x0 = x1; x1 = x2; x2 = x3;
    }
}

// =====================================================================
// K3: dt_bc = xc @ xproj_w.T (28); tanh B/C; dt = softplus(lowrank)+1e-4
// =====================================================================
__device__ __forceinline__ float softplus_stable(float v) {
    return v > 20.f ? v : log1pf(expf(v));
}

__global__ void k_proj(const float* __restrict__ xp_fw, const float* __restrict__ dw_fw,
                       const float* __restrict__ db_fw,
                       const float* __restrict__ xp_bw, const float* __restrict__ dw_bw,
                       const float* __restrict__ db_bw)
{
    const int warp = threadIdx.x >> 5, lane = threadIdx.x & 31;
    const long row = (long)blockIdx.x * 8 + warp;        // < 2*Mrows
    if (row >= 2L * Mrows) return;
    const int dir = row >= Mrows;
    const int m   = (int)(row - (long)dir * Mrows);

    const float* __restrict__ xpw = dir ? xp_bw : xp_fw;  // [28][384]
    const float* __restrict__ dw  = dir ? dw_bw : dw_fw;  // [384][12]
    const float* __restrict__ db  = dir ? db_bw : db_fw;  // [384]
    const float* __restrict__ rowp = g_xc[dir][m];

    float xv[12];
    #pragma unroll
    for (int i = 0; i < 12; i++) xv[i] = rowp[lane + 32*i];

    float dtp[RK];
    #pragma unroll
    for (int j = 0; j < NPJ; j++) {
        const float* wj = xpw + (size_t)j * DIn;
        float s = 0.f;
        #pragma unroll
        for (int i = 0; i < 12; i++) s = fmaf(xv[i], wj[lane + 32*i], s);
        #pragma unroll
        for (int o = 16; o; o >>= 1) s += __shfl_xor_sync(0xffffffffu, s, o);
        if (j < RK) {
            dtp[j] = s;
        } else {
            if (lane == 0) g_bc[dir][m][j - RK] = tanhf(s);
        }
    }

    #pragma unroll
    for (int i = 0; i < 12; i++) {
        int ch = lane + 32*i;
        const float* wr = dw + (size_t)ch * RK;
        float s = db[ch];
        #pragma unroll
        for (int r = 0; r < RK; r++) s = fmaf(dtp[r], wr[r], s);
        g_dt[dir][m][ch] = softplus_stable(s) + 1e-4f;
    }
}

// =====================================================================
// K4: selective scan, one thread per (dir,b,channel,state).
// Warp = 4 channels x 8 states. y-reduce over 8-lane groups via shfl.
// grid (24, 32, 2), block 128 -> 196608 threads.
// =====================================================================
__global__ void k_scan(const float* __restrict__ Al_fw, const float* __restrict__ Dk_fw,
                       const float* __restrict__ Al_bw, const float* __restrict__ Dk_bw)
{
    const int tid = threadIdx.x;
    const int s   = tid & 7;                       // state
    const int ch  = blockIdx.x * 16 + (tid >> 3);  // channel, < 384
    const int b   = blockIdx.y;
    const int dir = blockIdx.z;

    const float* Alog = (dir ? Al_bw : Al_fw);
    const float a   = -expf(Alog[(size_t)ch * DSt + s]);
    const float Dsk = (dir ? Dk_bw : Dk_fw)[ch];

    const size_t rbase = (size_t)b * Lseq;
    const float* __restrict__ dtp = &g_dt[dir][rbase][0];
    const float* __restrict__ xcp = &g_xc[dir][rbase][0];
    const float* __restrict__ zp  = &g_xz[dir][rbase][DIn];   // z half, stride 768
    const float* __restrict__ bcp = &g_bc[dir][rbase][0];
    float*       __restrict__ ysp = &g_ys[dir][rbase][0];

    float st = 0.f;

    // software-pipelined loads
    float dt = dtp[ch];
    float xx = xcp[ch];
    float bv = bcp[s];
    float cv = bcp[8 + s];
    float zz = zp[ch];

    for (int l = 0; l < Lseq; l++) {
        float dtn = 0.f, xxn = 0.f, bvn = 0.f, cvn = 0.f, zzn = 0.f;
        if (l + 1 < Lseq) {
            const size_t o = (size_t)(l+1) * DIn + ch;
            dtn = dtp[o];
            xxn = xcp[o];
            bvn = bcp[(size_t)(l+1)*16 + s];
            cvn = bcp[(size_t)(l+1)*16 + 8 + s];
            zzn = zp[(size_t)(l+1) * (2*DIn) + ch];
        }

        float da = fexp_neg(dt * a);
        float db = (1.f - da) * bv * xx;
        st = fmaf(da, st, db);

        float p = st * cv;
        p += __shfl_xor_sync(0xffffffffu, p, 1);
        p += __shfl_xor_sync(0xffffffffu, p, 2);
        p += __shfl_xor_sync(0xffffffffu, p, 4);

        if (s == 0) {
            float y  = fmaf(Dsk, xx, p);
            float sz = zz / (1.f + __expf(-zz));
            ysp[(size_t)l * DIn + ch] = y * sz;
        }

        dt = dtn; xx = xxn; bv = bvn; cv = cvn; zz = zzn;
    }
}

// =====================================================================
// K5: out = 0.5 * ( ys_fw @ ow_fw.T + flip(ys_bw) @ ow_bw.T )
// =====================================================================
__global__ void k_gemm_out(const float* __restrict__ ow_fw,
                           const float* __restrict__ ow_bw,
                           float* __restrict__ out)
{
    const int m0 = blockIdx.x * 128;
    const int n0 = blockIdx.y * 64;

    __shared__ float As[16][128];
    __shared__ float Bs[16][64];

    const int tid = threadIdx.x;
    const int tx = tid & 15, ty = tid >> 4;

    float acc[8][4];
    #pragma unroll
    for (int i = 0; i < 8; i++)
        #pragma unroll
        for (int j = 0; j < 4; j++) acc[i][j] = 0.f;

    for (int dir = 0; dir < 2; dir++) {
        const float* __restrict__ A = &g_ys[dir][0][0];
        const float* __restrict__ W = dir ? ow_bw : ow_fw;  // [192][384]

        for (int k0 = 0; k0 < DIn; k0 += 16) {
            #pragma unroll
            for (int rep = 0; rep < 2; rep++) {
                int idx = tid + rep * 256;
                int r   = idx >> 2;
                int kq  = (idx & 3) * 4;
                int m   = m0 + r;
                float4 v = make_float4(0.f, 0.f, 0.f, 0.f);
                if (m < Mrows) {
                    int b = m / Lseq, l = m % Lseq;
                    int ls = dir ? (Lseq - 1 - l) : l;
                    v = *(const float4*)(A + ((size_t)b * Lseq + ls) * DIn + k0 + kq);
                }
                As[kq+0][r] = v.x; As[kq+1][r] = v.y; As[kq+2][r] = v.z; As[kq+3][r] = v.w;
            }
            {
                int r  = tid >> 2;          // 0..63
                int kq = (tid & 3) * 4;
                float4 w = *(const float4*)(W + (size_t)(n0 + r) * DIn + k0 + kq);
                Bs[kq+0][r] = w.x; Bs[kq+1][r] = w.y; Bs[kq+2][r] = w.z; Bs[kq+3][r] = w.w;
            }
            __syncthreads();

            #pragma unroll
            for (int kk = 0; kk < 16; kk++) {
                float a[8], bb[4];
                #pragma unroll
                for (int i = 0; i < 8; i++) a[i]  = As[kk][ty*8 + i];
                #pragma unroll
                for (int j = 0; j < 4; j++) bb[j] = Bs[kk][tx*4 + j];
                #pragma unroll
                for (int i = 0; i < 8; i++)
                    #pragma unroll
                    for (int j = 0; j < 4; j++)
                        acc[i][j] = fmaf(a[i], bb[j], acc[i][j]);
            }
            __syncthreads();
        }
    }

    #pragma unroll
    for (int i = 0; i < 8; i++) {
        int m = m0 + ty*8 + i;
        if (m >= Mrows) continue;
        float* op = out + (size_t)m * Dm + n0 + tx*4;
        #pragma unroll
        for (int j = 0; j < 4; j++) op[j] = 0.5f * acc[i][j];
    }
}

// =====================================================================
extern "C" void kernel_launch(void* const* d_in, const int* in_sizes, int n_in,
                              void* d_out, int out_size)
{
    const float* x        = (const float*)d_in[0];
    const float* fw_in_w  = (const float*)d_in[1];
    const float* fw_cw    = (const float*)d_in[2];
    const float* fw_cb    = (const float*)d_in[3];
    const float* fw_xpw   = (const float*)d_in[4];
    const float* fw_dtw   = (const float*)d_in[5];
    const float* fw_dtb   = (const float*)d_in[6];
    const float* fw_Alog  = (const float*)d_in[7];
    const float* fw_D     = (const float*)d_in[8];
    const float* fw_ow    = (const float*)d_in[9];
    const float* bw_in_w  = (const float*)d_in[10];
    const float* bw_cw    = (const float*)d_in[11];
    const float* bw_cb    = (const float*)d_in[12];
    const float* bw_xpw   = (const float*)d_in[13];
    const float* bw_dtw   = (const float*)d_in[14];
    const float* bw_dtb   = (const float*)d_in[15];
    const float* bw_Alog  = (const float*)d_in[16];
    const float* bw_D     = (const float*)d_in[17];
    const float* bw_ow    = (const float*)d_in[18];
    float* out = (float*)d_out;

    dim3 g1((Mrows + 127) / 128, (2*DIn) / 128, 2);     // 145 x 6 x 2
    k_gemm_in<<<g1, 256>>>(x, fw_in_w, bw_in_w);

    dim3 g2(DIn / 128, (Lseq + LCH - 1) / LCH, 2 * Bsz); // 3 x 73 x 64
    k_conv<<<g2, 128>>>(fw_cw, fw_cb, bw_cw, bw_cb);

    int nrows = 2 * Mrows;
    k_proj<<<(nrows + 7) / 8, 256>>>(fw_xpw, fw_dtw, fw_dtb,
                                     bw_xpw, bw_dtw, bw_dtb);

    dim3 g4(DIn / 16, Bsz, 2);                           // 24 x 32 x 2
    k_scan<<<g4, 128>>>(fw_Alog, fw_D, bw_Alog, bw_D);

    dim3 g5((Mrows + 127) / 128, Dm / 64, 1);            // 145 x 3
    k_gemm_out<<<g5, 256>>>(fw_ow, bw_ow, out);
}

// round 3
// speedup vs baseline: 1.5305x; 1.3445x over previous
#include <cuda_runtime.h>
#include <math.h>

#define Bsz   32
#define Lseq  577
#define Dm    192
#define DIn   384
#define DSt   8
#define RK    12
#define NPJ   28
#define Mrows (Bsz*Lseq)   // 18464
#define NCH   8            // scan chunks
#define CLEN  73           // 8*73 = 584 >= 577

// ---- scratch ----
__device__ float g_xz[2][Mrows][2*DIn];   // in-proj output (x_part | z)
__device__ float g_xc[2][Mrows][DIn];     // conv+silu output
__device__ float g_dt[2][Mrows][DIn];     // dt after softplus
__device__ float g_bc[2][Mrows][16];      // tanh(B) (8) | tanh(C) (8)
__device__ float g_ys[2][Mrows][DIn];     // scan output * silu(z)
__device__ float g_tr[2][Bsz][DIn][NCH][16]; // chunk transfer: Aprod[8] | Bacc[8]

// FMA-only exp for x <= 0 (keeps MUFU free).
__device__ __forceinline__ float fexp_neg(float x)
{
    x = fmaxf(x, -80.f);
    float z  = x * 1.4426950408889634f;
    float fi = (z + 12582912.0f) - 12582912.0f;
    float f  = z - fi;
    float p  = 1.5403530e-4f;
    p = fmaf(p, f, 1.3333558e-3f);
    p = fmaf(p, f, 9.6181291e-3f);
    p = fmaf(p, f, 5.5504109e-2f);
    p = fmaf(p, f, 2.4022651e-1f);
    p = fmaf(p, f, 6.9314718e-1f);
    p = fmaf(p, f, 1.0f);
    int ie = (int)fi;
    return __int_as_float(__float_as_int(p) + (ie << 23));
}

// =====================================================================
// K1: xz = x @ in_w.T
// =====================================================================
__global__ void k_gemm_in(const float* __restrict__ x,
                          const float* __restrict__ w_fw,
                          const float* __restrict__ w_bw)
{
    const int dir = blockIdx.z;
    const float* __restrict__ W = dir ? w_bw : w_fw;   // [768][192]
    const int m0 = blockIdx.x * 128;
    const int n0 = blockIdx.y * 128;

    __shared__ float As[16][128];
    __shared__ float Bs[16][128];

    const int tid = threadIdx.x;
    const int tx = tid & 15, ty = tid >> 4;

    float acc[8][8];
    #pragma unroll
    for (int i = 0; i < 8; i++)
        #pragma unroll
        for (int j = 0; j < 8; j++) acc[i][j] = 0.f;

    for (int k0 = 0; k0 < Dm; k0 += 16) {
        #pragma unroll
        for (int rep = 0; rep < 2; rep++) {
            int idx = tid + rep * 256;
            int r   = idx >> 2;
            int kq  = (idx & 3) * 4;
            int m   = m0 + r;
            float4 v = make_float4(0.f, 0.f, 0.f, 0.f);
            if (m < Mrows) {
                int b = m / Lseq, l = m % Lseq;
                int ls = dir ? (Lseq - 1 - l) : l;
                v = *(const float4*)(x + ((size_t)b * Lseq + ls) * Dm + k0 + kq);
            }
            As[kq+0][r] = v.x; As[kq+1][r] = v.y; As[kq+2][r] = v.z; As[kq+3][r] = v.w;

            float4 w = *(const float4*)(W + (size_t)(n0 + r) * Dm + k0 + kq);
            Bs[kq+0][r] = w.x; Bs[kq+1][r] = w.y; Bs[kq+2][r] = w.z; Bs[kq+3][r] = w.w;
        }
        __syncthreads();

        #pragma unroll
        for (int kk = 0; kk < 16; kk++) {
            float a[8], bb[8];
            #pragma unroll
            for (int i = 0; i < 8; i++) a[i]  = As[kk][ty*8 + i];
            #pragma unroll
            for (int j = 0; j < 8; j++) bb[j] = Bs[kk][tx*8 + j];
            #pragma unroll
            for (int i = 0; i < 8; i++)
                #pragma unroll
                for (int j = 0; j < 8; j++)
                    acc[i][j] = fmaf(a[i], bb[j], acc[i][j]);
        }
        __syncthreads();
    }

    #pragma unroll
    for (int i = 0; i < 8; i++) {
        int m = m0 + ty*8 + i;
        if (m >= Mrows) continue;
        float* op = &g_xz[dir][m][n0 + tx*8];
        #pragma unroll
        for (int j = 0; j < 8; j++) op[j] = acc[i][j];
    }
}

// =====================================================================
// K2: causal depthwise conv (k=4) + bias + SiLU, parallel over L.
// =====================================================================
#define LCH 8
__global__ void k_conv(const float* __restrict__ cw_fw, const float* __restrict__ cb_fw,
                       const float* __restrict__ cw_bw, const float* __restrict__ cb_bw)
{
    const int ch  = blockIdx.x * 128 + threadIdx.x;
    const int l0  = blockIdx.y * LCH;
    const int b   = blockIdx.z & 31;
    const int dir = blockIdx.z >> 5;

    const float* cw = (dir ? cw_bw : cw_fw) + ch * 4;
    const float w0 = cw[0], w1 = cw[1], w2 = cw[2], w3 = cw[3];
    const float bias = (dir ? cb_bw : cb_fw)[ch];

    const float* __restrict__ src = &g_xz[dir][(size_t)b * Lseq][0];
    float*       __restrict__ dst = &g_xc[dir][(size_t)b * Lseq][0];

    float x0 = (l0 >= 3) ? src[(size_t)(l0-3) * (2*DIn) + ch] : 0.f;
    float x1 = (l0 >= 2) ? src[(size_t)(l0-2) * (2*DIn) + ch] : 0.f;
    float x2 = (l0 >= 1) ? src[(size_t)(l0-1) * (2*DIn) + ch] : 0.f;

    #pragma unroll
    for (int i = 0; i < LCH; i++) {
        int l = l0 + i;
        if (l >= Lseq) break;
        float x3 = src[(size_t)l * (2*DIn) + ch];
        float v = fmaf(w0, x0, fmaf(w1, x1, fmaf(w2, x2, fmaf(w3, x3, bias))));
        v = v / (1.f + __expf(-v));
        dst[(size_t)l * DIn + ch] = v;
        x0 = x1; x1 = x2; x2 = x3;
    }
}

// =====================================================================
// K3: x_proj + tanh(B,C) + dt lowrank + softplus
// =====================================================================
__device__ __forceinline__ float softplus_stable(float v) {
    return v > 20.f ? v : log1pf(expf(v));
}

__global__ void k_proj(const float* __restrict__ xp_fw, const float* __restrict__ dw_fw,
                       const float* __restrict__ db_fw,
                       const float* __restrict__ xp_bw, const float* __restrict__ dw_bw,
                       const float* __restrict__ db_bw)
{
    const int warp = threadIdx.x >> 5, lane = threadIdx.x & 31;
    const long row = (long)blockIdx.x * 8 + warp;
    if (row >= 2L * Mrows) return;
    const int dir = row >= Mrows;
    const int m   = (int)(row - (long)dir * Mrows);

    const float* __restrict__ xpw = dir ? xp_bw : xp_fw;
    const float* __restrict__ dw  = dir ? dw_bw : dw_fw;
    const float* __restrict__ db  = dir ? db_bw : db_fw;
    const float* __restrict__ rowp = g_xc[dir][m];

    float xv[12];
    #pragma unroll
    for (int i = 0; i < 12; i++) xv[i] = rowp[lane + 32*i];

    float dtp[RK];
    #pragma unroll
    for (int j = 0; j < NPJ; j++) {
        const float* wj = xpw + (size_t)j * DIn;
        float s = 0.f;
        #pragma unroll
        for (int i = 0; i < 12; i++) s = fmaf(xv[i], wj[lane + 32*i], s);
        #pragma unroll
        for (int o = 16; o; o >>= 1) s += __shfl_xor_sync(0xffffffffu, s, o);
        if (j < RK) {
            dtp[j] = s;
        } else {
            if (lane == 0) g_bc[dir][m][j - RK] = tanhf(s);
        }
    }

    #pragma unroll
    for (int i = 0; i < 12; i++) {
        int ch = lane + 32*i;
        const float* wr = dw + (size_t)ch * RK;
        float s = db[ch];
        #pragma unroll
        for (int r = 0; r < RK; r++) s = fmaf(dtp[r], wr[r], s);
        g_dt[dir][m][ch] = softplus_stable(s) + 1e-4f;
    }
}

// =====================================================================
// K4a: scan phase 1 — per (dir,b,ch,chunk): chunk transfer (Aprod, Bacc)
// grid (3, NCH, 64), block 128
// =====================================================================
__global__ void k_scan1(const float* __restrict__ Al_fw, const float* __restrict__ Al_bw)
{
    const int ch    = blockIdx.x * 128 + threadIdx.x;
    const int chunk = blockIdx.y;
    const int b     = blockIdx.z & 31;
    const int dir   = blockIdx.z >> 5;

    const float* Alog = (dir ? Al_bw : Al_fw) + (size_t)ch * DSt;
    float a[DSt];
    #pragma unroll
    for (int s = 0; s < DSt; s++) a[s] = -expf(Alog[s]);

    const size_t rbase = (size_t)b * Lseq;
    const float* __restrict__ dtp = &g_dt[dir][rbase][0];
    const float* __restrict__ xcp = &g_xc[dir][rbase][0];
    const float4* __restrict__ bc4 = (const float4*)&g_bc[dir][rbase][0];

    const int l0 = chunk * CLEN;
    const int l1 = min(l0 + CLEN, Lseq);

    float st[DSt], Ap[DSt];
    #pragma unroll
    for (int s = 0; s < DSt; s++) { st[s] = 0.f; Ap[s] = 1.f; }

    for (int l = l0; l < l1; l++) {
        const size_t off = (size_t)l * DIn + ch;
        const float dt = dtp[off];
        const float xx = xcp[off];
        float4 b0 = bc4[(size_t)l*4 + 0];
        float4 b1 = bc4[(size_t)l*4 + 1];
        const float bv[DSt] = {b0.x,b0.y,b0.z,b0.w,b1.x,b1.y,b1.z,b1.w};

        #pragma unroll
        for (int s = 0; s < DSt; s++) {
            float da = fexp_neg(dt * a[s]);
            st[s] = fmaf(da, st[s], (1.f - da) * bv[s] * xx);
            Ap[s] *= da;
        }
    }

    float* tr = &g_tr[dir][b][ch][chunk][0];
    #pragma unroll
    for (int s = 0; s < DSt; s++) { tr[s] = Ap[s]; tr[8 + s] = st[s]; }
}

// =====================================================================
// K4b: scan phase 2+3 — compose init from preceding transfers, replay
// chunk computing y * silu(z).
// =====================================================================
__global__ void k_scan2(const float* __restrict__ Al_fw, const float* __restrict__ Dk_fw,
                        const float* __restrict__ Al_bw, const float* __restrict__ Dk_bw)
{
    const int ch    = blockIdx.x * 128 + threadIdx.x;
    const int chunk = blockIdx.y;
    const int b     = blockIdx.z & 31;
    const int dir   = blockIdx.z >> 5;

    const float* Alog = (dir ? Al_bw : Al_fw) + (size_t)ch * DSt;
    float a[DSt];
    #pragma unroll
    for (int s = 0; s < DSt; s++) a[s] = -expf(Alog[s]);
    const float Dsk = (dir ? Dk_bw : Dk_fw)[ch];

    // compose initial state from chunks 0..chunk-1
    float st[DSt];
    #pragma unroll
    for (int s = 0; s < DSt; s++) st[s] = 0.f;
    {
        const float* tr = &g_tr[dir][b][ch][0][0];
        for (int c = 0; c < chunk; c++) {
            const float* t = tr + c * 16;
            #pragma unroll
            for (int s = 0; s < DSt; s++)
                st[s] = fmaf(t[s], st[s], t[8 + s]);
        }
    }

    const size_t rbase = (size_t)b * Lseq;
    const float* __restrict__ dtp = &g_dt[dir][rbase][0];
    const float* __restrict__ xcp = &g_xc[dir][rbase][0];
    const float* __restrict__ zp  = &g_xz[dir][rbase][DIn];
    const float4* __restrict__ bc4 = (const float4*)&g_bc[dir][rbase][0];
    float*       __restrict__ ysp = &g_ys[dir][rbase][0];

    const int l0 = chunk * CLEN;
    const int l1 = min(l0 + CLEN, Lseq);

    for (int l = l0; l < l1; l++) {
        const size_t off = (size_t)l * DIn + ch;
        const float dt = dtp[off];
        const float xx = xcp[off];
        float4 b0 = bc4[(size_t)l*4 + 0];
        float4 b1 = bc4[(size_t)l*4 + 1];
        float4 c0 = bc4[(size_t)l*4 + 2];
        float4 c1 = bc4[(size_t)l*4 + 3];
        const float bv[DSt] = {b0.x,b0.y,b0.z,b0.w,b1.x,b1.y,b1.z,b1.w};
        const float cv[DSt] = {c0.x,c0.y,c0.z,c0.w,c1.x,c1.y,c1.z,c1.w};

        float acc = 0.f;
        #pragma unroll
        for (int s = 0; s < DSt; s++) {
            float da = fexp_neg(dt * a[s]);
            st[s] = fmaf(da, st[s], (1.f - da) * bv[s] * xx);
            acc = fmaf(st[s], cv[s], acc);
        }
        float y = fmaf(Dsk, xx, acc);
        float z = zp[(size_t)l * (2*DIn) + ch];
        float sz = z / (1.f + __expf(-z));
        ysp[off] = y * sz;
    }
}

// =====================================================================
// K5: out = 0.5 * ( ys_fw @ ow_fw.T + flip(ys_bw) @ ow_bw.T )
// =====================================================================
__global__ void k_gemm_out(const float* __restrict__ ow_fw,
                           const float* __restrict__ ow_bw,
                           float* __restrict__ out)
{
    const int m0 = blockIdx.x * 128;
    const int n0 = blockIdx.y * 64;

    __shared__ float As[16][128];
    __shared__ float Bs[16][64];

    const int tid = threadIdx.x;
    const int tx = tid & 15, ty = tid >> 4;

    float acc[8][4];
    #pragma unroll
    for (int i = 0; i < 8; i++)
        #pragma unroll
        for (int j = 0; j < 4; j++) acc[i][j] = 0.f;

    for (int dir = 0; dir < 2; dir++) {
        const float* __restrict__ A = &g_ys[dir][0][0];
        const float* __restrict__ W = dir ? ow_bw : ow_fw;

        for (int k0 = 0; k0 < DIn; k0 += 16) {
            #pragma unroll
            for (int rep = 0; rep < 2; rep++) {
                int idx = tid + rep * 256;
                int r   = idx >> 2;
                int kq  = (idx & 3) * 4;
                int m   = m0 + r;
                float4 v = make_float4(0.f, 0.f, 0.f, 0.f);
                if (m < Mrows) {
                    int b = m / Lseq, l = m % Lseq;
                    int ls = dir ? (Lseq - 1 - l) : l;
                    v = *(const float4*)(A + ((size_t)b * Lseq + ls) * DIn + k0 + kq);
                }
                As[kq+0][r] = v.x; As[kq+1][r] = v.y; As[kq+2][r] = v.z; As[kq+3][r] = v.w;
            }
            {
                int r  = tid >> 2;
                int kq = (tid & 3) * 4;
                float4 w = *(const float4*)(W + (size_t)(n0 + r) * DIn + k0 + kq);
                Bs[kq+0][r] = w.x; Bs[kq+1][r] = w.y; Bs[kq+2][r] = w.z; Bs[kq+3][r] = w.w;
            }
            __syncthreads();

            #pragma unroll
            for (int kk = 0; kk < 16; kk++) {
                float a[8], bb[4];
                #pragma unroll
                for (int i = 0; i < 8; i++) a[i]  = As[kk][ty*8 + i];
                #pragma unroll
                for (int j = 0; j < 4; j++) bb[j] = Bs[kk][tx*4 + j];
                #pragma unroll
                for (int i = 0; i < 8; i++)
                    #pragma unroll
                    for (int j = 0; j < 4; j++)
                        acc[i][j] = fmaf(a[i], bb[j], acc[i][j]);
            }
            __syncthreads();
        }
    }

    #pragma unroll
    for (int i = 0; i < 8; i++) {
        int m = m0 + ty*8 + i;
        if (m >= Mrows) continue;
        float* op = out + (size_t)m * Dm + n0 + tx*4;
        #pragma unroll
        for (int j = 0; j < 4; j++) op[j] = 0.5f * acc[i][j];
    }
}

// =====================================================================
extern "C" void kernel_launch(void* const* d_in, const int* in_sizes, int n_in,
                              void* d_out, int out_size)
{
    const float* x        = (const float*)d_in[0];
    const float* fw_in_w  = (const float*)d_in[1];
    const float* fw_cw    = (const float*)d_in[2];
    const float* fw_cb    = (const float*)d_in[3];
    const float* fw_xpw   = (const float*)d_in[4];
    const float* fw_dtw   = (const float*)d_in[5];
    const float* fw_dtb   = (const float*)d_in[6];
    const float* fw_Alog  = (const float*)d_in[7];
    const float* fw_D     = (const float*)d_in[8];
    const float* fw_ow    = (const float*)d_in[9];
    const float* bw_in_w  = (const float*)d_in[10];
    const float* bw_cw    = (const float*)d_in[11];
    const float* bw_cb    = (const float*)d_in[12];
    const float* bw_xpw   = (const float*)d_in[13];
    const float* bw_dtw   = (const float*)d_in[14];
    const float* bw_dtb   = (const float*)d_in[15];
    const float* bw_Alog  = (const float*)d_in[16];
    const float* bw_D     = (const float*)d_in[17];
    const float* bw_ow    = (const float*)d_in[18];
    float* out = (float*)d_out;

    dim3 g1((Mrows + 127) / 128, (2*DIn) / 128, 2);
    k_gemm_in<<<g1, 256>>>(x, fw_in_w, bw_in_w);

    dim3 g2(DIn / 128, (Lseq + LCH - 1) / LCH, 2 * Bsz);
    k_conv<<<g2, 128>>>(fw_cw, fw_cb, bw_cw, bw_cb);

    int nrows = 2 * Mrows;
    k_proj<<<(nrows + 7) / 8, 256>>>(fw_xpw, fw_dtw, fw_dtb,
                                     bw_xpw, bw_dtw, bw_dtb);

    dim3 g4(DIn / 128, NCH, 2 * Bsz);      // 3 x 8 x 64
    k_scan1<<<g4, 128>>>(fw_Alog, bw_Alog);
    k_scan2<<<g4, 128>>>(fw_Alog, fw_D, bw_Alog, bw_D);

    dim3 g5((Mrows + 127) / 128, Dm / 64, 1);
    k_gemm_out<<<g5, 256>>>(fw_ow, bw_ow, out);
}

// round 6
// speedup vs baseline: 2.2735x; 1.4855x over previous
#include <cuda_runtime.h>
#include <cuda_bf16.h>
#include <cstdint>
#include <cstddef>
#include <math.h>

#define Bsz   32
#define Lseq  577
#define Dm    192
#define DIn   384
#define DSt   8
#define RK    12
#define NPJ   28
#define Mrows (Bsz*Lseq)   // 18464
#define NCH   8            // scan chunks
#define CLEN  73           // 8*73 = 584 >= 577

// bw-direction intermediates stored at PHYSICAL sequence index (unflipped):
// GEMMs need no flips; conv mirrors its window; scans walk backwards for bw.

// ---- scratch ----
__device__ float g_xz[2][Mrows][2*DIn];   // in-proj output (x_part | z)
__device__ float g_xc[2][Mrows][DIn];     // conv+silu output
__device__ float g_dt[2][Mrows][DIn];     // dt after softplus
__device__ float g_bc[2][Mrows][16];      // tanh(B) (8) | tanh(C) (8)
__device__ float g_ys[2][Mrows][DIn];     // scan output * silu(z)
__device__ float g_tr[2][Bsz][DIn][NCH][16]; // chunk transfer: Aprod[8] | Bacc[8]

// FMA-only exp for x <= 0 (keeps MUFU free).
__device__ __forceinline__ float fexp_neg(float x)
{
    x = fmaxf(x, -80.f);
    float z  = x * 1.4426950408889634f;
    float fi = (z + 12582912.0f) - 12582912.0f;
    float f  = z - fi;
    float p  = 1.5403530e-4f;
    p = fmaf(p, f, 1.3333558e-3f);
    p = fmaf(p, f, 9.6181291e-3f);
    p = fmaf(p, f, 5.5504109e-2f);
    p = fmaf(p, f, 2.4022651e-1f);
    p = fmaf(p, f, 6.9314718e-1f);
    p = fmaf(p, f, 1.0f);
    int ie = (int)fi;
    return __int_as_float(__float_as_int(p) + (ie << 23));
}

// ---- tensor-core helpers ----
__device__ __forceinline__ unsigned smem_u32(const void* p) {
    return (unsigned)__cvta_generic_to_shared(p);
}

__device__ __forceinline__ void ldsm_x4(unsigned& r0, unsigned& r1, unsigned& r2, unsigned& r3,
                                        unsigned addr) {
    asm volatile("ldmatrix.sync.aligned.m8n8.x4.shared.b16 {%0,%1,%2,%3}, [%4];"
                 : "=r"(r0), "=r"(r1), "=r"(r2), "=r"(r3) : "r"(addr));
}
__device__ __forceinline__ void ldsm_x2(unsigned& r0, unsigned& r1, unsigned addr) {
    asm volatile("ldmatrix.sync.aligned.m8n8.x2.shared.b16 {%0,%1}, [%2];"
                 : "=r"(r0), "=r"(r1) : "r"(addr));
}
__device__ __forceinline__ void mma_bf16(float* c, const unsigned* a, const unsigned* b) {
    asm volatile("mma.sync.aligned.m16n8k16.row.col.f32.bf16.bf16.f32 "
                 "{%0,%1,%2,%3},{%4,%5,%6,%7},{%8,%9},{%0,%1,%2,%3};"
                 : "+f"(c[0]), "+f"(c[1]), "+f"(c[2]), "+f"(c[3])
                 : "r"(a[0]), "r"(a[1]), "r"(a[2]), "r"(a[3]), "r"(b[0]), "r"(b[1]));
}

// fp32 pair -> bf16x2 hi + bf16x2 lo (residual). low half = even-k element.
__device__ __forceinline__ void cvt_hilo(float f0, float f1, unsigned& hi, unsigned& lo) {
    __nv_bfloat162 h = __floats2bfloat162_rn(f0, f1);
    float2 hf = __bfloat1622float2(h);
    __nv_bfloat162 l = __floats2bfloat162_rn(f0 - hf.x, f1 - hf.y);
    hi = *reinterpret_cast<unsigned*>(&h);
    lo = *reinterpret_cast<unsigned*>(&l);
}

#define KP   40   // smem row pitch in bf16 elems (32 data + 8 pad) = 80B
#define KP32 20

// =====================================================================
// K1: xz = x @ [in_w_fw | in_w_bw].T  (fused N=1536, no flips)
// block 128m x 128n, 8 warps (warp tile 64m x 32n), bf16 3-pass mma
// =====================================================================
__global__ void __launch_bounds__(256)
k_gemm_in(const float* __restrict__ x,
          const float* __restrict__ w_fw,
          const float* __restrict__ w_bw)
{
    __shared__ __align__(16) unsigned short Ah[128*KP], Al[128*KP], Bh[128*KP], Bl[128*KP];

    const int m0   = blockIdx.x * 128;
    const int nblk = blockIdx.y;            // 0..11
    const int dir  = nblk >= 6;
    const int n0l  = (nblk - 6*dir) * 128;  // local col base within 768
    const float* __restrict__ W = dir ? w_bw : w_fw;  // [768][192]

    const int tid = threadIdx.x;
    const int warp = tid >> 5, lane = tid & 31;
    const int wm = warp >> 2, wn = warp & 3;      // wm:0-1 (64 rows), wn:0-3 (32 cols)

    float acc[4][4][4];
    #pragma unroll
    for (int i = 0; i < 4; i++)
        #pragma unroll
        for (int j = 0; j < 4; j++)
            #pragma unroll
            for (int r = 0; r < 4; r++) acc[i][j][r] = 0.f;

    unsigned* Ah32 = (unsigned*)Ah; unsigned* Al32 = (unsigned*)Al;
    unsigned* Bh32 = (unsigned*)Bh; unsigned* Bl32 = (unsigned*)Bl;
    const unsigned sAh = smem_u32(Ah), sAl = smem_u32(Al);
    const unsigned sBh = smem_u32(Bh), sBl = smem_u32(Bl);

    for (int kc = 0; kc < Dm; kc += 32) {
        #pragma unroll
        for (int i = 0; i < 4; i++) {
            int s = tid + i * 256;          // 0..1023
            int r = s >> 3, c4 = s & 7;     // row, float4-slot
            int m = m0 + r;
            float4 v = make_float4(0.f, 0.f, 0.f, 0.f);
            if (m < Mrows) v = *(const float4*)(x + (size_t)m * Dm + kc + c4*4);
            unsigned h0, q0, h1, q1;
            cvt_hilo(v.x, v.y, h0, q0);
            cvt_hilo(v.z, v.w, h1, q1);
            Ah32[r*KP32 + c4*2] = h0;  Ah32[r*KP32 + c4*2 + 1] = h1;
            Al32[r*KP32 + c4*2] = q0;  Al32[r*KP32 + c4*2 + 1] = q1;

            float4 wv = *(const float4*)(W + (size_t)(n0l + r) * Dm + kc + c4*4);
            cvt_hilo(wv.x, wv.y, h0, q0);
            cvt_hilo(wv.z, wv.w, h1, q1);
            Bh32[r*KP32 + c4*2] = h0;  Bh32[r*KP32 + c4*2 + 1] = h1;
            Bl32[r*KP32 + c4*2] = q0;  Bl32[r*KP32 + c4*2 + 1] = q1;
        }
        __syncthreads();

        #pragma unroll
        for (int kk = 0; kk < 32; kk += 16) {
            unsigned bh[4][2], bl[4][2];
            #pragma unroll
            for (int ni = 0; ni < 4; ni++) {
                int row  = wn*32 + ni*8 + (lane & 7);
                int kcol = kk + ((lane >> 3) & 1) * 8;
                unsigned off = (unsigned)(row * KP + kcol) * 2;
                ldsm_x2(bh[ni][0], bh[ni][1], sBh + off);
                ldsm_x2(bl[ni][0], bl[ni][1], sBl + off);
            }
            #pragma unroll
            for (int mi = 0; mi < 4; mi++) {
                int row  = wm*64 + mi*16 + (lane & 7) + ((lane >> 3) & 1) * 8;
                int kcol = kk + (lane >> 4) * 8;
                unsigned off = (unsigned)(row * KP + kcol) * 2;
                unsigned ah[4], al[4];
                ldsm_x4(ah[0], ah[1], ah[2], ah[3], sAh + off);
                ldsm_x4(al[0], al[1], al[2], al[3], sAl + off);
                #pragma unroll
                for (int ni = 0; ni < 4; ni++) {
                    mma_bf16(acc[mi][ni], ah, bh[ni]);
                    mma_bf16(acc[mi][ni], al, bh[ni]);
                    mma_bf16(acc[mi][ni], ah, bl[ni]);
                }
            }
        }
        __syncthreads();
    }

    const int g = lane >> 2, t4 = lane & 3;
    #pragma unroll
    for (int mi = 0; mi < 4; mi++) {
        #pragma unroll
        for (int ni = 0; ni < 4; ni++) {
            int col = n0l + wn*32 + ni*8 + t4*2;
            int mr  = m0 + wm*64 + mi*16 + g;
            if (mr < Mrows)
                *(float2*)&g_xz[dir][mr][col]   = make_float2(acc[mi][ni][0], acc[mi][ni][1]);
            if (mr + 8 < Mrows)
                *(float2*)&g_xz[dir][mr+8][col] = make_float2(acc[mi][ni][2], acc[mi][ni][3]);
        }
    }
}

// =====================================================================
// K2: causal depthwise conv (k=4) + bias + SiLU.
// =====================================================================
#define LCH 8
__global__ void k_conv(const float* __restrict__ cw_fw, const float* __restrict__ cb_fw,
                       const float* __restrict__ cw_bw, const float* __restrict__ cb_bw)
{
    const int ch  = blockIdx.x * 128 + threadIdx.x;
    const int l0  = blockIdx.y * LCH;
    const int b   = blockIdx.z & 31;
    const int dir = blockIdx.z >> 5;

    const float* cw = (dir ? cw_bw : cw_fw) + ch * 4;
    const float W0 = dir ? cw[3] : cw[0];
    const float W1 = dir ? cw[2] : cw[1];
    const float W2 = dir ? cw[1] : cw[2];
    const float W3 = dir ? cw[0] : cw[3];
    const float bias = (dir ? cb_bw : cb_fw)[ch];

    const float* __restrict__ src = &g_xz[dir][(size_t)b * Lseq][0];  // stride 768
    float*       __restrict__ dst = &g_xc[dir][(size_t)b * Lseq][0];  // stride 384

    const int poff = dir ? 0 : -3;
    const int coff = dir ? 3 : 0;
    float x0 = 0.f, x1 = 0.f, x2 = 0.f;
    {
        int p0 = l0 + poff, p1 = p0 + 1, p2 = p0 + 2;
        if (p0 >= 0 && p0 < Lseq) x0 = src[(size_t)p0 * (2*DIn) + ch];
        if (p1 >= 0 && p1 < Lseq) x1 = src[(size_t)p1 * (2*DIn) + ch];
        if (p2 >= 0 && p2 < Lseq) x2 = src[(size_t)p2 * (2*DIn) + ch];
    }

    #pragma unroll
    for (int i = 0; i < LCH; i++) {
        int l = l0 + i;
        int q = l + coff;
        float x3 = (q < Lseq) ? src[(size_t)q * (2*DIn) + ch] : 0.f;
        float v = fmaf(W0, x0, fmaf(W1, x1, fmaf(W2, x2, fmaf(W3, x3, bias))));
        v = v / (1.f + __expf(-v));
        if (l < Lseq) dst[(size_t)l * DIn + ch] = v;
        x0 = x1; x1 = x2; x2 = x3;
    }
}

// =====================================================================
// K3: x_proj + tanh(B,C) + dt lowrank + softplus  (pointwise per row)
// =====================================================================
__device__ __forceinline__ float softplus_stable(float v) {
    return v > 20.f ? v : log1pf(expf(v));
}

__global__ void k_proj(const float* __restrict__ xp_fw, const float* __restrict__ dw_fw,
                       const float* __restrict__ db_fw,
                       const float* __restrict__ xp_bw, const float* __restrict__ dw_bw,
                       const float* __restrict__ db_bw)
{
    const int warp = threadIdx.x >> 5, lane = threadIdx.x & 31;
    const long row = (long)blockIdx.x * 8 + warp;
    if (row >= 2L * Mrows) return;
    const int dir = row >= Mrows;
    const int m   = (int)(row - (long)dir * Mrows);

    const float* __restrict__ xpw = dir ? xp_bw : xp_fw;
    const float* __restrict__ dw  = dir ? dw_bw : dw_fw;
    const float* __restrict__ db  = dir ? db_bw : db_fw;
    const float* __restrict__ rowp = g_xc[dir][m];

    float xv[12];
    #pragma unroll
    for (int i = 0; i < 12; i++) xv[i] = rowp[lane + 32*i];

    float dtp[RK];
    #pragma unroll
    for (int j = 0; j < NPJ; j++) {
        const float* wj = xpw + (size_t)j * DIn;
        float s = 0.f;
        #pragma unroll
        for (int i = 0; i < 12; i++) s = fmaf(xv[i], wj[lane + 32*i], s);
        #pragma unroll
        for (int o = 16; o; o >>= 1) s += __shfl_xor_sync(0xffffffffu, s, o);
        if (j < RK) {
            dtp[j] = s;
        } else {
            if (lane == 0) g_bc[dir][m][j - RK] = tanhf(s);
        }
    }

    #pragma unroll
    for (int i = 0; i < 12; i++) {
        int ch = lane + 32*i;
        const float* wr = dw + (size_t)ch * RK;
        float s = db[ch];
        #pragma unroll
        for (int r = 0; r < RK; r++) s = fmaf(dtp[r], wr[r], s);
        g_dt[dir][m][ch] = softplus_stable(s) + 1e-4f;
    }
}

// =====================================================================
// K4a: scan phase 1 — chunk transfer (Aprod, Bacc). bw walks backwards.
// =====================================================================
__global__ void k_scan1(const float* __restrict__ Al_fw, const float* __restrict__ Al_bw)
{
    const int ch    = blockIdx.x * 128 + threadIdx.x;
    const int chunk = blockIdx.y;
    const int b     = blockIdx.z & 31;
    const int dir   = blockIdx.z >> 5;

    const float* Alog = (dir ? Al_bw : Al_fw) + (size_t)ch * DSt;
    float a[DSt];
    #pragma unroll
    for (int s = 0; s < DSt; s++) a[s] = -expf(Alog[s]);

    const size_t rbase = (size_t)b * Lseq;
    const float* __restrict__ dtp = &g_dt[dir][rbase][0];
    const float* __restrict__ xcp = &g_xc[dir][rbase][0];
    const float4* __restrict__ bc4 = (const float4*)&g_bc[dir][rbase][0];

    const int l0 = chunk * CLEN;
    const int l1 = min(l0 + CLEN, Lseq);

    float st[DSt], Ap[DSt];
    #pragma unroll
    for (int s = 0; s < DSt; s++) { st[s] = 0.f; Ap[s] = 1.f; }

    for (int l = l0; l < l1; l++) {
        const int pl = dir ? (Lseq - 1 - l) : l;
        const size_t off = (size_t)pl * DIn + ch;
        const float dt = dtp[off];
        const float xx = xcp[off];
        float4 b0 = bc4[(size_t)pl*4 + 0];
        float4 b1 = bc4[(size_t)pl*4 + 1];
        const float bv[DSt] = {b0.x,b0.y,b0.z,b0.w,b1.x,b1.y,b1.z,b1.w};

        #pragma unroll
        for (int s = 0; s < DSt; s++) {
            float da = fexp_neg(dt * a[s]);
            st[s] = fmaf(da, st[s], (1.f - da) * bv[s] * xx);
            Ap[s] *= da;
        }
    }

    float* tr = &g_tr[dir][b][ch][chunk][0];
    #pragma unroll
    for (int s = 0; s < DSt; s++) { tr[s] = Ap[s]; tr[8 + s] = st[s]; }
}

// =====================================================================
// K4b: scan phase 2+3 — compose init, replay chunk with y*silu(z).
// =====================================================================
__global__ void k_scan2(const float* __restrict__ Al_fw, const float* __restrict__ Dk_fw,
                        const float* __restrict__ Al_bw, const float* __restrict__ Dk_bw)
{
    const int ch    = blockIdx.x * 128 + threadIdx.x;
    const int chunk = blockIdx.y;
    const int b     = blockIdx.z & 31;
    const int dir   = blockIdx.z >> 5;

    const float* Alog = (dir ? Al_bw : Al_fw) + (size_t)ch * DSt;
    float a[DSt];
    #pragma unroll
    for (int s = 0; s < DSt; s++) a[s] = -expf(Alog[s]);
    const float Dsk = (dir ? Dk_bw : Dk_fw)[ch];

    float st[DSt];
    #pragma unroll
    for (int s = 0; s < DSt; s++) st[s] = 0.f;
    {
        const float* tr = &g_tr[dir][b][ch][0][0];
        for (int c = 0; c < chunk; c++) {
            const float* t = tr + c * 16;
            #pragma unroll
            for (int s = 0; s < DSt; s++)
                st[s] = fmaf(t[s], st[s], t[8 + s]);
        }
    }

    const size_t rbase = (size_t)b * Lseq;
    const float* __restrict__ dtp = &g_dt[dir][rbase][0];
    const float* __restrict__ xcp = &g_xc[dir][rbase][0];
    const float* __restrict__ zp  = &g_xz[dir][rbase][DIn];
    const float4* __restrict__ bc4 = (const float4*)&g_bc[dir][rbase][0];
    float*       __restrict__ ysp = &g_ys[dir][rbase][0];

    const int l0 = chunk * CLEN;
    const int l1 = min(l0 + CLEN, Lseq);

    for (int l = l0; l < l1; l++) {
        const int pl = dir ? (Lseq - 1 - l) : l;
        const size_t off = (size_t)pl * DIn + ch;
        const float dt = dtp[off];
        const float xx = xcp[off];
        float4 b0 = bc4[(size_t)pl*4 + 0];
        float4 b1 = bc4[(size_t)pl*4 + 1];
        float4 c0 = bc4[(size_t)pl*4 + 2];
        float4 c1 = bc4[(size_t)pl*4 + 3];
        const float bv[DSt] = {b0.x,b0.y,b0.z,b0.w,b1.x,b1.y,b1.z,b1.w};
        const float cv[DSt] = {c0.x,c0.y,c0.z,c0.w,c1.x,c1.y,c1.z,c1.w};

        float acc = 0.f;
        #pragma unroll
        for (int s = 0; s < DSt; s++) {
            float da = fexp_neg(dt * a[s]);
            st[s] = fmaf(da, st[s], (1.f - da) * bv[s] * xx);
            acc = fmaf(st[s], cv[s], acc);
        }
        float y = fmaf(Dsk, xx, acc);
        float z = zp[(size_t)pl * (2*DIn) + ch];
        float sz = z / (1.f + __expf(-z));
        ysp[off] = y * sz;
    }
}

// =====================================================================
// K5: out = 0.5*( ys_fw @ ow_fw.T + ys_bw @ ow_bw.T )  (fused K=768)
// block 128m x 64n, 8 warps (warp 32m x 32n), bf16 3-pass mma
// =====================================================================
__global__ void __launch_bounds__(256)
k_gemm_out(const float* __restrict__ ow_fw,
           const float* __restrict__ ow_bw,
           float* __restrict__ out)
{
    __shared__ __align__(16) unsigned short Ah[128*KP], Al[128*KP], Bh[64*KP], Bl[64*KP];

    const int m0 = blockIdx.x * 128;
    const int n0 = blockIdx.y * 64;

    const int tid = threadIdx.x;
    const int warp = tid >> 5, lane = tid & 31;
    const int wm = warp >> 1, wn = warp & 1;   // wm:0-3 (32 rows), wn:0-1 (32 cols)

    float acc[2][4][4];
    #pragma unroll
    for (int i = 0; i < 2; i++)
        #pragma unroll
        for (int j = 0; j < 4; j++)
            #pragma unroll
            for (int r = 0; r < 4; r++) acc[i][j][r] = 0.f;

    unsigned* Ah32 = (unsigned*)Ah; unsigned* Al32 = (unsigned*)Al;
    unsigned* Bh32 = (unsigned*)Bh; unsigned* Bl32 = (unsigned*)Bl;
    const unsigned sAh = smem_u32(Ah), sAl = smem_u32(Al);
    const unsigned sBh = smem_u32(Bh), sBl = smem_u32(Bl);

    for (int kc = 0; kc < 2*DIn; kc += 32) {
        const int dirk = kc >= DIn;
        const int kcl  = kc - DIn * dirk;
        const float* __restrict__ Asrc = &g_ys[dirk][0][0];
        const float* __restrict__ Wd   = dirk ? ow_bw : ow_fw;   // [192][384]

        #pragma unroll
        for (int i = 0; i < 4; i++) {
            int s = tid + i * 256;
            int r = s >> 3, c4 = s & 7;
            int m = m0 + r;
            float4 v = make_float4(0.f, 0.f, 0.f, 0.f);
            if (m < Mrows) v = *(const float4*)(Asrc + (size_t)m * DIn + kcl + c4*4);
            unsigned h0, q0, h1, q1;
            cvt_hilo(v.x, v.y, h0, q0);
            cvt_hilo(v.z, v.w, h1, q1);
            Ah32[r*KP32 + c4*2] = h0;  Ah32[r*KP32 + c4*2 + 1] = h1;
            Al32[r*KP32 + c4*2] = q0;  Al32[r*KP32 + c4*2 + 1] = q1;
        }
        #pragma unroll
        for (int i = 0; i < 2; i++) {
            int s = tid + i * 256;        // 0..511
            int r = s >> 3, c4 = s & 7;   // r: 0..63
            float4 wv = *(const float4*)(Wd + (size_t)(n0 + r) * DIn + kcl + c4*4);
            unsigned h0, q0, h1, q1;
            cvt_hilo(wv.x, wv.y, h0, q0);
            cvt_hilo(wv.z, wv.w, h1, q1);
            Bh32[r*KP32 + c4*2] = h0;  Bh32[r*KP32 + c4*2 + 1] = h1;
            Bl32[r*KP32 + c4*2] = q0;  Bl32[r*KP32 + c4*2 + 1] = q1;
        }
        __syncthreads();

        #pragma unroll
        for (int kk = 0; kk < 32; kk += 16) {
            unsigned bh[4][2], bl[4][2];
            #pragma unroll
            for (int ni = 0; ni < 4; ni++) {
                int row  = wn*32 + ni*8 + (lane & 7);
                int kcol = kk + ((lane >> 3) & 1) * 8;
                unsigned off = (unsigned)(row * KP + kcol) * 2;
                ldsm_x2(bh[ni][0], bh[ni][1], sBh + off);
                ldsm_x2(bl[ni][0], bl[ni][1], sBl + off);
            }
            #pragma unroll
            for (int mi = 0; mi < 2; mi++) {
                int row  = wm*32 + mi*16 + (lane & 7) + ((lane >> 3) & 1) * 8;
                int kcol = kk + (lane >> 4) * 8;
                unsigned off = (unsigned)(row * KP + kcol) * 2;
                unsigned ah[4], al[4];
                ldsm_x4(ah[0], ah[1], ah[2], ah[3], sAh + off);
                ldsm_x4(al[0], al[1], al[2], al[3], sAl + off);
                #pragma unroll
                for (int ni = 0; ni < 4; ni++) {
                    mma_bf16(acc[mi][ni], ah, bh[ni]);
                    mma_bf16(acc[mi][ni], al, bh[ni]);
                    mma_bf16(acc[mi][ni], ah, bl[ni]);
                }
            }
        }
        __syncthreads();
    }

    const int g = lane >> 2, t4 = lane & 3;
    #pragma unroll
    for (int mi = 0; mi < 2; mi++) {
        #pragma unroll
        for (int ni = 0; ni < 4; ni++) {
            int col = n0 + wn*32 + ni*8 + t4*2;
            int mr  = m0 + wm*32 + mi*16 + g;
            if (mr < Mrows)
                *(float2*)&out[(size_t)mr * Dm + col] =
                    make_float2(0.5f*acc[mi][ni][0], 0.5f*acc[mi][ni][1]);
            if (mr + 8 < Mrows)
                *(float2*)&out[(size_t)(mr+8) * Dm + col] =
                    make_float2(0.5f*acc[mi][ni][2], 0.5f*acc[mi][ni][3]);
        }
    }
}

// =====================================================================
extern "C" void kernel_launch(void* const* d_in, const int* in_sizes, int n_in,
                              void* d_out, int out_size)
{
    const float* x        = (const float*)d_in[0];
    const float* fw_in_w  = (const float*)d_in[1];
    const float* fw_cw    = (const float*)d_in[2];
    const float* fw_cb    = (const float*)d_in[3];
    const float* fw_xpw   = (const float*)d_in[4];
    const float* fw_dtw   = (const float*)d_in[5];
    const float* fw_dtb   = (const float*)d_in[6];
    const float* fw_Alog  = (const float*)d_in[7];
    const float* fw_D     = (const float*)d_in[8];
    const float* fw_ow    = (const float*)d_in[9];
    const float* bw_in_w  = (const float*)d_in[10];
    const float* bw_cw    = (const float*)d_in[11];
    const float* bw_cb    = (const float*)d_in[12];
    const float* bw_xpw   = (const float*)d_in[13];
    const float* bw_dtw   = (const float*)d_in[14];
    const float* bw_dtb   = (const float*)d_in[15];
    const float* bw_Alog  = (const float*)d_in[16];
    const float* bw_D     = (const float*)d_in[17];
    const float* bw_ow    = (const float*)d_in[18];
    float* out = (float*)d_out;

    dim3 g1((Mrows + 127) / 128, 12, 1);
    k_gemm_in<<<g1, 256>>>(x, fw_in_w, bw_in_w);

    dim3 g2(DIn / 128, (Lseq + LCH - 1) / LCH, 2 * Bsz);
    k_conv<<<g2, 128>>>(fw_cw, fw_cb, bw_cw, bw_cb);

    int nrows = 2 * Mrows;
    k_proj<<<(nrows + 7) / 8, 256>>>(fw_xpw, fw_dtw, fw_dtb,
                                     bw_xpw, bw_dtw, bw_dtb);

    dim3 g4(DIn / 128, NCH, 2 * Bsz);      // 3 x 8 x 64
    k_scan1<<<g4, 128>>>(fw_Alog, bw_Alog);
    k_scan2<<<g4, 128>>>(fw_Alog, fw_D, bw_Alog, bw_D);

    dim3 g5((Mrows + 127) / 128, Dm / 64, 1);
    k_gemm_out<<<g5, 256>>>(fw_ow, bw_ow, out);
}

// round 7
// speedup vs baseline: 2.4023x; 1.0567x over previous
#include <cuda_runtime.h>
#include <cuda_bf16.h>
#include <cstdint>
#include <cstddef>
#include <math.h>

#define Bsz   32
#define Lseq  577
#define Dm    192
#define DIn   384
#define DSt   8
#define RK    12
#define NPJ   28
#define Mrows (Bsz*Lseq)   // 18464
#define NCH   8            // scan chunks
#define CLEN  73           // 8*73 = 584 >= 577

// bw-direction intermediates stored at PHYSICAL sequence index (unflipped):
// GEMMs need no flips; conv mirrors its window; scans walk backwards for bw.

// ---- scratch ----
__device__ float g_xz[2][Mrows][2*DIn];   // in-proj output (x_part | z)
__device__ float g_xc[2][Mrows][DIn];     // conv+silu output
__device__ float g_dt[2][Mrows][DIn];     // dt after softplus
__device__ float g_bc[2][Mrows][16];      // tanh(B) (8) | tanh(C) (8)
__device__ float g_tr[2][Bsz][DIn][NCH][16]; // chunk transfer: Aprod[8] | Bacc[8]

// bf16 split-precision operand buffers
__device__ __nv_bfloat16 g_xh[Mrows][Dm],  g_xl[Mrows][Dm];     // input x hi/lo
__device__ __nv_bfloat16 g_wih[2][2*DIn][Dm], g_wil[2][2*DIn][Dm]; // in_w hi/lo
__device__ __nv_bfloat16 g_woh[2][Dm][DIn], g_wol[2][Dm][DIn];  // out_w hi/lo
__device__ __nv_bfloat16 g_ysh[2][Mrows][DIn], g_ysl[2][Mrows][DIn]; // ys hi/lo

// FMA-only exp for x <= 0, degree-4 (rel err ~4e-5; MUFU stays free).
__device__ __forceinline__ float fexp_neg(float x)
{
    x = fmaxf(x, -80.f);
    float z  = x * 1.4426950408889634f;
    float fi = (z + 12582912.0f) - 12582912.0f;
    float f  = z - fi;
    float p  = 9.6181291e-3f;
    p = fmaf(p, f, 5.5504109e-2f);
    p = fmaf(p, f, 2.4022651e-1f);
    p = fmaf(p, f, 6.9314718e-1f);
    p = fmaf(p, f, 1.0f);
    int ie = (int)fi;
    return __int_as_float(__float_as_int(p) + (ie << 23));
}

// ---- tensor-core helpers ----
__device__ __forceinline__ unsigned smem_u32(const void* p) {
    return (unsigned)__cvta_generic_to_shared(p);
}
__device__ __forceinline__ void ldsm_x4(unsigned& r0, unsigned& r1, unsigned& r2, unsigned& r3,
                                        unsigned addr) {
    asm volatile("ldmatrix.sync.aligned.m8n8.x4.shared.b16 {%0,%1,%2,%3}, [%4];"
                 : "=r"(r0), "=r"(r1), "=r"(r2), "=r"(r3) : "r"(addr));
}
__device__ __forceinline__ void ldsm_x2(unsigned& r0, unsigned& r1, unsigned addr) {
    asm volatile("ldmatrix.sync.aligned.m8n8.x2.shared.b16 {%0,%1}, [%2];"
                 : "=r"(r0), "=r"(r1) : "r"(addr));
}
__device__ __forceinline__ void mma_bf16(float* c, const unsigned* a, const unsigned* b) {
    asm volatile("mma.sync.aligned.m16n8k16.row.col.f32.bf16.bf16.f32 "
                 "{%0,%1,%2,%3},{%4,%5,%6,%7},{%8,%9},{%0,%1,%2,%3};"
                 : "+f"(c[0]), "+f"(c[1]), "+f"(c[2]), "+f"(c[3])
                 : "r"(a[0]), "r"(a[1]), "r"(a[2]), "r"(a[3]), "r"(b[0]), "r"(b[1]));
}
// fp32 pair -> bf16x2 hi + bf16x2 lo (residual). low half = even element.
__device__ __forceinline__ void cvt_hilo(float f0, float f1, unsigned& hi, unsigned& lo) {
    __nv_bfloat162 h = __floats2bfloat162_rn(f0, f1);
    float2 hf = __bfloat1622float2(h);
    __nv_bfloat162 l = __floats2bfloat162_rn(f0 - hf.x, f1 - hf.y);
    hi = *reinterpret_cast<unsigned*>(&h);
    lo = *reinterpret_cast<unsigned*>(&l);
}

#define KP   56   // smem row pitch in bf16 elems: 112B (16B-aligned, ldmatrix conflict-free)

// =====================================================================
// K0: one-time fp32 -> bf16 hi/lo conversion of x and all GEMM weights
// =====================================================================
#define XP   ((long)Mrows*Dm/2)        // pairs in x
#define WIP  ((long)(2*DIn)*Dm/2)      // pairs per in_w
#define WOP  ((long)Dm*DIn/2)          // pairs per out_w
#define TOTP (XP + 2*WIP + 2*WOP)

__global__ void k_cvt(const float* __restrict__ x,
                      const float* __restrict__ wi_fw, const float* __restrict__ wi_bw,
                      const float* __restrict__ wo_fw, const float* __restrict__ wo_bw)
{
    long p = (long)blockIdx.x * 256 + threadIdx.x;
    if (p >= TOTP) return;
    const float* src; unsigned *dh, *dl; long off;
    if (p < XP)                    { src = x;     dh = (unsigned*)g_xh;      dl = (unsigned*)g_xl;      off = p; }
    else if (p < XP + WIP)         { src = wi_fw; dh = (unsigned*)g_wih[0]; dl = (unsigned*)g_wil[0]; off = p - XP; }
    else if (p < XP + 2*WIP)       { src = wi_bw; dh = (unsigned*)g_wih[1]; dl = (unsigned*)g_wil[1]; off = p - XP - WIP; }
    else if (p < XP + 2*WIP + WOP) { src = wo_fw; dh = (unsigned*)g_woh[0]; dl = (unsigned*)g_wol[0]; off = p - XP - 2*WIP; }
    else                           { src = wo_bw; dh = (unsigned*)g_woh[1]; dl = (unsigned*)g_wol[1]; off = p - XP - 2*WIP - WOP; }
    float2 v = ((const float2*)src)[off];
    unsigned h, l;
    cvt_hilo(v.x, v.y, h, l);
    dh[off] = h; dl[off] = l;
}

// =====================================================================
// K1: xz = x @ [in_w_fw | in_w_bw].T  (fused N=1536, no flips)
// block 128m x 128n, 8 warps (warp tile 64m x 32n), bf16 3-pass mma
// =====================================================================
__global__ void __launch_bounds__(256)
k_gemm_in()
{
    __shared__ __align__(16) __nv_bfloat16 Ah[128*KP], Al[128*KP], Bh[128*KP], Bl[128*KP];

    const int m0   = blockIdx.x * 128;
    const int nblk = blockIdx.y;            // 0..11
    const int dir  = nblk >= 6;
    const int n0l  = (nblk - 6*dir) * 128;  // local col base within 768

    const int tid = threadIdx.x;
    const int warp = tid >> 5, lane = tid & 31;
    const int wm = warp >> 2, wn = warp & 3;      // wm:0-1 (64 rows), wn:0-3 (32 cols)

    float acc[4][4][4];
    #pragma unroll
    for (int i = 0; i < 4; i++)
        #pragma unroll
        for (int j = 0; j < 4; j++)
            #pragma unroll
            for (int r = 0; r < 4; r++) acc[i][j][r] = 0.f;

    const unsigned sAh = smem_u32(Ah), sAl = smem_u32(Al);
    const unsigned sBh = smem_u32(Bh), sBl = smem_u32(Bl);

    for (int kc = 0; kc < Dm; kc += 32) {
        #pragma unroll
        for (int i = 0; i < 2; i++) {
            int s = tid + i * 256;          // 0..511
            int r = s >> 2, c8 = (s & 3) * 8;  // row 0..127, col slot (8 bf16 = 16B)
            int m = m0 + r;
            uint4 vh = make_uint4(0,0,0,0), vl = make_uint4(0,0,0,0);
            if (m < Mrows) {
                vh = *(const uint4*)&g_xh[m][kc + c8];
                vl = *(const uint4*)&g_xl[m][kc + c8];
            }
            *(uint4*)&Ah[r*KP + c8] = vh;
            *(uint4*)&Al[r*KP + c8] = vl;
            *(uint4*)&Bh[r*KP + c8] = *(const uint4*)&g_wih[dir][n0l + r][kc + c8];
            *(uint4*)&Bl[r*KP + c8] = *(const uint4*)&g_wil[dir][n0l + r][kc + c8];
        }
        __syncthreads();

        #pragma unroll
        for (int kk = 0; kk < 32; kk += 16) {
            unsigned bh[4][2], bl[4][2];
            #pragma unroll
            for (int ni = 0; ni < 4; ni++) {
                int row  = wn*32 + ni*8 + (lane & 7);
                int kcol = kk + ((lane >> 3) & 1) * 8;
                unsigned off = (unsigned)(row * KP + kcol) * 2;
                ldsm_x2(bh[ni][0], bh[ni][1], sBh + off);
                ldsm_x2(bl[ni][0], bl[ni][1], sBl + off);
            }
            #pragma unroll
            for (int mi = 0; mi < 4; mi++) {
                int row  = wm*64 + mi*16 + (lane & 7) + ((lane >> 3) & 1) * 8;
                int kcol = kk + (lane >> 4) * 8;
                unsigned off = (unsigned)(row * KP + kcol) * 2;
                unsigned ah[4], al[4];
                ldsm_x4(ah[0], ah[1], ah[2], ah[3], sAh + off);
                ldsm_x4(al[0], al[1], al[2], al[3], sAl + off);
                #pragma unroll
                for (int ni = 0; ni < 4; ni++) {
                    mma_bf16(acc[mi][ni], ah, bh[ni]);
                    mma_bf16(acc[mi][ni], al, bh[ni]);
                    mma_bf16(acc[mi][ni], ah, bl[ni]);
                }
            }
        }
        __syncthreads();
    }

    const int g = lane >> 2, t4 = lane & 3;
    #pragma unroll
    for (int mi = 0; mi < 4; mi++) {
        #pragma unroll
        for (int ni = 0; ni < 4; ni++) {
            int col = n0l + wn*32 + ni*8 + t4*2;
            int mr  = m0 + wm*64 + mi*16 + g;
            if (mr < Mrows)
                *(float2*)&g_xz[dir][mr][col]   = make_float2(acc[mi][ni][0], acc[mi][ni][1]);
            if (mr + 8 < Mrows)
                *(float2*)&g_xz[dir][mr+8][col] = make_float2(acc[mi][ni][2], acc[mi][ni][3]);
        }
    }
}

// =====================================================================
// K2: causal depthwise conv (k=4) + bias + SiLU.
// =====================================================================
#define LCH 8
__global__ void k_conv(const float* __restrict__ cw_fw, const float* __restrict__ cb_fw,
                       const float* __restrict__ cw_bw, const float* __restrict__ cb_bw)
{
    const int ch  = blockIdx.x * 128 + threadIdx.x;
    const int l0  = blockIdx.y * LCH;
    const int b   = blockIdx.z & 31;
    const int dir = blockIdx.z >> 5;

    const float* cw = (dir ? cw_bw : cw_fw) + ch * 4;
    const float W0 = dir ? cw[3] : cw[0];
    const float W1 = dir ? cw[2] : cw[1];
    const float W2 = dir ? cw[1] : cw[2];
    const float W3 = dir ? cw[0] : cw[3];
    const float bias = (dir ? cb_bw : cb_fw)[ch];

    const float* __restrict__ src = &g_xz[dir][(size_t)b * Lseq][0];  // stride 768
    float*       __restrict__ dst = &g_xc[dir][(size_t)b * Lseq][0];  // stride 384

    const int poff = dir ? 0 : -3;
    const int coff = dir ? 3 : 0;
    float x0 = 0.f, x1 = 0.f, x2 = 0.f;
    {
        int p0 = l0 + poff, p1 = p0 + 1, p2 = p0 + 2;
        if (p0 >= 0 && p0 < Lseq) x0 = src[(size_t)p0 * (2*DIn) + ch];
        if (p1 >= 0 && p1 < Lseq) x1 = src[(size_t)p1 * (2*DIn) + ch];
        if (p2 >= 0 && p2 < Lseq) x2 = src[(size_t)p2 * (2*DIn) + ch];
    }

    #pragma unroll
    for (int i = 0; i < LCH; i++) {
        int l = l0 + i;
        int q = l + coff;
        float x3 = (q < Lseq) ? src[(size_t)q * (2*DIn) + ch] : 0.f;
        float v = fmaf(W0, x0, fmaf(W1, x1, fmaf(W2, x2, fmaf(W3, x3, bias))));
        v = v / (1.f + __expf(-v));
        if (l < Lseq) dst[(size_t)l * DIn + ch] = v;
        x0 = x1; x1 = x2; x2 = x3;
    }
}

// =====================================================================
// K3: x_proj + tanh(B,C) + dt lowrank + softplus. float4 weight loads.
// =====================================================================
__device__ __forceinline__ float softplus_stable(float v) {
    return v > 20.f ? v : log1pf(expf(v));
}

__global__ void k_proj(const float* __restrict__ xp_fw, const float* __restrict__ dw_fw,
                       const float* __restrict__ db_fw,
                       const float* __restrict__ xp_bw, const float* __restrict__ dw_bw,
                       const float* __restrict__ db_bw)
{
    const int warp = threadIdx.x >> 5, lane = threadIdx.x & 31;
    const long row = (long)blockIdx.x * 8 + warp;
    if (row >= 2L * Mrows) return;
    const int dir = row >= Mrows;
    const int m   = (int)(row - (long)dir * Mrows);

    const float* __restrict__ xpw = dir ? xp_bw : xp_fw;   // [28][384]
    const float* __restrict__ dw  = dir ? dw_bw : dw_fw;   // [384][12]
    const float* __restrict__ db  = dir ? db_bw : db_fw;   // [384]

    const float4* __restrict__ rowp4 = (const float4*)g_xc[dir][m];
    float4 xv4[3];
    #pragma unroll
    for (int q = 0; q < 3; q++) xv4[q] = rowp4[lane + 32*q];

    float dtp[RK];
    #pragma unroll
    for (int j = 0; j < NPJ; j++) {
        const float4* wj4 = (const float4*)(xpw + (size_t)j * DIn);
        float s = 0.f;
        #pragma unroll
        for (int q = 0; q < 3; q++) {
            float4 w = wj4[lane + 32*q];
            s = fmaf(xv4[q].x, w.x, s);
            s = fmaf(xv4[q].y, w.y, s);
            s = fmaf(xv4[q].z, w.z, s);
            s = fmaf(xv4[q].w, w.w, s);
        }
        #pragma unroll
        for (int o = 16; o; o >>= 1) s += __shfl_xor_sync(0xffffffffu, s, o);
        if (j < RK) {
            dtp[j] = s;
        } else {
            if (lane == 0) g_bc[dir][m][j - RK] = tanhf(s);
        }
    }

    #pragma unroll
    for (int i = 0; i < 12; i++) {
        int ch = lane + 32*i;
        const float4* wr4 = (const float4*)(dw + (size_t)ch * RK);  // 48B rows, 16B aligned
        float4 w0 = wr4[0], w1 = wr4[1], w2 = wr4[2];
        float s = db[ch];
        s = fmaf(dtp[0], w0.x, s); s = fmaf(dtp[1],  w0.y, s);
        s = fmaf(dtp[2], w0.z, s); s = fmaf(dtp[3],  w0.w, s);
        s = fmaf(dtp[4], w1.x, s); s = fmaf(dtp[5],  w1.y, s);
        s = fmaf(dtp[6], w1.z, s); s = fmaf(dtp[7],  w1.w, s);
        s = fmaf(dtp[8], w2.x, s); s = fmaf(dtp[9],  w2.y, s);
        s = fmaf(dtp[10], w2.z, s); s = fmaf(dtp[11], w2.w, s);
        g_dt[dir][m][ch] = softplus_stable(s) + 1e-4f;
    }
}

// =====================================================================
// K4a: scan phase 1 — chunk transfer (Aprod, Bacc). bw walks backwards.
// =====================================================================
__global__ void k_scan1(const float* __restrict__ Al_fw, const float* __restrict__ Al_bw)
{
    const int ch    = blockIdx.x * 128 + threadIdx.x;
    const int chunk = blockIdx.y;
    const int b     = blockIdx.z & 31;
    const int dir   = blockIdx.z >> 5;

    const float* Alog = (dir ? Al_bw : Al_fw) + (size_t)ch * DSt;
    float a[DSt];
    #pragma unroll
    for (int s = 0; s < DSt; s++) a[s] = -expf(Alog[s]);

    const size_t rbase = (size_t)b * Lseq;
    const float* __restrict__ dtp = &g_dt[dir][rbase][0];
    const float* __restrict__ xcp = &g_xc[dir][rbase][0];
    const float4* __restrict__ bc4 = (const float4*)&g_bc[dir][rbase][0];

    const int l0 = chunk * CLEN;
    const int l1 = min(l0 + CLEN, Lseq);

    float st[DSt], Ap[DSt];
    #pragma unroll
    for (int s = 0; s < DSt; s++) { st[s] = 0.f; Ap[s] = 1.f; }

    for (int l = l0; l < l1; l++) {
        const int pl = dir ? (Lseq - 1 - l) : l;
        const size_t off = (size_t)pl * DIn + ch;
        const float dt = dtp[off];
        const float xx = xcp[off];
        float4 b0 = bc4[(size_t)pl*4 + 0];
        float4 b1 = bc4[(size_t)pl*4 + 1];
        const float bv[DSt] = {b0.x,b0.y,b0.z,b0.w,b1.x,b1.y,b1.z,b1.w};

        #pragma unroll
        for (int s = 0; s < DSt; s++) {
            float da = fexp_neg(dt * a[s]);
            float bx = bv[s] * xx;
            st[s] = fmaf(da, st[s] - bx, bx);
            Ap[s] *= da;
        }
    }

    float* tr = &g_tr[dir][b][ch][chunk][0];
    #pragma unroll
    for (int s = 0; s < DSt; s++) { tr[s] = Ap[s]; tr[8 + s] = st[s]; }
}

// =====================================================================
// K4b: scan phase 2+3 — compose init, replay chunk with y*silu(z),
// write ys as bf16 hi/lo for the output GEMM.
// =====================================================================
__global__ void k_scan2(const float* __restrict__ Al_fw, const float* __restrict__ Dk_fw,
                        const float* __restrict__ Al_bw, const float* __restrict__ Dk_bw)
{
    const int ch    = blockIdx.x * 128 + threadIdx.x;
    const int chunk = blockIdx.y;
    const int b     = blockIdx.z & 31;
    const int dir   = blockIdx.z >> 5;

    const float* Alog = (dir ? Al_bw : Al_fw) + (size_t)ch * DSt;
    float a[DSt];
    #pragma unroll
    for (int s = 0; s < DSt; s++) a[s] = -expf(Alog[s]);
    const float Dsk = (dir ? Dk_bw : Dk_fw)[ch];

    float st[DSt];
    #pragma unroll
    for (int s = 0; s < DSt; s++) st[s] = 0.f;
    {
        const float* tr = &g_tr[dir][b][ch][0][0];
        for (int c = 0; c < chunk; c++) {
            const float* t = tr + c * 16;
            #pragma unroll
            for (int s = 0; s < DSt; s++)
                st[s] = fmaf(t[s], st[s], t[8 + s]);
        }
    }

    const size_t rbase = (size_t)b * Lseq;
    const float* __restrict__ dtp = &g_dt[dir][rbase][0];
    const float* __restrict__ xcp = &g_xc[dir][rbase][0];
    const float* __restrict__ zp  = &g_xz[dir][rbase][DIn];
    const float4* __restrict__ bc4 = (const float4*)&g_bc[dir][rbase][0];
    __nv_bfloat16* __restrict__ ysh = &g_ysh[dir][rbase][0];
    __nv_bfloat16* __restrict__ ysl = &g_ysl[dir][rbase][0];

    const int l0 = chunk * CLEN;
    const int l1 = min(l0 + CLEN, Lseq);

    for (int l = l0; l < l1; l++) {
        const int pl = dir ? (Lseq - 1 - l) : l;
        const size_t off = (size_t)pl * DIn + ch;
        const float dt = dtp[off];
        const float xx = xcp[off];
        float4 b0 = bc4[(size_t)pl*4 + 0];
        float4 b1 = bc4[(size_t)pl*4 + 1];
        float4 c0 = bc4[(size_t)pl*4 + 2];
        float4 c1 = bc4[(size_t)pl*4 + 3];
        const float bv[DSt] = {b0.x,b0.y,b0.z,b0.w,b1.x,b1.y,b1.z,b1.w};
        const float cv[DSt] = {c0.x,c0.y,c0.z,c0.w,c1.x,c1.y,c1.z,c1.w};

        float acc = 0.f;
        #pragma unroll
        for (int s = 0; s < DSt; s++) {
            float da = fexp_neg(dt * a[s]);
            float bx = bv[s] * xx;
            st[s] = fmaf(da, st[s] - bx, bx);
            acc = fmaf(st[s], cv[s], acc);
        }
        float y = fmaf(Dsk, xx, acc);
        float z = zp[(size_t)pl * (2*DIn) + ch];
        float sz = z / (1.f + __expf(-z));
        float v = y * sz;
        __nv_bfloat16 h = __float2bfloat16(v);
        ysh[off] = h;
        ysl[off] = __float2bfloat16(v - __bfloat162float(h));
    }
}

// =====================================================================
// K5: out = 0.5*( ys_fw @ ow_fw.T + ys_bw @ ow_bw.T )  (fused K=768)
// block 128m x 64n, 8 warps (warp 32m x 32n), bf16 3-pass mma
// =====================================================================
__global__ void __launch_bounds__(256)
k_gemm_out(float* __restrict__ out)
{
    __shared__ __align__(16) __nv_bfloat16 Ah[128*KP], Al[128*KP], Bh[64*KP], Bl[64*KP];

    const int m0 = blockIdx.x * 128;
    const int n0 = blockIdx.y * 64;

    const int tid = threadIdx.x;
    const int warp = tid >> 5, lane = tid & 31;
    const int wm = warp >> 1, wn = warp & 1;   // wm:0-3 (32 rows), wn:0-1 (32 cols)

    float acc[2][4][4];
    #pragma unroll
    for (int i = 0; i < 2; i++)
        #pragma unroll
        for (int j = 0; j < 4; j++)
            #pragma unroll
            for (int r = 0; r < 4; r++) acc[i][j][r] = 0.f;

    const unsigned sAh = smem_u32(Ah), sAl = smem_u32(Al);
    const unsigned sBh = smem_u32(Bh), sBl = smem_u32(Bl);

    for (int kc = 0; kc < 2*DIn; kc += 32) {
        const int dirk = kc >= DIn;
        const int kcl  = kc - DIn * dirk;

        #pragma unroll
        for (int i = 0; i < 2; i++) {
            int s = tid + i * 256;             // 0..511
            int r = s >> 2, c8 = (s & 3) * 8;  // row 0..127
            int m = m0 + r;
            uint4 vh = make_uint4(0,0,0,0), vl = make_uint4(0,0,0,0);
            if (m < Mrows) {
                vh = *(const uint4*)&g_ysh[dirk][m][kcl + c8];
                vl = *(const uint4*)&g_ysl[dirk][m][kcl + c8];
            }
            *(uint4*)&Ah[r*KP + c8] = vh;
            *(uint4*)&Al[r*KP + c8] = vl;
        }
        {
            int r = tid >> 2, c8 = (tid & 3) * 8;   // r: 0..63
            *(uint4*)&Bh[r*KP + c8] = *(const uint4*)&g_woh[dirk][n0 + r][kcl + c8];
            *(uint4*)&Bl[r*KP + c8] = *(const uint4*)&g_wol[dirk][n0 + r][kcl + c8];
        }
        __syncthreads();

        #pragma unroll
        for (int kk = 0; kk < 32; kk += 16) {
            unsigned bh[4][2], bl[4][2];
            #pragma unroll
            for (int ni = 0; ni < 4; ni++) {
                int row  = wn*32 + ni*8 + (lane & 7);
                int kcol = kk + ((lane >> 3) & 1) * 8;
                unsigned off = (unsigned)(row * KP + kcol) * 2;
                ldsm_x2(bh[ni][0], bh[ni][1], sBh + off);
                ldsm_x2(bl[ni][0], bl[ni][1], sBl + off);
            }
            #pragma unroll
            for (int mi = 0; mi < 2; mi++) {
                int row  = wm*32 + mi*16 + (lane & 7) + ((lane >> 3) & 1) * 8;
                int kcol = kk + (lane >> 4) * 8;
                unsigned off = (unsigned)(row * KP + kcol) * 2;
                unsigned ah[4], al[4];
                ldsm_x4(ah[0], ah[1], ah[2], ah[3], sAh + off);
                ldsm_x4(al[0], al[1], al[2], al[3], sAl + off);
                #pragma unroll
                for (int ni = 0; ni < 4; ni++) {
                    mma_bf16(acc[mi][ni], ah, bh[ni]);
                    mma_bf16(acc[mi][ni], al, bh[ni]);
                    mma_bf16(acc[mi][ni], ah, bl[ni]);
                }
            }
        }
        __syncthreads();
    }

    const int g = lane >> 2, t4 = lane & 3;
    #pragma unroll
    for (int mi = 0; mi < 2; mi++) {
        #pragma unroll
        for (int ni = 0; ni < 4; ni++) {
            int col = n0 + wn*32 + ni*8 + t4*2;
            int mr  = m0 + wm*32 + mi*16 + g;
            if (mr < Mrows)
                *(float2*)&out[(size_t)mr * Dm + col] =
                    make_float2(0.5f*acc[mi][ni][0], 0.5f*acc[mi][ni][1]);
            if (mr + 8 < Mrows)
                *(float2*)&out[(size_t)(mr+8) * Dm + col] =
                    make_float2(0.5f*acc[mi][ni][2], 0.5f*acc[mi][ni][3]);
        }
    }
}

// =====================================================================
extern "C" void kernel_launch(void* const* d_in, const int* in_sizes, int n_in,
                              void* d_out, int out_size)
{
    const float* x        = (const float*)d_in[0];
    const float* fw_in_w  = (const float*)d_in[1];
    const float* fw_cw    = (const float*)d_in[2];
    const float* fw_cb    = (const float*)d_in[3];
    const float* fw_xpw   = (const float*)d_in[4];
    const float* fw_dtw   = (const float*)d_in[5];
    const float* fw_dtb   = (const float*)d_in[6];
    const float* fw_Alog  = (const float*)d_in[7];
    const float* fw_D     = (const float*)d_in[8];
    const float* fw_ow    = (const float*)d_in[9];
    const float* bw_in_w  = (const float*)d_in[10];
    const float* bw_cw    = (const float*)d_in[11];
    const float* bw_cb    = (const float*)d_in[12];
    const float* bw_xpw   = (const float*)d_in[13];
    const float* bw_dtw   = (const float*)d_in[14];
    const float* bw_dtb   = (const float*)d_in[15];
    const float* bw_Alog  = (const float*)d_in[16];
    const float* bw_D     = (const float*)d_in[17];
    const float* bw_ow    = (const float*)d_in[18];
    float* out = (float*)d_out;

    long nblk0 = (TOTP + 255) / 256;
    k_cvt<<<(unsigned)nblk0, 256>>>(x, fw_in_w, bw_in_w, fw_ow, bw_ow);

    dim3 g1((Mrows + 127) / 128, 12, 1);
    k_gemm_in<<<g1, 256>>>();

    dim3 g2(DIn / 128, (Lseq + LCH - 1) / LCH, 2 * Bsz);
    k_conv<<<g2, 128>>>(fw_cw, fw_cb, bw_cw, bw_cb);

    int nrows = 2 * Mrows;
    k_proj<<<(nrows + 7) / 8, 256>>>(fw_xpw, fw_dtw, fw_dtb,
                                     bw_xpw, bw_dtw, bw_dtb);

    dim3 g4(DIn / 128, NCH, 2 * Bsz);      // 3 x 8 x 64
    k_scan1<<<g4, 128>>>(fw_Alog, bw_Alog);
    k_scan2<<<g4, 128>>>(fw_Alog, fw_D, bw_Alog, bw_D);

    dim3 g5((Mrows + 127) / 128, Dm / 64, 1);
    k_gemm_out<<<g5, 256>>>(out);
}

// round 8
// speedup vs baseline: 2.4121x; 1.0041x over previous
#include <cuda_runtime.h>
#include <cuda_bf16.h>
#include <cstdint>
#include <cstddef>
#include <math.h>

#define Bsz   32
#define Lseq  577
#define Dm    192
#define DIn   384
#define DSt   8
#define RK    12
#define NPJ   28
#define Mrows (Bsz*Lseq)   // 18464
#define NCH   8            // scan chunks
#define CLEN  73           // 8*73 = 584 >= 577

// bw-direction intermediates stored at PHYSICAL sequence index (unflipped):
// GEMMs need no flips; conv mirrors its window; scans walk backwards for bw.

// ---- scratch ----
__device__ float g_xz[2][Mrows][2*DIn];   // in-proj output (x_part | z)
__device__ float g_xc[2][Mrows][DIn];     // conv+silu output
__device__ float g_dt[2][Mrows][DIn];     // dt after softplus
__device__ float g_bc[2][Mrows][16];      // tanh(B) (8) | tanh(C) (8)
__device__ float g_tr[2][Bsz][DIn][NCH][16]; // chunk transfer: Aprod[8] | Bacc[8]

// bf16 split-precision operand buffers
__device__ __nv_bfloat16 g_xh[Mrows][Dm],  g_xl[Mrows][Dm];     // input x hi/lo
__device__ __nv_bfloat16 g_wih[2][2*DIn][Dm], g_wil[2][2*DIn][Dm]; // in_w hi/lo
__device__ __nv_bfloat16 g_woh[2][Dm][DIn], g_wol[2][Dm][DIn];  // out_w hi/lo
__device__ __nv_bfloat16 g_ysh[2][Mrows][DIn], g_ysl[2][Mrows][DIn]; // ys hi/lo

// FMA-only exp for x <= 0, degree-4 (rel err ~4e-5; MUFU stays free).
__device__ __forceinline__ float fexp_neg(float x)
{
    x = fmaxf(x, -80.f);
    float z  = x * 1.4426950408889634f;
    float fi = (z + 12582912.0f) - 12582912.0f;
    float f  = z - fi;
    float p  = 9.6181291e-3f;
    p = fmaf(p, f, 5.5504109e-2f);
    p = fmaf(p, f, 2.4022651e-1f);
    p = fmaf(p, f, 6.9314718e-1f);
    p = fmaf(p, f, 1.0f);
    int ie = (int)fi;
    return __int_as_float(__float_as_int(p) + (ie << 23));
}

// ---- tensor-core helpers ----
__device__ __forceinline__ unsigned smem_u32(const void* p) {
    return (unsigned)__cvta_generic_to_shared(p);
}
__device__ __forceinline__ void ldsm_x4(unsigned& r0, unsigned& r1, unsigned& r2, unsigned& r3,
                                        unsigned addr) {
    asm volatile("ldmatrix.sync.aligned.m8n8.x4.shared.b16 {%0,%1,%2,%3}, [%4];"
                 : "=r"(r0), "=r"(r1), "=r"(r2), "=r"(r3) : "r"(addr));
}
__device__ __forceinline__ void ldsm_x2(unsigned& r0, unsigned& r1, unsigned addr) {
    asm volatile("ldmatrix.sync.aligned.m8n8.x2.shared.b16 {%0,%1}, [%2];"
                 : "=r"(r0), "=r"(r1) : "r"(addr));
}
__device__ __forceinline__ void mma_bf16(float* c, const unsigned* a, const unsigned* b) {
    asm volatile("mma.sync.aligned.m16n8k16.row.col.f32.bf16.bf16.f32 "
                 "{%0,%1,%2,%3},{%4,%5,%6,%7},{%8,%9},{%0,%1,%2,%3};"
                 : "+f"(c[0]), "+f"(c[1]), "+f"(c[2]), "+f"(c[3])
                 : "r"(a[0]), "r"(a[1]), "r"(a[2]), "r"(a[3]), "r"(b[0]), "r"(b[1]));
}
// fp32 pair -> bf16x2 hi + bf16x2 lo (residual). low half = even element.
__device__ __forceinline__ void cvt_hilo(float f0, float f1, unsigned& hi, unsigned& lo) {
    __nv_bfloat162 h = __floats2bfloat162_rn(f0, f1);
    float2 hf = __bfloat1622float2(h);
    __nv_bfloat162 l = __floats2bfloat162_rn(f0 - hf.x, f1 - hf.y);
    hi = *reinterpret_cast<unsigned*>(&h);
    lo = *reinterpret_cast<unsigned*>(&l);
}

#define KP   56   // smem row pitch in bf16 elems: 112B (16B-aligned, ldmatrix conflict-free)

// =====================================================================
// K0: one-time fp32 -> bf16 hi/lo conversion of x and all GEMM weights
// =====================================================================
#define XP   ((long)Mrows*Dm/2)        // pairs in x
#define WIP  ((long)(2*DIn)*Dm/2)      // pairs per in_w
#define WOP  ((long)Dm*DIn/2)          // pairs per out_w
#define TOTP (XP + 2*WIP + 2*WOP)

__global__ void k_cvt(const float* __restrict__ x,
                      const float* __restrict__ wi_fw, const float* __restrict__ wi_bw,
                      const float* __restrict__ wo_fw, const float* __restrict__ wo_bw)
{
    long p = (long)blockIdx.x * 256 + threadIdx.x;
    if (p >= TOTP) return;
    const float* src; unsigned *dh, *dl; long off;
    if (p < XP)                    { src = x;     dh = (unsigned*)g_xh;      dl = (unsigned*)g_xl;      off = p; }
    else if (p < XP + WIP)         { src = wi_fw; dh = (unsigned*)g_wih[0]; dl = (unsigned*)g_wil[0]; off = p - XP; }
    else if (p < XP + 2*WIP)       { src = wi_bw; dh = (unsigned*)g_wih[1]; dl = (unsigned*)g_wil[1]; off = p - XP - WIP; }
    else if (p < XP + 2*WIP + WOP) { src = wo_fw; dh = (unsigned*)g_woh[0]; dl = (unsigned*)g_wol[0]; off = p - XP - 2*WIP; }
    else                           { src = wo_bw; dh = (unsigned*)g_woh[1]; dl = (unsigned*)g_wol[1]; off = p - XP - 2*WIP - WOP; }
    float2 v = ((const float2*)src)[off];
    unsigned h, l;
    cvt_hilo(v.x, v.y, h, l);
    dh[off] = h; dl[off] = l;
}

// =====================================================================
// K1: xz = x @ [in_w_fw | in_w_bw].T  (fused N=1536, no flips)
// block 128m x 128n, 8 warps (warp tile 64m x 32n), bf16 3-pass mma
// =====================================================================
__global__ void __launch_bounds__(256)
k_gemm_in()
{
    __shared__ __align__(16) __nv_bfloat16 Ah[128*KP], Al[128*KP], Bh[128*KP], Bl[128*KP];

    const int m0   = blockIdx.x * 128;
    const int nblk = blockIdx.y;            // 0..11
    const int dir  = nblk >= 6;
    const int n0l  = (nblk - 6*dir) * 128;  // local col base within 768

    const int tid = threadIdx.x;
    const int warp = tid >> 5, lane = tid & 31;
    const int wm = warp >> 2, wn = warp & 3;      // wm:0-1 (64 rows), wn:0-3 (32 cols)

    float acc[4][4][4];
    #pragma unroll
    for (int i = 0; i < 4; i++)
        #pragma unroll
        for (int j = 0; j < 4; j++)
            #pragma unroll
            for (int r = 0; r < 4; r++) acc[i][j][r] = 0.f;

    const unsigned sAh = smem_u32(Ah), sAl = smem_u32(Al);
    const unsigned sBh = smem_u32(Bh), sBl = smem_u32(Bl);

    for (int kc = 0; kc < Dm; kc += 32) {
        #pragma unroll
        for (int i = 0; i < 2; i++) {
            int s = tid + i * 256;          // 0..511
            int r = s >> 2, c8 = (s & 3) * 8;  // row 0..127, col slot (8 bf16 = 16B)
            int m = m0 + r;
            uint4 vh = make_uint4(0,0,0,0), vl = make_uint4(0,0,0,0);
            if (m < Mrows) {
                vh = *(const uint4*)&g_xh[m][kc + c8];
                vl = *(const uint4*)&g_xl[m][kc + c8];
            }
            *(uint4*)&Ah[r*KP + c8] = vh;
            *(uint4*)&Al[r*KP + c8] = vl;
            *(uint4*)&Bh[r*KP + c8] = *(const uint4*)&g_wih[dir][n0l + r][kc + c8];
            *(uint4*)&Bl[r*KP + c8] = *(const uint4*)&g_wil[dir][n0l + r][kc + c8];
        }
        __syncthreads();

        #pragma unroll
        for (int kk = 0; kk < 32; kk += 16) {
            unsigned bh[4][2], bl[4][2];
            #pragma unroll
            for (int ni = 0; ni < 4; ni++) {
                int row  = wn*32 + ni*8 + (lane & 7);
                int kcol = kk + ((lane >> 3) & 1) * 8;
                unsigned off = (unsigned)(row * KP + kcol) * 2;
                ldsm_x2(bh[ni][0], bh[ni][1], sBh + off);
                ldsm_x2(bl[ni][0], bl[ni][1], sBl + off);
            }
            #pragma unroll
            for (int mi = 0; mi < 4; mi++) {
                int row  = wm*64 + mi*16 + (lane & 7) + ((lane >> 3) & 1) * 8;
                int kcol = kk + (lane >> 4) * 8;
                unsigned off = (unsigned)(row * KP + kcol) * 2;
                unsigned ah[4], al[4];
                ldsm_x4(ah[0], ah[1], ah[2], ah[3], sAh + off);
                ldsm_x4(al[0], al[1], al[2], al[3], sAl + off);
                #pragma unroll
                for (int ni = 0; ni < 4; ni++) {
                    mma_bf16(acc[mi][ni], ah, bh[ni]);
                    mma_bf16(acc[mi][ni], al, bh[ni]);
                    mma_bf16(acc[mi][ni], ah, bl[ni]);
                }
            }
        }
        __syncthreads();
    }

    const int g = lane >> 2, t4 = lane & 3;
    #pragma unroll
    for (int mi = 0; mi < 4; mi++) {
        #pragma unroll
        for (int ni = 0; ni < 4; ni++) {
            int col = n0l + wn*32 + ni*8 + t4*2;
            int mr  = m0 + wm*64 + mi*16 + g;
            if (mr < Mrows)
                *(float2*)&g_xz[dir][mr][col]   = make_float2(acc[mi][ni][0], acc[mi][ni][1]);
            if (mr + 8 < Mrows)
                *(float2*)&g_xz[dir][mr+8][col] = make_float2(acc[mi][ni][2], acc[mi][ni][3]);
        }
    }
}

// =====================================================================
// K2: causal depthwise conv (k=4) + bias + SiLU.
// =====================================================================
#define LCH 8
__global__ void k_conv(const float* __restrict__ cw_fw, const float* __restrict__ cb_fw,
                       const float* __restrict__ cw_bw, const float* __restrict__ cb_bw)
{
    const int ch  = blockIdx.x * 128 + threadIdx.x;
    const int l0  = blockIdx.y * LCH;
    const int b   = blockIdx.z & 31;
    const int dir = blockIdx.z >> 5;

    const float* cw = (dir ? cw_bw : cw_fw) + ch * 4;
    const float W0 = dir ? cw[3] : cw[0];
    const float W1 = dir ? cw[2] : cw[1];
    const float W2 = dir ? cw[1] : cw[2];
    const float W3 = dir ? cw[0] : cw[3];
    const float bias = (dir ? cb_bw : cb_fw)[ch];

    const float* __restrict__ src = &g_xz[dir][(size_t)b * Lseq][0];  // stride 768
    float*       __restrict__ dst = &g_xc[dir][(size_t)b * Lseq][0];  // stride 384

    const int poff = dir ? 0 : -3;
    const int coff = dir ? 3 : 0;
    float x0 = 0.f, x1 = 0.f, x2 = 0.f;
    {
        int p0 = l0 + poff, p1 = p0 + 1, p2 = p0 + 2;
        if (p0 >= 0 && p0 < Lseq) x0 = src[(size_t)p0 * (2*DIn) + ch];
        if (p1 >= 0 && p1 < Lseq) x1 = src[(size_t)p1 * (2*DIn) + ch];
        if (p2 >= 0 && p2 < Lseq) x2 = src[(size_t)p2 * (2*DIn) + ch];
    }

    #pragma unroll
    for (int i = 0; i < LCH; i++) {
        int l = l0 + i;
        int q = l + coff;
        float x3 = (q < Lseq) ? src[(size_t)q * (2*DIn) + ch] : 0.f;
        float v = fmaf(W0, x0, fmaf(W1, x1, fmaf(W2, x2, fmaf(W3, x3, bias))));
        v = v / (1.f + __expf(-v));
        if (l < Lseq) dst[(size_t)l * DIn + ch] = v;
        x0 = x1; x1 = x2; x2 = x3;
    }
}

// =====================================================================
// K3: x_proj + tanh(B,C) + dt lowrank + softplus.
// 2 rows per warp: each weight float4 load feeds both rows' FMAs
// (halves the L1 wavefront traffic that dominated this kernel).
// =====================================================================
__device__ __forceinline__ float softplus_stable(float v) {
    return v > 20.f ? v : log1pf(expf(v));
}

__global__ void __launch_bounds__(256)
k_proj(const float* __restrict__ xp_fw, const float* __restrict__ dw_fw,
       const float* __restrict__ db_fw,
       const float* __restrict__ xp_bw, const float* __restrict__ dw_bw,
       const float* __restrict__ db_bw)
{
    const int warp = threadIdx.x >> 5, lane = threadIdx.x & 31;
    // each warp: rows (r0, r0+1); Mrows even so both rows share dir
    const long r0 = ((long)blockIdx.x * 8 + warp) * 2;   // < 2*Mrows (exact grid)
    const int dir = r0 >= Mrows;
    const int m   = (int)(r0 - (long)dir * Mrows);

    const float* __restrict__ xpw = dir ? xp_bw : xp_fw;   // [28][384]
    const float* __restrict__ dw  = dir ? dw_bw : dw_fw;   // [384][12]
    const float* __restrict__ db  = dir ? db_bw : db_fw;   // [384]

    const float4* __restrict__ rowa4 = (const float4*)g_xc[dir][m];
    const float4* __restrict__ rowb4 = (const float4*)g_xc[dir][m + 1];
    float4 xa[3], xb[3];
    #pragma unroll
    for (int q = 0; q < 3; q++) { xa[q] = rowa4[lane + 32*q]; xb[q] = rowb4[lane + 32*q]; }

    float dta[RK], dtb[RK];
    #pragma unroll
    for (int j = 0; j < NPJ; j++) {
        const float4* wj4 = (const float4*)(xpw + (size_t)j * DIn);
        float sa = 0.f, sb = 0.f;
        #pragma unroll
        for (int q = 0; q < 3; q++) {
            float4 w = wj4[lane + 32*q];
            sa = fmaf(xa[q].x, w.x, sa); sb = fmaf(xb[q].x, w.x, sb);
            sa = fmaf(xa[q].y, w.y, sa); sb = fmaf(xb[q].y, w.y, sb);
            sa = fmaf(xa[q].z, w.z, sa); sb = fmaf(xb[q].z, w.z, sb);
            sa = fmaf(xa[q].w, w.w, sa); sb = fmaf(xb[q].w, w.w, sb);
        }
        #pragma unroll
        for (int o = 16; o; o >>= 1) {
            sa += __shfl_xor_sync(0xffffffffu, sa, o);
            sb += __shfl_xor_sync(0xffffffffu, sb, o);
        }
        if (j < RK) {
            dta[j] = sa; dtb[j] = sb;
        } else {
            if (lane == 0) {
                g_bc[dir][m][j - RK]     = tanhf(sa);
                g_bc[dir][m + 1][j - RK] = tanhf(sb);
            }
        }
    }

    #pragma unroll
    for (int i = 0; i < 12; i++) {
        int ch = lane + 32*i;
        const float4* wr4 = (const float4*)(dw + (size_t)ch * RK);  // 48B rows, 16B aligned
        float4 w0 = wr4[0], w1 = wr4[1], w2 = wr4[2];
        float bb = db[ch];
        float sa = bb, sb = bb;
        sa = fmaf(dta[0],  w0.x, sa); sb = fmaf(dtb[0],  w0.x, sb);
        sa = fmaf(dta[1],  w0.y, sa); sb = fmaf(dtb[1],  w0.y, sb);
        sa = fmaf(dta[2],  w0.z, sa); sb = fmaf(dtb[2],  w0.z, sb);
        sa = fmaf(dta[3],  w0.w, sa); sb = fmaf(dtb[3],  w0.w, sb);
        sa = fmaf(dta[4],  w1.x, sa); sb = fmaf(dtb[4],  w1.x, sb);
        sa = fmaf(dta[5],  w1.y, sa); sb = fmaf(dtb[5],  w1.y, sb);
        sa = fmaf(dta[6],  w1.z, sa); sb = fmaf(dtb[6],  w1.z, sb);
        sa = fmaf(dta[7],  w1.w, sa); sb = fmaf(dtb[7],  w1.w, sb);
        sa = fmaf(dta[8],  w2.x, sa); sb = fmaf(dtb[8],  w2.x, sb);
        sa = fmaf(dta[9],  w2.y, sa); sb = fmaf(dtb[9],  w2.y, sb);
        sa = fmaf(dta[10], w2.z, sa); sb = fmaf(dtb[10], w2.z, sb);
        sa = fmaf(dta[11], w2.w, sa); sb = fmaf(dtb[11], w2.w, sb);
        g_dt[dir][m][ch]     = softplus_stable(sa) + 1e-4f;
        g_dt[dir][m + 1][ch] = softplus_stable(sb) + 1e-4f;
    }
}

// =====================================================================
// K4a: scan phase 1 — chunk transfer (Aprod, Bacc). bw walks backwards.
// =====================================================================
__global__ void k_scan1(const float* __restrict__ Al_fw, const float* __restrict__ Al_bw)
{
    const int ch    = blockIdx.x * 128 + threadIdx.x;
    const int chunk = blockIdx.y;
    const int b     = blockIdx.z & 31;
    const int dir   = blockIdx.z >> 5;

    const float* Alog = (dir ? Al_bw : Al_fw) + (size_t)ch * DSt;
    float a[DSt];
    #pragma unroll
    for (int s = 0; s < DSt; s++) a[s] = -expf(Alog[s]);

    const size_t rbase = (size_t)b * Lseq;
    const float* __restrict__ dtp = &g_dt[dir][rbase][0];
    const float* __restrict__ xcp = &g_xc[dir][rbase][0];
    const float4* __restrict__ bc4 = (const float4*)&g_bc[dir][rbase][0];

    const int l0 = chunk * CLEN;
    const int l1 = min(l0 + CLEN, Lseq);

    float st[DSt], Ap[DSt];
    #pragma unroll
    for (int s = 0; s < DSt; s++) { st[s] = 0.f; Ap[s] = 1.f; }

    for (int l = l0; l < l1; l++) {
        const int pl = dir ? (Lseq - 1 - l) : l;
        const size_t off = (size_t)pl * DIn + ch;
        const float dt = dtp[off];
        const float xx = xcp[off];
        float4 b0 = bc4[(size_t)pl*4 + 0];
        float4 b1 = bc4[(size_t)pl*4 + 1];
        const float bv[DSt] = {b0.x,b0.y,b0.z,b0.w,b1.x,b1.y,b1.z,b1.w};

        #pragma unroll
        for (int s = 0; s < DSt; s++) {
            float da = fexp_neg(dt * a[s]);
            float bx = bv[s] * xx;
            st[s] = fmaf(da, st[s] - bx, bx);
            Ap[s] *= da;
        }
    }

    float* tr = &g_tr[dir][b][ch][chunk][0];
    #pragma unroll
    for (int s = 0; s < DSt; s++) { tr[s] = Ap[s]; tr[8 + s] = st[s]; }
}

// =====================================================================
// K4b: scan phase 2+3 — compose init, replay chunk with y*silu(z),
// write ys as bf16 hi/lo for the output GEMM.
// =====================================================================
__global__ void k_scan2(const float* __restrict__ Al_fw, const float* __restrict__ Dk_fw,
                        const float* __restrict__ Al_bw, const float* __restrict__ Dk_bw)
{
    const int ch    = blockIdx.x * 128 + threadIdx.x;
    const int chunk = blockIdx.y;
    const int b     = blockIdx.z & 31;
    const int dir   = blockIdx.z >> 5;

    const float* Alog = (dir ? Al_bw : Al_fw) + (size_t)ch * DSt;
    float a[DSt];
    #pragma unroll
    for (int s = 0; s < DSt; s++) a[s] = -expf(Alog[s]);
    const float Dsk = (dir ? Dk_bw : Dk_fw)[ch];

    float st[DSt];
    #pragma unroll
    for (int s = 0; s < DSt; s++) st[s] = 0.f;
    {
        const float* tr = &g_tr[dir][b][ch][0][0];
        for (int c = 0; c < chunk; c++) {
            const float* t = tr + c * 16;
            #pragma unroll
            for (int s = 0; s < DSt; s++)
                st[s] = fmaf(t[s], st[s], t[8 + s]);
        }
    }

    const size_t rbase = (size_t)b * Lseq;
    const float* __restrict__ dtp = &g_dt[dir][rbase][0];
    const float* __restrict__ xcp = &g_xc[dir][rbase][0];
    const float* __restrict__ zp  = &g_xz[dir][rbase][DIn];
    const float4* __restrict__ bc4 = (const float4*)&g_bc[dir][rbase][0];
    __nv_bfloat16* __restrict__ ysh = &g_ysh[dir][rbase][0];
    __nv_bfloat16* __restrict__ ysl = &g_ysl[dir][rbase][0];

    const int l0 = chunk * CLEN;
    const int l1 = min(l0 + CLEN, Lseq);

    for (int l = l0; l < l1; l++) {
        const int pl = dir ? (Lseq - 1 - l) : l;
        const size_t off = (size_t)pl * DIn + ch;
        const float dt = dtp[off];
        const float xx = xcp[off];
        float4 b0 = bc4[(size_t)pl*4 + 0];
        float4 b1 = bc4[(size_t)pl*4 + 1];
        float4 c0 = bc4[(size_t)pl*4 + 2];
        float4 c1 = bc4[(size_t)pl*4 + 3];
        const float bv[DSt] = {b0.x,b0.y,b0.z,b0.w,b1.x,b1.y,b1.z,b1.w};
        const float cv[DSt] = {c0.x,c0.y,c0.z,c0.w,c1.x,c1.y,c1.z,c1.w};

        float acc = 0.f;
        #pragma unroll
        for (int s = 0; s < DSt; s++) {
            float da = fexp_neg(dt * a[s]);
            float bx = bv[s] * xx;
            st[s] = fmaf(da, st[s] - bx, bx);
            acc = fmaf(st[s], cv[s], acc);
        }
        float y = fmaf(Dsk, xx, acc);
        float z = zp[(size_t)pl * (2*DIn) + ch];
        float sz = z / (1.f + __expf(-z));
        float v = y * sz;
        __nv_bfloat16 h = __float2bfloat16(v);
        ysh[off] = h;
        ysl[off] = __float2bfloat16(v - __bfloat162float(h));
    }
}

// =====================================================================
// K5: out = 0.5*( ys_fw @ ow_fw.T + ys_bw @ ow_bw.T )  (fused K=768)
// block 128m x 64n, 8 warps (warp 32m x 32n), bf16 3-pass mma
// =====================================================================
__global__ void __launch_bounds__(256)
k_gemm_out(float* __restrict__ out)
{
    __shared__ __align__(16) __nv_bfloat16 Ah[128*KP], Al[128*KP], Bh[64*KP], Bl[64*KP];

    const int m0 = blockIdx.x * 128;
    const int n0 = blockIdx.y * 64;

    const int tid = threadIdx.x;
    const int warp = tid >> 5, lane = tid & 31;
    const int wm = warp >> 1, wn = warp & 1;   // wm:0-3 (32 rows), wn:0-1 (32 cols)

    float acc[2][4][4];
    #pragma unroll
    for (int i = 0; i < 2; i++)
        #pragma unroll
        for (int j = 0; j < 4; j++)
            #pragma unroll
            for (int r = 0; r < 4; r++) acc[i][j][r] = 0.f;

    const unsigned sAh = smem_u32(Ah), sAl = smem_u32(Al);
    const unsigned sBh = smem_u32(Bh), sBl = smem_u32(Bl);

    for (int kc = 0; kc < 2*DIn; kc += 32) {
        const int dirk = kc >= DIn;
        const int kcl  = kc - DIn * dirk;

        #pragma unroll
        for (int i = 0; i < 2; i++) {
            int s = tid + i * 256;             // 0..511
            int r = s >> 2, c8 = (s & 3) * 8;  // row 0..127
            int m = m0 + r;
            uint4 vh = make_uint4(0,0,0,0), vl = make_uint4(0,0,0,0);
            if (m < Mrows) {
                vh = *(const uint4*)&g_ysh[dirk][m][kcl + c8];
                vl = *(const uint4*)&g_ysl[dirk][m][kcl + c8];
            }
            *(uint4*)&Ah[r*KP + c8] = vh;
            *(uint4*)&Al[r*KP + c8] = vl;
        }
        {
            int r = tid >> 2, c8 = (tid & 3) * 8;   // r: 0..63
            *(uint4*)&Bh[r*KP + c8] = *(const uint4*)&g_woh[dirk][n0 + r][kcl + c8];
            *(uint4*)&Bl[r*KP + c8] = *(const uint4*)&g_wol[dirk][n0 + r][kcl + c8];
        }
        __syncthreads();

        #pragma unroll
        for (int kk = 0; kk < 32; kk += 16) {
            unsigned bh[4][2], bl[4][2];
            #pragma unroll
            for (int ni = 0; ni < 4; ni++) {
                int row  = wn*32 + ni*8 + (lane & 7);
                int kcol = kk + ((lane >> 3) & 1) * 8;
                unsigned off = (unsigned)(row * KP + kcol) * 2;
                ldsm_x2(bh[ni][0], bh[ni][1], sBh + off);
                ldsm_x2(bl[ni][0], bl[ni][1], sBl + off);
            }
            #pragma unroll
            for (int mi = 0; mi < 2; mi++) {
                int row  = wm*32 + mi*16 + (lane & 7) + ((lane >> 3) & 1) * 8;
                int kcol = kk + (lane >> 4) * 8;
                unsigned off = (unsigned)(row * KP + kcol) * 2;
                unsigned ah[4], al[4];
                ldsm_x4(ah[0], ah[1], ah[2], ah[3], sAh + off);
                ldsm_x4(al[0], al[1], al[2], al[3], sAl + off);
                #pragma unroll
                for (int ni = 0; ni < 4; ni++) {
                    mma_bf16(acc[mi][ni], ah, bh[ni]);
                    mma_bf16(acc[mi][ni], al, bh[ni]);
                    mma_bf16(acc[mi][ni], ah, bl[ni]);
                }
            }
        }
        __syncthreads();
    }

    const int g = lane >> 2, t4 = lane & 3;
    #pragma unroll
    for (int mi = 0; mi < 2; mi++) {
        #pragma unroll
        for (int ni = 0; ni < 4; ni++) {
            int col = n0 + wn*32 + ni*8 + t4*2;
            int mr  = m0 + wm*32 + mi*16 + g;
            if (mr < Mrows)
                *(float2*)&out[(size_t)mr * Dm + col] =
                    make_float2(0.5f*acc[mi][ni][0], 0.5f*acc[mi][ni][1]);
            if (mr + 8 < Mrows)
                *(float2*)&out[(size_t)(mr+8) * Dm + col] =
                    make_float2(0.5f*acc[mi][ni][2], 0.5f*acc[mi][ni][3]);
        }
    }
}

// =====================================================================
extern "C" void kernel_launch(void* const* d_in, const int* in_sizes, int n_in,
                              void* d_out, int out_size)
{
    const float* x        = (const float*)d_in[0];
    const float* fw_in_w  = (const float*)d_in[1];
    const float* fw_cw    = (const float*)d_in[2];
    const float* fw_cb    = (const float*)d_in[3];
    const float* fw_xpw   = (const float*)d_in[4];
    const float* fw_dtw   = (const float*)d_in[5];
    const float* fw_dtb   = (const float*)d_in[6];
    const float* fw_Alog  = (const float*)d_in[7];
    const float* fw_D     = (const float*)d_in[8];
    const float* fw_ow    = (const float*)d_in[9];
    const float* bw_in_w  = (const float*)d_in[10];
    const float* bw_cw    = (const float*)d_in[11];
    const float* bw_cb    = (const float*)d_in[12];
    const float* bw_xpw   = (const float*)d_in[13];
    const float* bw_dtw   = (const float*)d_in[14];
    const float* bw_dtb   = (const float*)d_in[15];
    const float* bw_Alog  = (const float*)d_in[16];
    const float* bw_D     = (const float*)d_in[17];
    const float* bw_ow    = (const float*)d_in[18];
    float* out = (float*)d_out;

    long nblk0 = (TOTP + 255) / 256;
    k_cvt<<<(unsigned)nblk0, 256>>>(x, fw_in_w, bw_in_w, fw_ow, bw_ow);

    dim3 g1((Mrows + 127) / 128, 12, 1);
    k_gemm_in<<<g1, 256>>>();

    dim3 g2(DIn / 128, (Lseq + LCH - 1) / LCH, 2 * Bsz);
    k_conv<<<g2, 128>>>(fw_cw, fw_cb, bw_cw, bw_cb);

    int nrows2 = 2 * Mrows / 16;   // 2308 blocks, 8 warps x 2 rows each
    k_proj<<<nrows2, 256>>>(fw_xpw, fw_dtw, fw_dtb,
                            bw_xpw, bw_dtw, bw_dtb);

    dim3 g4(DIn / 128, NCH, 2 * Bsz);      // 3 x 8 x 64
    k_scan1<<<g4, 128>>>(fw_Alog, bw_Alog);
    k_scan2<<<g4, 128>>>(fw_Alog, fw_D, bw_Alog, bw_D);

    dim3 g5((Mrows + 127) / 128, Dm / 64, 1);
    k_gemm_out<<<g5, 256>>>(out);
}

// round 9
// speedup vs baseline: 2.5241x; 1.0464x over previous
#include <cuda_runtime.h>
#include <cuda_bf16.h>
#include <cstdint>
#include <cstddef>
#include <math.h>

#define Bsz   32
#define Lseq  577
#define Dm    192
#define DIn   384
#define DSt   8
#define RK    12
#define NPJ   28
#define Mrows (Bsz*Lseq)   // 18464
#define NCH   8            // scan chunks
#define CLEN  73           // 8*73 = 584 >= 577

// bw-direction intermediates stored at PHYSICAL sequence index (unflipped).

// ---- scratch ----
__device__ float g_xz[2][Mrows][2*DIn];   // in-proj output (x_part | z)
__device__ float g_xc[2][Mrows][DIn];     // conv+silu output (fp32, for scans)
__device__ float g_dt[2][Mrows][DIn];     // dt after softplus
__device__ float g_bc[2][Mrows][16];      // tanh(B) (8) | tanh(C) (8)
__device__ float g_tr[2][Bsz][DIn][NCH][16]; // chunk transfer: Aprod[8] | Bacc[8]

// bf16 split-precision operand buffers
__device__ __nv_bfloat16 g_xh[Mrows][Dm],  g_xl[Mrows][Dm];        // input x hi/lo
__device__ __nv_bfloat16 g_wih[2][2*DIn][Dm], g_wil[2][2*DIn][Dm]; // in_w hi/lo
__device__ __nv_bfloat16 g_woh[2][Dm][DIn], g_wol[2][Dm][DIn];     // out_w hi/lo
__device__ __nv_bfloat16 g_ysh[2][Mrows][DIn], g_ysl[2][Mrows][DIn]; // ys hi/lo
__device__ __nv_bfloat16 g_xch[2][Mrows][DIn], g_xcl[2][Mrows][DIn]; // conv out hi/lo
__device__ __nv_bfloat16 g_xph[2][32][DIn],  g_xpl[2][32][DIn];    // xproj_w hi/lo (rows 28..31 zero)
__device__ __nv_bfloat16 g_dwh[2][DIn][16],  g_dwl[2][DIn][16];    // dt_w hi/lo (cols 12..15 zero)
__device__ __nv_bfloat16 g_dtph[2][Mrows][16], g_dtpl[2][Mrows][16]; // dtp hi/lo (cols 12..15 zero)

// FMA-only exp for x <= 0, degree-4.
__device__ __forceinline__ float fexp_neg(float x)
{
    x = fmaxf(x, -80.f);
    float z  = x * 1.4426950408889634f;
    float fi = (z + 12582912.0f) - 12582912.0f;
    float f  = z - fi;
    float p  = 9.6181291e-3f;
    p = fmaf(p, f, 5.5504109e-2f);
    p = fmaf(p, f, 2.4022651e-1f);
    p = fmaf(p, f, 6.9314718e-1f);
    p = fmaf(p, f, 1.0f);
    int ie = (int)fi;
    return __int_as_float(__float_as_int(p) + (ie << 23));
}

// ---- tensor-core helpers ----
__device__ __forceinline__ unsigned smem_u32(const void* p) {
    return (unsigned)__cvta_generic_to_shared(p);
}
__device__ __forceinline__ void ldsm_x4(unsigned& r0, unsigned& r1, unsigned& r2, unsigned& r3,
                                        unsigned addr) {
    asm volatile("ldmatrix.sync.aligned.m8n8.x4.shared.b16 {%0,%1,%2,%3}, [%4];"
                 : "=r"(r0), "=r"(r1), "=r"(r2), "=r"(r3) : "r"(addr));
}
__device__ __forceinline__ void ldsm_x2(unsigned& r0, unsigned& r1, unsigned addr) {
    asm volatile("ldmatrix.sync.aligned.m8n8.x2.shared.b16 {%0,%1}, [%2];"
                 : "=r"(r0), "=r"(r1) : "r"(addr));
}
__device__ __forceinline__ void mma_bf16(float* c, const unsigned* a, const unsigned* b) {
    asm volatile("mma.sync.aligned.m16n8k16.row.col.f32.bf16.bf16.f32 "
                 "{%0,%1,%2,%3},{%4,%5,%6,%7},{%8,%9},{%0,%1,%2,%3};"
                 : "+f"(c[0]), "+f"(c[1]), "+f"(c[2]), "+f"(c[3])
                 : "r"(a[0]), "r"(a[1]), "r"(a[2]), "r"(a[3]), "r"(b[0]), "r"(b[1]));
}
__device__ __forceinline__ void cvt_hilo(float f0, float f1, unsigned& hi, unsigned& lo) {
    __nv_bfloat162 h = __floats2bfloat162_rn(f0, f1);
    float2 hf = __bfloat1622float2(h);
    __nv_bfloat162 l = __floats2bfloat162_rn(f0 - hf.x, f1 - hf.y);
    hi = *reinterpret_cast<unsigned*>(&h);
    lo = *reinterpret_cast<unsigned*>(&l);
}

#define KP   56   // pitch for 32-wide K tiles (112B rows)
#define KP2  24   // pitch for 16-wide K tiles (48B rows, ldmatrix conflict-free)

// =====================================================================
// K0: one-time fp32 -> bf16 hi/lo conversions (x, in_w, out_w, xproj_w, dt_w)
// =====================================================================
#define XP    ((long)Mrows*Dm/2)
#define WIP   ((long)(2*DIn)*Dm/2)
#define WOP   ((long)Dm*DIn/2)
#define XPP   ((long)NPJ*DIn/2)        // 5376 pairs per xproj_w
#define DWP   ((long)DIn*RK/2)         // 2304 pairs per dt_w
#define TOTP  (XP + 2*WIP + 2*WOP + 2*XPP + 2*DWP)

__global__ void k_cvt(const float* __restrict__ x,
                      const float* __restrict__ wi_fw, const float* __restrict__ wi_bw,
                      const float* __restrict__ wo_fw, const float* __restrict__ wo_bw,
                      const float* __restrict__ xp_fw, const float* __restrict__ xp_bw,
                      const float* __restrict__ dw_fw, const float* __restrict__ dw_bw)
{
    long p = (long)blockIdx.x * 256 + threadIdx.x;
    if (p >= TOTP) return;
    const float* src; unsigned *dh, *dl; long soff, doff;
    if (p < XP)                    { src = x;     dh = (unsigned*)g_xh;     dl = (unsigned*)g_xl;     soff = doff = p; }
    else if (p < XP + WIP)         { src = wi_fw; dh = (unsigned*)g_wih[0]; dl = (unsigned*)g_wil[0]; soff = doff = p - XP; }
    else if (p < XP + 2*WIP)       { src = wi_bw; dh = (unsigned*)g_wih[1]; dl = (unsigned*)g_wil[1]; soff = doff = p - XP - WIP; }
    else if (p < XP + 2*WIP + WOP) { src = wo_fw; dh = (unsigned*)g_woh[0]; dl = (unsigned*)g_wol[0]; soff = doff = p - XP - 2*WIP; }
    else if (p < XP + 2*WIP + 2*WOP) { src = wo_bw; dh = (unsigned*)g_woh[1]; dl = (unsigned*)g_wol[1]; soff = doff = p - XP - 2*WIP - WOP; }
    else if (p < XP + 2*WIP + 2*WOP + XPP) { src = xp_fw; dh = (unsigned*)g_xph[0]; dl = (unsigned*)g_xpl[0]; soff = doff = p - XP - 2*WIP - 2*WOP; }
    else if (p < XP + 2*WIP + 2*WOP + 2*XPP) { src = xp_bw; dh = (unsigned*)g_xph[1]; dl = (unsigned*)g_xpl[1]; soff = doff = p - XP - 2*WIP - 2*WOP - XPP; }
    else if (p < XP + 2*WIP + 2*WOP + 2*XPP + DWP) {
        long q = p - XP - 2*WIP - 2*WOP - 2*XPP;   // 0..2303
        long ch = q / 6, cp = q % 6;
        src = dw_fw; dh = (unsigned*)g_dwh[0]; dl = (unsigned*)g_dwl[0];
        soff = ch * 6 + cp; doff = ch * 8 + cp;
    } else {
        long q = p - XP - 2*WIP - 2*WOP - 2*XPP - DWP;
        long ch = q / 6, cp = q % 6;
        src = dw_bw; dh = (unsigned*)g_dwh[1]; dl = (unsigned*)g_dwl[1];
        soff = ch * 6 + cp; doff = ch * 8 + cp;
    }
    float2 v = ((const float2*)src)[soff];
    unsigned h, l;
    cvt_hilo(v.x, v.y, h, l);
    dh[doff] = h; dl[doff] = l;
}

// =====================================================================
// K1: xz = x @ [in_w_fw | in_w_bw].T  (fused N=1536, no flips)
// =====================================================================
__global__ void __launch_bounds__(256)
k_gemm_in()
{
    __shared__ __align__(16) __nv_bfloat16 Ah[128*KP], Al[128*KP], Bh[128*KP], Bl[128*KP];

    const int m0   = blockIdx.x * 128;
    const int nblk = blockIdx.y;
    const int dir  = nblk >= 6;
    const int n0l  = (nblk - 6*dir) * 128;

    const int tid = threadIdx.x;
    const int warp = tid >> 5, lane = tid & 31;
    const int wm = warp >> 2, wn = warp & 3;

    float acc[4][4][4];
    #pragma unroll
    for (int i = 0; i < 4; i++)
        #pragma unroll
        for (int j = 0; j < 4; j++)
            #pragma unroll
            for (int r = 0; r < 4; r++) acc[i][j][r] = 0.f;

    const unsigned sAh = smem_u32(Ah), sAl = smem_u32(Al);
    const unsigned sBh = smem_u32(Bh), sBl = smem_u32(Bl);

    for (int kc = 0; kc < Dm; kc += 32) {
        #pragma unroll
        for (int i = 0; i < 2; i++) {
            int s = tid + i * 256;
            int r = s >> 2, c8 = (s & 3) * 8;
            int m = m0 + r;
            uint4 vh = make_uint4(0,0,0,0), vl = make_uint4(0,0,0,0);
            if (m < Mrows) {
                vh = *(const uint4*)&g_xh[m][kc + c8];
                vl = *(const uint4*)&g_xl[m][kc + c8];
            }
            *(uint4*)&Ah[r*KP + c8] = vh;
            *(uint4*)&Al[r*KP + c8] = vl;
            *(uint4*)&Bh[r*KP + c8] = *(const uint4*)&g_wih[dir][n0l + r][kc + c8];
            *(uint4*)&Bl[r*KP + c8] = *(const uint4*)&g_wil[dir][n0l + r][kc + c8];
        }
        __syncthreads();

        #pragma unroll
        for (int kk = 0; kk < 32; kk += 16) {
            unsigned bh[4][2], bl[4][2];
            #pragma unroll
            for (int ni = 0; ni < 4; ni++) {
                int row  = wn*32 + ni*8 + (lane & 7);
                int kcol = kk + ((lane >> 3) & 1) * 8;
                unsigned off = (unsigned)(row * KP + kcol) * 2;
                ldsm_x2(bh[ni][0], bh[ni][1], sBh + off);
                ldsm_x2(bl[ni][0], bl[ni][1], sBl + off);
            }
            #pragma unroll
            for (int mi = 0; mi < 4; mi++) {
                int row  = wm*64 + mi*16 + (lane & 7) + ((lane >> 3) & 1) * 8;
                int kcol = kk + (lane >> 4) * 8;
                unsigned off = (unsigned)(row * KP + kcol) * 2;
                unsigned ah[4], al[4];
                ldsm_x4(ah[0], ah[1], ah[2], ah[3], sAh + off);
                ldsm_x4(al[0], al[1], al[2], al[3], sAl + off);
                #pragma unroll
                for (int ni = 0; ni < 4; ni++) {
                    mma_bf16(acc[mi][ni], ah, bh[ni]);
                    mma_bf16(acc[mi][ni], al, bh[ni]);
                    mma_bf16(acc[mi][ni], ah, bl[ni]);
                }
            }
        }
        __syncthreads();
    }

    const int g = lane >> 2, t4 = lane & 3;
    #pragma unroll
    for (int mi = 0; mi < 4; mi++) {
        #pragma unroll
        for (int ni = 0; ni < 4; ni++) {
            int col = n0l + wn*32 + ni*8 + t4*2;
            int mr  = m0 + wm*64 + mi*16 + g;
            if (mr < Mrows)
                *(float2*)&g_xz[dir][mr][col]   = make_float2(acc[mi][ni][0], acc[mi][ni][1]);
            if (mr + 8 < Mrows)
                *(float2*)&g_xz[dir][mr+8][col] = make_float2(acc[mi][ni][2], acc[mi][ni][3]);
        }
    }
}

// =====================================================================
// K2: causal depthwise conv (k=4) + bias + SiLU; writes fp32 + bf16 hi/lo.
// =====================================================================
#define LCH 8
__global__ void k_conv(const float* __restrict__ cw_fw, const float* __restrict__ cb_fw,
                       const float* __restrict__ cw_bw, const float* __restrict__ cb_bw)
{
    const int ch  = blockIdx.x * 128 + threadIdx.x;
    const int l0  = blockIdx.y * LCH;
    const int b   = blockIdx.z & 31;
    const int dir = blockIdx.z >> 5;

    const float* cw = (dir ? cw_bw : cw_fw) + ch * 4;
    const float W0 = dir ? cw[3] : cw[0];
    const float W1 = dir ? cw[2] : cw[1];
    const float W2 = dir ? cw[1] : cw[2];
    const float W3 = dir ? cw[0] : cw[3];
    const float bias = (dir ? cb_bw : cb_fw)[ch];

    const size_t rbase = (size_t)b * Lseq;
    const float* __restrict__ src = &g_xz[dir][rbase][0];
    float*       __restrict__ dst = &g_xc[dir][rbase][0];
    __nv_bfloat16* __restrict__ dsth = &g_xch[dir][rbase][0];
    __nv_bfloat16* __restrict__ dstl = &g_xcl[dir][rbase][0];

    const int poff = dir ? 0 : -3;
    const int coff = dir ? 3 : 0;
    float x0 = 0.f, x1 = 0.f, x2 = 0.f;
    {
        int p0 = l0 + poff, p1 = p0 + 1, p2 = p0 + 2;
        if (p0 >= 0 && p0 < Lseq) x0 = src[(size_t)p0 * (2*DIn) + ch];
        if (p1 >= 0 && p1 < Lseq) x1 = src[(size_t)p1 * (2*DIn) + ch];
        if (p2 >= 0 && p2 < Lseq) x2 = src[(size_t)p2 * (2*DIn) + ch];
    }

    #pragma unroll
    for (int i = 0; i < LCH; i++) {
        int l = l0 + i;
        int q = l + coff;
        float x3 = (q < Lseq) ? src[(size_t)q * (2*DIn) + ch] : 0.f;
        float v = fmaf(W0, x0, fmaf(W1, x1, fmaf(W2, x2, fmaf(W3, x3, bias))));
        v = v / (1.f + __expf(-v));
        if (l < Lseq) {
            size_t o = (size_t)l * DIn + ch;
            dst[o] = v;
            __nv_bfloat16 h = __float2bfloat16(v);
            dsth[o] = h;
            dstl[o] = __float2bfloat16(v - __bfloat162float(h));
        }
        x0 = x1; x1 = x2; x2 = x3;
    }
}

// =====================================================================
// K3a: x_proj GEMM: dt_bc = xc @ xproj_w.T  (N=28 padded to 32)
// block 128m x 32n, 8 warps (16m x 32n each), bf16 3-pass mma.
// Epilogue: cols<12 -> dtp hi/lo; cols 12..27 -> tanh -> g_bc.
// =====================================================================
__global__ void __launch_bounds__(256)
k_gemm_xp()
{
    __shared__ __align__(16) __nv_bfloat16 Ah[128*KP], Al[128*KP], Bh[32*KP], Bl[32*KP];

    const int m0  = blockIdx.x * 128;
    const int dir = blockIdx.y;

    const int tid = threadIdx.x;
    const int warp = tid >> 5, lane = tid & 31;

    float acc[4][4];
    #pragma unroll
    for (int j = 0; j < 4; j++)
        #pragma unroll
        for (int r = 0; r < 4; r++) acc[j][r] = 0.f;

    const unsigned sAh = smem_u32(Ah), sAl = smem_u32(Al);
    const unsigned sBh = smem_u32(Bh), sBl = smem_u32(Bl);

    for (int kc = 0; kc < DIn; kc += 32) {
        #pragma unroll
        for (int i = 0; i < 2; i++) {
            int s = tid + i * 256;
            int r = s >> 2, c8 = (s & 3) * 8;
            int m = m0 + r;
            uint4 vh = make_uint4(0,0,0,0), vl = make_uint4(0,0,0,0);
            if (m < Mrows) {
                vh = *(const uint4*)&g_xch[dir][m][kc + c8];
                vl = *(const uint4*)&g_xcl[dir][m][kc + c8];
            }
            *(uint4*)&Ah[r*KP + c8] = vh;
            *(uint4*)&Al[r*KP + c8] = vl;
        }
        if (tid < 128) {
            int r = tid >> 2, c8 = (tid & 3) * 8;   // r 0..31
            *(uint4*)&Bh[r*KP + c8] = *(const uint4*)&g_xph[dir][r][kc + c8];
            *(uint4*)&Bl[r*KP + c8] = *(const uint4*)&g_xpl[dir][r][kc + c8];
        }
        __syncthreads();

        #pragma unroll
        for (int kk = 0; kk < 32; kk += 16) {
            unsigned bh[4][2], bl[4][2];
            #pragma unroll
            for (int ni = 0; ni < 4; ni++) {
                int row  = ni*8 + (lane & 7);
                int kcol = kk + ((lane >> 3) & 1) * 8;
                unsigned off = (unsigned)(row * KP + kcol) * 2;
                ldsm_x2(bh[ni][0], bh[ni][1], sBh + off);
                ldsm_x2(bl[ni][0], bl[ni][1], sBl + off);
            }
            {
                int row  = warp*16 + (lane & 7) + ((lane >> 3) & 1) * 8;
                int kcol = kk + (lane >> 4) * 8;
                unsigned off = (unsigned)(row * KP + kcol) * 2;
                unsigned ah[4], al[4];
                ldsm_x4(ah[0], ah[1], ah[2], ah[3], sAh + off);
                ldsm_x4(al[0], al[1], al[2], al[3], sAl + off);
                #pragma unroll
                for (int ni = 0; ni < 4; ni++) {
                    mma_bf16(acc[ni], ah, bh[ni]);
                    mma_bf16(acc[ni], al, bh[ni]);
                    mma_bf16(acc[ni], ah, bl[ni]);
                }
            }
        }
        __syncthreads();
    }

    const int g = lane >> 2, t4 = lane & 3;
    #pragma unroll
    for (int ni = 0; ni < 4; ni++) {
        int col = ni*8 + t4*2;
        #pragma unroll
        for (int half = 0; half < 2; half++) {
            int mr = m0 + warp*16 + g + half*8;
            if (mr >= Mrows) continue;
            float v0 = acc[ni][half*2], v1 = acc[ni][half*2 + 1];
            if (col < RK) {
                unsigned h, l;
                cvt_hilo(v0, v1, h, l);
                *(unsigned*)&g_dtph[dir][mr][col] = h;
                *(unsigned*)&g_dtpl[dir][mr][col] = l;
            } else if (col < NPJ) {
                *(float2*)&g_bc[dir][mr][col - RK] = make_float2(tanhf(v0), tanhf(v1));
            }
        }
    }
}

// =====================================================================
// K3b: dt GEMM: dt = softplus(dtp @ dt_w.T + dt_b) + 1e-4  (K=12 pad 16)
// block 128m x 128n, 8 warps (64m x 32n), single K chunk, 3-pass mma.
// =====================================================================
__device__ __forceinline__ float softplus_stable(float v) {
    return v > 20.f ? v : log1pf(expf(v));
}

__global__ void __launch_bounds__(256)
k_gemm_dt(const float* __restrict__ db_fw, const float* __restrict__ db_bw)
{
    __shared__ __align__(16) __nv_bfloat16 Ah[128*KP2], Al[128*KP2], Bh[128*KP2], Bl[128*KP2];

    const int m0  = blockIdx.x * 128;
    const int n0  = blockIdx.y * 128;
    const int dir = blockIdx.z;
    const float* __restrict__ db = dir ? db_bw : db_fw;

    const int tid = threadIdx.x;
    const int warp = tid >> 5, lane = tid & 31;
    const int wm = warp >> 2, wn = warp & 3;

    float acc[4][4][4];
    #pragma unroll
    for (int i = 0; i < 4; i++)
        #pragma unroll
        for (int j = 0; j < 4; j++)
            #pragma unroll
            for (int r = 0; r < 4; r++) acc[i][j][r] = 0.f;

    const unsigned sAh = smem_u32(Ah), sAl = smem_u32(Al);
    const unsigned sBh = smem_u32(Bh), sBl = smem_u32(Bl);

    {
        int r = tid >> 1, c8 = (tid & 1) * 8;   // 128 rows x 16 cols
        int m = m0 + r;
        uint4 vh = make_uint4(0,0,0,0), vl = make_uint4(0,0,0,0);
        if (m < Mrows) {
            vh = *(const uint4*)&g_dtph[dir][m][c8];
            vl = *(const uint4*)&g_dtpl[dir][m][c8];
        }
        *(uint4*)&Ah[r*KP2 + c8] = vh;
        *(uint4*)&Al[r*KP2 + c8] = vl;
        *(uint4*)&Bh[r*KP2 + c8] = *(const uint4*)&g_dwh[dir][n0 + r][c8];
        *(uint4*)&Bl[r*KP2 + c8] = *(const uint4*)&g_dwl[dir][n0 + r][c8];
    }
    __syncthreads();

    {
        unsigned bh[4][2], bl[4][2];
        #pragma unroll
        for (int ni = 0; ni < 4; ni++) {
            int row  = wn*32 + ni*8 + (lane & 7);
            int kcol = ((lane >> 3) & 1) * 8;
            unsigned off = (unsigned)(row * KP2 + kcol) * 2;
            ldsm_x2(bh[ni][0], bh[ni][1], sBh + off);
            ldsm_x2(bl[ni][0], bl[ni][1], sBl + off);
        }
        #pragma unroll
        for (int mi = 0; mi < 4; mi++) {
            int row  = wm*64 + mi*16 + (lane & 7) + ((lane >> 3) & 1) * 8;
            int kcol = (lane >> 4) * 8;
            unsigned off = (unsigned)(row * KP2 + kcol) * 2;
            unsigned ah[4], al[4];
            ldsm_x4(ah[0], ah[1], ah[2], ah[3], sAh + off);
            ldsm_x4(al[0], al[1], al[2], al[3], sAl + off);
            #pragma unroll
            for (int ni = 0; ni < 4; ni++) {
                mma_bf16(acc[mi][ni], ah, bh[ni]);
                mma_bf16(acc[mi][ni], al, bh[ni]);
                mma_bf16(acc[mi][ni], ah, bl[ni]);
            }
        }
    }

    const int g = lane >> 2, t4 = lane & 3;
    #pragma unroll
    for (int mi = 0; mi < 4; mi++) {
        #pragma unroll
        for (int ni = 0; ni < 4; ni++) {
            int col = n0 + wn*32 + ni*8 + t4*2;
            float2 bb = *(const float2*)&db[col];
            #pragma unroll
            for (int half = 0; half < 2; half++) {
                int mr = m0 + wm*64 + mi*16 + g + half*8;
                if (mr >= Mrows) continue;
                float v0 = softplus_stable(acc[mi][ni][half*2]     + bb.x) + 1e-4f;
                float v1 = softplus_stable(acc[mi][ni][half*2 + 1] + bb.y) + 1e-4f;
                *(float2*)&g_dt[dir][mr][col] = make_float2(v0, v1);
            }
        }
    }
}

// =====================================================================
// K4a: scan phase 1 — chunk transfer (Aprod, Bacc). bw walks backwards.
// =====================================================================
__global__ void k_scan1(const float* __restrict__ Al_fw, const float* __restrict__ Al_bw)
{
    const int ch    = blockIdx.x * 128 + threadIdx.x;
    const int chunk = blockIdx.y;
    const int b     = blockIdx.z & 31;
    const int dir   = blockIdx.z >> 5;

    const float* Alog = (dir ? Al_bw : Al_fw) + (size_t)ch * DSt;
    float a[DSt];
    #pragma unroll
    for (int s = 0; s < DSt; s++) a[s] = -expf(Alog[s]);

    const size_t rbase = (size_t)b * Lseq;
    const float* __restrict__ dtp = &g_dt[dir][rbase][0];
    const float* __restrict__ xcp = &g_xc[dir][rbase][0];
    const float4* __restrict__ bc4 = (const float4*)&g_bc[dir][rbase][0];

    const int l0 = chunk * CLEN;
    const int l1 = min(l0 + CLEN, Lseq);

    float st[DSt], Ap[DSt];
    #pragma unroll
    for (int s = 0; s < DSt; s++) { st[s] = 0.f; Ap[s] = 1.f; }

    for (int l = l0; l < l1; l++) {
        const int pl = dir ? (Lseq - 1 - l) : l;
        const size_t off = (size_t)pl * DIn + ch;
        const float dt = dtp[off];
        const float xx = xcp[off];
        float4 b0 = bc4[(size_t)pl*4 + 0];
        float4 b1 = bc4[(size_t)pl*4 + 1];
        const float bv[DSt] = {b0.x,b0.y,b0.z,b0.w,b1.x,b1.y,b1.z,b1.w};

        #pragma unroll
        for (int s = 0; s < DSt; s++) {
            float da = fexp_neg(dt * a[s]);
            float bx = bv[s] * xx;
            st[s] = fmaf(da, st[s] - bx, bx);
            Ap[s] *= da;
        }
    }

    float* tr = &g_tr[dir][b][ch][chunk][0];
    #pragma unroll
    for (int s = 0; s < DSt; s++) { tr[s] = Ap[s]; tr[8 + s] = st[s]; }
}

// =====================================================================
// K4b: scan phase 2+3 — compose init, replay chunk with y*silu(z),
// write ys as bf16 hi/lo for the output GEMM.
// =====================================================================
__global__ void k_scan2(const float* __restrict__ Al_fw, const float* __restrict__ Dk_fw,
                        const float* __restrict__ Al_bw, const float* __restrict__ Dk_bw)
{
    const int ch    = blockIdx.x * 128 + threadIdx.x;
    const int chunk = blockIdx.y;
    const int b     = blockIdx.z & 31;
    const int dir   = blockIdx.z >> 5;

    const float* Alog = (dir ? Al_bw : Al_fw) + (size_t)ch * DSt;
    float a[DSt];
    #pragma unroll
    for (int s = 0; s < DSt; s++) a[s] = -expf(Alog[s]);
    const float Dsk = (dir ? Dk_bw : Dk_fw)[ch];

    float st[DSt];
    #pragma unroll
    for (int s = 0; s < DSt; s++) st[s] = 0.f;
    {
        const float* tr = &g_tr[dir][b][ch][0][0];
        for (int c = 0; c < chunk; c++) {
            const float* t = tr + c * 16;
            #pragma unroll
            for (int s = 0; s < DSt; s++)
                st[s] = fmaf(t[s], st[s], t[8 + s]);
        }
    }

    const size_t rbase = (size_t)b * Lseq;
    const float* __restrict__ dtp = &g_dt[dir][rbase][0];
    const float* __restrict__ xcp = &g_xc[dir][rbase][0];
    const float* __restrict__ zp  = &g_xz[dir][rbase][DIn];
    const float4* __restrict__ bc4 = (const float4*)&g_bc[dir][rbase][0];
    __nv_bfloat16* __restrict__ ysh = &g_ysh[dir][rbase][0];
    __nv_bfloat16* __restrict__ ysl = &g_ysl[dir][rbase][0];

    const int l0 = chunk * CLEN;
    const int l1 = min(l0 + CLEN, Lseq);

    for (int l = l0; l < l1; l++) {
        const int pl = dir ? (Lseq - 1 - l) : l;
        const size_t off = (size_t)pl * DIn + ch;
        const float dt = dtp[off];
        const float xx = xcp[off];
        float4 b0 = bc4[(size_t)pl*4 + 0];
        float4 b1 = bc4[(size_t)pl*4 + 1];
        float4 c0 = bc4[(size_t)pl*4 + 2];
        float4 c1 = bc4[(size_t)pl*4 + 3];
        const float bv[DSt] = {b0.x,b0.y,b0.z,b0.w,b1.x,b1.y,b1.z,b1.w};
        const float cv[DSt] = {c0.x,c0.y,c0.z,c0.w,c1.x,c1.y,c1.z,c1.w};

        float acc = 0.f;
        #pragma unroll
        for (int s = 0; s < DSt; s++) {
            float da = fexp_neg(dt * a[s]);
            float bx = bv[s] * xx;
            st[s] = fmaf(da, st[s] - bx, bx);
            acc = fmaf(st[s], cv[s], acc);
        }
        float y = fmaf(Dsk, xx, acc);
        float z = zp[(size_t)pl * (2*DIn) + ch];
        float sz = z / (1.f + __expf(-z));
        float v = y * sz;
        __nv_bfloat16 h = __float2bfloat16(v);
        ysh[off] = h;
        ysl[off] = __float2bfloat16(v - __bfloat162float(h));
    }
}

// =====================================================================
// K5: out = 0.5*( ys_fw @ ow_fw.T + ys_bw @ ow_bw.T )  (fused K=768)
// =====================================================================
__global__ void __launch_bounds__(256)
k_gemm_out(float* __restrict__ out)
{
    __shared__ __align__(16) __nv_bfloat16 Ah[128*KP], Al[128*KP], Bh[64*KP], Bl[64*KP];

    const int m0 = blockIdx.x * 128;
    const int n0 = blockIdx.y * 64;

    const int tid = threadIdx.x;
    const int warp = tid >> 5, lane = tid & 31;
    const int wm = warp >> 1, wn = warp & 1;

    float acc[2][4][4];
    #pragma unroll
    for (int i = 0; i < 2; i++)
        #pragma unroll
        for (int j = 0; j < 4; j++)
            #pragma unroll
            for (int r = 0; r < 4; r++) acc[i][j][r] = 0.f;

    const unsigned sAh = smem_u32(Ah), sAl = smem_u32(Al);
    const unsigned sBh = smem_u32(Bh), sBl = smem_u32(Bl);

    for (int kc = 0; kc < 2*DIn; kc += 32) {
        const int dirk = kc >= DIn;
        const int kcl  = kc - DIn * dirk;

        #pragma unroll
        for (int i = 0; i < 2; i++) {
            int s = tid + i * 256;
            int r = s >> 2, c8 = (s & 3) * 8;
            int m = m0 + r;
            uint4 vh = make_uint4(0,0,0,0), vl = make_uint4(0,0,0,0);
            if (m < Mrows) {
                vh = *(const uint4*)&g_ysh[dirk][m][kcl + c8];
                vl = *(const uint4*)&g_ysl[dirk][m][kcl + c8];
            }
            *(uint4*)&Ah[r*KP + c8] = vh;
            *(uint4*)&Al[r*KP + c8] = vl;
        }
        {
            int r = tid >> 2, c8 = (tid & 3) * 8;
            *(uint4*)&Bh[r*KP + c8] = *(const uint4*)&g_woh[dirk][n0 + r][kcl + c8];
            *(uint4*)&Bl[r*KP + c8] = *(const uint4*)&g_wol[dirk][n0 + r][kcl + c8];
        }
        __syncthreads();

        #pragma unroll
        for (int kk = 0; kk < 32; kk += 16) {
            unsigned bh[4][2], bl[4][2];
            #pragma unroll
            for (int ni = 0; ni < 4; ni++) {
                int row  = wn*32 + ni*8 + (lane & 7);
                int kcol = kk + ((lane >> 3) & 1) * 8;
                unsigned off = (unsigned)(row * KP + kcol) * 2;
                ldsm_x2(bh[ni][0], bh[ni][1], sBh + off);
                ldsm_x2(bl[ni][0], bl[ni][1], sBl + off);
            }
            #pragma unroll
            for (int mi = 0; mi < 2; mi++) {
                int row  = wm*32 + mi*16 + (lane & 7) + ((lane >> 3) & 1) * 8;
                int kcol = kk + (lane >> 4) * 8;
                unsigned off = (unsigned)(row * KP + kcol) * 2;
                unsigned ah[4], al[4];
                ldsm_x4(ah[0], ah[1], ah[2], ah[3], sAh + off);
                ldsm_x4(al[0], al[1], al[2], al[3], sAl + off);
                #pragma unroll
                for (int ni = 0; ni < 4; ni++) {
                    mma_bf16(acc[mi][ni], ah, bh[ni]);
                    mma_bf16(acc[mi][ni], al, bh[ni]);
                    mma_bf16(acc[mi][ni], ah, bl[ni]);
                }
            }
        }
        __syncthreads();
    }

    const int g = lane >> 2, t4 = lane & 3;
    #pragma unroll
    for (int mi = 0; mi < 2; mi++) {
        #pragma unroll
        for (int ni = 0; ni < 4; ni++) {
            int col = n0 + wn*32 + ni*8 + t4*2;
            int mr  = m0 + wm*32 + mi*16 + g;
            if (mr < Mrows)
                *(float2*)&out[(size_t)mr * Dm + col] =
                    make_float2(0.5f*acc[mi][ni][0], 0.5f*acc[mi][ni][1]);
            if (mr + 8 < Mrows)
                *(float2*)&out[(size_t)(mr+8) * Dm + col] =
                    make_float2(0.5f*acc[mi][ni][2], 0.5f*acc[mi][ni][3]);
        }
    }
}

// =====================================================================
extern "C" void kernel_launch(void* const* d_in, const int* in_sizes, int n_in,
                              void* d_out, int out_size)
{
    const float* x        = (const float*)d_in[0];
    const float* fw_in_w  = (const float*)d_in[1];
    const float* fw_cw    = (const float*)d_in[2];
    const float* fw_cb    = (const float*)d_in[3];
    const float* fw_xpw   = (const float*)d_in[4];
    const float* fw_dtw   = (const float*)d_in[5];
    const float* fw_dtb   = (const float*)d_in[6];
    const float* fw_Alog  = (const float*)d_in[7];
    const float* fw_D     = (const float*)d_in[8];
    const float* fw_ow    = (const float*)d_in[9];
    const float* bw_in_w  = (const float*)d_in[10];
    const float* bw_cw    = (const float*)d_in[11];
    const float* bw_cb    = (const float*)d_in[12];
    const float* bw_xpw   = (const float*)d_in[13];
    const float* bw_dtw   = (const float*)d_in[14];
    const float* bw_dtb   = (const float*)d_in[15];
    const float* bw_Alog  = (const float*)d_in[16];
    const float* bw_D     = (const float*)d_in[17];
    const float* bw_ow    = (const float*)d_in[18];
    float* out = (float*)d_out;

    long nblk0 = (TOTP + 255) / 256;
    k_cvt<<<(unsigned)nblk0, 256>>>(x, fw_in_w, bw_in_w, fw_ow, bw_ow,
                                    fw_xpw, bw_xpw, fw_dtw, bw_dtw);

    dim3 g1((Mrows + 127) / 128, 12, 1);
    k_gemm_in<<<g1, 256>>>();

    dim3 g2(DIn / 128, (Lseq + LCH - 1) / LCH, 2 * Bsz);
    k_conv<<<g2, 128>>>(fw_cw, fw_cb, bw_cw, bw_cb);

    dim3 g3((Mrows + 127) / 128, 2, 1);
    k_gemm_xp<<<g3, 256>>>();

    dim3 g3b((Mrows + 127) / 128, DIn / 128, 2);
    k_gemm_dt<<<g3b, 256>>>(fw_dtb, bw_dtb);

    dim3 g4(DIn / 128, NCH, 2 * Bsz);
    k_scan1<<<g4, 128>>>(fw_Alog, bw_Alog);
    k_scan2<<<g4, 128>>>(fw_Alog, fw_D, bw_Alog, bw_D);

    dim3 g5((Mrows + 127) / 128, Dm / 64, 1);
    k_gemm_out<<<g5, 256>>>(out);
}

// round 11
// speedup vs baseline: 2.5874x; 1.0251x over previous
#include <cuda_runtime.h>
#include <cuda_bf16.h>
#include <cstdint>
#include <cstddef>
#include <math.h>

#define Bsz   32
#define Lseq  577
#define Dm    192
#define DIn   384
#define DSt   8
#define RK    12
#define NPJ   28
#define Mrows (Bsz*Lseq)   // 18464
#define NCH   8            // scan chunks
#define CLEN  73           // 8*73 = 584 >= 577

// bw-direction intermediates stored at PHYSICAL sequence index (unflipped).

// ---- scratch ----
__device__ float g_xz[2][Mrows][2*DIn];   // in-proj output (x_part | z)
__device__ float g_xc[2][Mrows][DIn];     // conv+silu output (fp32, for scans)
__device__ float g_dt[2][Mrows][DIn];     // dt after softplus
__device__ float g_bc[2][Mrows][16];      // tanh(B) (8) | tanh(C) (8)
__device__ float g_tr[2][Bsz][DIn][NCH][16]; // chunk transfer: Aprod[8] | Bacc[8]

// bf16 split-precision operand buffers
__device__ __nv_bfloat16 g_xh[Mrows][Dm],  g_xl[Mrows][Dm];
__device__ __nv_bfloat16 g_wih[2][2*DIn][Dm], g_wil[2][2*DIn][Dm];
__device__ __nv_bfloat16 g_woh[2][Dm][DIn], g_wol[2][Dm][DIn];
__device__ __nv_bfloat16 g_ysh[2][Mrows][DIn], g_ysl[2][Mrows][DIn];
__device__ __nv_bfloat16 g_xch[2][Mrows][DIn], g_xcl[2][Mrows][DIn];
__device__ __nv_bfloat16 g_xph[2][32][DIn],  g_xpl[2][32][DIn];   // rows 28..31 stay zero
__device__ __nv_bfloat16 g_dwh[2][DIn][16],  g_dwl[2][DIn][16];   // cols 12..15 stay zero
__device__ __nv_bfloat16 g_dtph[2][Mrows][16], g_dtpl[2][Mrows][16]; // cols 12..15 stay zero

// ---- packed f32x2 helpers (sm_103a FFMA2 path) ----
typedef unsigned long long ull;
#define MUL2(d,a,b)   asm("mul.rn.f32x2 %0,%1,%2;"    : "=l"(d) : "l"(a), "l"(b))
#define ADD2(d,a,b)   asm("add.rn.f32x2 %0,%1,%2;"    : "=l"(d) : "l"(a), "l"(b))
#define FMA2(d,a,b,c) asm("fma.rn.f32x2 %0,%1,%2,%3;" : "=l"(d) : "l"(a), "l"(b), "l"(c))
#define SGN2 0x8000000080000000ULL

__device__ __forceinline__ ull pk2(float x, float y) {
    ull r; asm("mov.b64 %0,{%1,%2};" : "=l"(r) : "f"(x), "f"(y)); return r;
}
__device__ __forceinline__ void upk2(ull v, float& x, float& y) {
    asm("mov.b64 {%0,%1},%2;" : "=f"(x), "=f"(y) : "l"(v));
}
__device__ __forceinline__ ull pk2c(float f) {
    unsigned u = __float_as_uint(f);
    return ((ull)u << 32) | u;
}

// packed exp(x) for z = x*log2(e) already applied; both lanes <= 0, |z| < 2^21.
__device__ __forceinline__ ull fexp2z(ull z2)
{
    const ull MAG = pk2c(12582912.0f);
    const ull NMG = pk2c(-12582912.0f);
    const ull C4  = pk2c(9.6181291e-3f);
    const ull C3  = pk2c(5.5504109e-2f);
    const ull C2  = pk2c(2.4022651e-1f);
    const ull C1  = pk2c(6.9314718e-1f);
    const ull ONE = pk2c(1.0f);
    ull t2, fi2, f2, p2, nfi2;
    ADD2(t2, z2, MAG);
    ADD2(fi2, t2, NMG);
    nfi2 = fi2 ^ SGN2;
    ADD2(f2, z2, nfi2);
    p2 = C4;
    FMA2(p2, p2, f2, C3);
    FMA2(p2, p2, f2, C2);
    FMA2(p2, p2, f2, C1);
    FMA2(p2, p2, f2, ONE);
    unsigned e0 = (unsigned)t2 - 0x4B400000u;
    unsigned e1 = (unsigned)(t2 >> 32) - 0x4B400000u;
    unsigned r0 = (unsigned)p2 + (e0 << 23);
    unsigned r1 = (unsigned)(p2 >> 32) + (e1 << 23);
    return ((ull)r1 << 32) | r0;
}

// ---- tensor-core helpers ----
__device__ __forceinline__ unsigned smem_u32(const void* p) {
    return (unsigned)__cvta_generic_to_shared(p);
}
__device__ __forceinline__ void ldsm_x4(unsigned& r0, unsigned& r1, unsigned& r2, unsigned& r3,
                                        unsigned addr) {
    asm volatile("ldmatrix.sync.aligned.m8n8.x4.shared.b16 {%0,%1,%2,%3}, [%4];"
                 : "=r"(r0), "=r"(r1), "=r"(r2), "=r"(r3) : "r"(addr));
}
__device__ __forceinline__ void ldsm_x2(unsigned& r0, unsigned& r1, unsigned addr) {
    asm volatile("ldmatrix.sync.aligned.m8n8.x2.shared.b16 {%0,%1}, [%2];"
                 : "=r"(r0), "=r"(r1) : "r"(addr));
}
__device__ __forceinline__ void mma_bf16(float* c, const unsigned* a, const unsigned* b) {
    asm volatile("mma.sync.aligned.m16n8k16.row.col.f32.bf16.bf16.f32 "
                 "{%0,%1,%2,%3},{%4,%5,%6,%7},{%8,%9},{%0,%1,%2,%3};"
                 : "+f"(c[0]), "+f"(c[1]), "+f"(c[2]), "+f"(c[3])
                 : "r"(a[0]), "r"(a[1]), "r"(a[2]), "r"(a[3]), "r"(b[0]), "r"(b[1]));
}
__device__ __forceinline__ void cvt_hilo(float f0, float f1, unsigned& hi, unsigned& lo) {
    __nv_bfloat162 h = __floats2bfloat162_rn(f0, f1);
    float2 hf = __bfloat1622float2(h);
    __nv_bfloat162 l = __floats2bfloat162_rn(f0 - hf.x, f1 - hf.y);
    hi = *reinterpret_cast<unsigned*>(&h);
    lo = *reinterpret_cast<unsigned*>(&l);
}

#define KP   56
#define KP2  24

// =====================================================================
// K0a/b/c: fp32 -> bf16 hi/lo conversions (split so gemm_in = launch #3)
// =====================================================================
#define XPn   ((long)Mrows*Dm/2)
#define WIPn  ((long)(2*DIn)*Dm/2)
#define WOPn  ((long)Dm*DIn/2)
#define XPPn  ((long)NPJ*DIn/2)
#define DWPn  ((long)DIn*RK/2)

__global__ void k_cvt_x(const float* __restrict__ x)
{
    long p = (long)blockIdx.x * 256 + threadIdx.x;
    if (p >= XPn) return;
    float2 v = ((const float2*)x)[p];
    unsigned h, l; cvt_hilo(v.x, v.y, h, l);
    ((unsigned*)g_xh)[p] = h; ((unsigned*)g_xl)[p] = l;
}

__global__ void k_cvt_wi(const float* __restrict__ wi_fw, const float* __restrict__ wi_bw)
{
    long p = (long)blockIdx.x * 256 + threadIdx.x;
    if (p >= 2*WIPn) return;
    int d = p >= WIPn;
    long off = p - (long)d * WIPn;
    const float* src = d ? wi_bw : wi_fw;
    float2 v = ((const float2*)src)[off];
    unsigned h, l; cvt_hilo(v.x, v.y, h, l);
    ((unsigned*)g_wih[d])[off] = h; ((unsigned*)g_wil[d])[off] = l;
}

__global__ void k_cvt_w2(const float* __restrict__ wo_fw, const float* __restrict__ wo_bw,
                         const float* __restrict__ xp_fw, const float* __restrict__ xp_bw,
                         const float* __restrict__ dw_fw, const float* __restrict__ dw_bw)
{
    long p = (long)blockIdx.x * 256 + threadIdx.x;
    const long TOT = 2*WOPn + 2*XPPn + 2*DWPn;
    if (p >= TOT) return;
    const float* src; unsigned *dh, *dl; long soff, doff;
    if (p < WOPn)            { src = wo_fw; dh = (unsigned*)g_woh[0]; dl = (unsigned*)g_wol[0]; soff = doff = p; }
    else if (p < 2*WOPn)     { src = wo_bw; dh = (unsigned*)g_woh[1]; dl = (unsigned*)g_wol[1]; soff = doff = p - WOPn; }
    else if (p < 2*WOPn + XPPn)   { src = xp_fw; dh = (unsigned*)g_xph[0]; dl = (unsigned*)g_xpl[0]; soff = doff = p - 2*WOPn; }
    else if (p < 2*WOPn + 2*XPPn) { src = xp_bw; dh = (unsigned*)g_xph[1]; dl = (unsigned*)g_xpl[1]; soff = doff = p - 2*WOPn - XPPn; }
    else if (p < 2*WOPn + 2*XPPn + DWPn) {
        long q = p - 2*WOPn - 2*XPPn;
        long ch = q / 6, cp = q % 6;
        src = dw_fw; dh = (unsigned*)g_dwh[0]; dl = (unsigned*)g_dwl[0];
        soff = ch * 6 + cp; doff = ch * 8 + cp;
    } else {
        long q = p - 2*WOPn - 2*XPPn - DWPn;
        long ch = q / 6, cp = q % 6;
        src = dw_bw; dh = (unsigned*)g_dwh[1]; dl = (unsigned*)g_dwl[1];
        soff = ch * 6 + cp; doff = ch * 8 + cp;
    }
    float2 v = ((const float2*)src)[soff];
    unsigned h, l; cvt_hilo(v.x, v.y, h, l);
    dh[doff] = h; dl[doff] = l;
}

// =====================================================================
// K1: xz = x @ [in_w_fw | in_w_bw].T  (fused N=1536, no flips)
// =====================================================================
__global__ void __launch_bounds__(256)
k_gemm_in()
{
    __shared__ __align__(16) __nv_bfloat16 Ah[128*KP], Al[128*KP], Bh[128*KP], Bl[128*KP];

    const int m0   = blockIdx.x * 128;
    const int nblk = blockIdx.y;
    const int dir  = nblk >= 6;
    const int n0l  = (nblk - 6*dir) * 128;

    const int tid = threadIdx.x;
    const int warp = tid >> 5, lane = tid & 31;
    const int wm = warp >> 2, wn = warp & 3;

    float acc[4][4][4];
    #pragma unroll
    for (int i = 0; i < 4; i++)
        #pragma unroll
        for (int j = 0; j < 4; j++)
            #pragma unroll
            for (int r = 0; r < 4; r++) acc[i][j][r] = 0.f;

    const unsigned sAh = smem_u32(Ah), sAl = smem_u32(Al);
    const unsigned sBh = smem_u32(Bh), sBl = smem_u32(Bl);

    for (int kc = 0; kc < Dm; kc += 32) {
        #pragma unroll
        for (int i = 0; i < 2; i++) {
            int s = tid + i * 256;
            int r = s >> 2, c8 = (s & 3) * 8;
            int m = m0 + r;
            uint4 vh = make_uint4(0,0,0,0), vl = make_uint4(0,0,0,0);
            if (m < Mrows) {
                vh = *(const uint4*)&g_xh[m][kc + c8];
                vl = *(const uint4*)&g_xl[m][kc + c8];
            }
            *(uint4*)&Ah[r*KP + c8] = vh;
            *(uint4*)&Al[r*KP + c8] = vl;
            *(uint4*)&Bh[r*KP + c8] = *(const uint4*)&g_wih[dir][n0l + r][kc + c8];
            *(uint4*)&Bl[r*KP + c8] = *(const uint4*)&g_wil[dir][n0l + r][kc + c8];
        }
        __syncthreads();

        #pragma unroll
        for (int kk = 0; kk < 32; kk += 16) {
            unsigned bh[4][2], bl[4][2];
            #pragma unroll
            for (int ni = 0; ni < 4; ni++) {
                int row  = wn*32 + ni*8 + (lane & 7);
                int kcol = kk + ((lane >> 3) & 1) * 8;
                unsigned off = (unsigned)(row * KP + kcol) * 2;
                ldsm_x2(bh[ni][0], bh[ni][1], sBh + off);
                ldsm_x2(bl[ni][0], bl[ni][1], sBl + off);
            }
            #pragma unroll
            for (int mi = 0; mi < 4; mi++) {
                int row  = wm*64 + mi*16 + (lane & 7) + ((lane >> 3) & 1) * 8;
                int kcol = kk + (lane >> 4) * 8;
                unsigned off = (unsigned)(row * KP + kcol) * 2;
                unsigned ah[4], al[4];
                ldsm_x4(ah[0], ah[1], ah[2], ah[3], sAh + off);
                ldsm_x4(al[0], al[1], al[2], al[3], sAl + off);
                #pragma unroll
                for (int ni = 0; ni < 4; ni++) {
                    mma_bf16(acc[mi][ni], ah, bh[ni]);
                    mma_bf16(acc[mi][ni], al, bh[ni]);
                    mma_bf16(acc[mi][ni], ah, bl[ni]);
                }
            }
        }
        __syncthreads();
    }

    const int g = lane >> 2, t4 = lane & 3;
    #pragma unroll
    for (int mi = 0; mi < 4; mi++) {
        #pragma unroll
        for (int ni = 0; ni < 4; ni++) {
            int col = n0l + wn*32 + ni*8 + t4*2;
            int mr  = m0 + wm*64 + mi*16 + g;
            if (mr < Mrows)
                *(float2*)&g_xz[dir][mr][col]   = make_float2(acc[mi][ni][0], acc[mi][ni][1]);
            if (mr + 8 < Mrows)
                *(float2*)&g_xz[dir][mr+8][col] = make_float2(acc[mi][ni][2], acc[mi][ni][3]);
        }
    }
}

// =====================================================================
// K2: causal depthwise conv (k=4) + bias + SiLU; writes fp32 + bf16 hi/lo.
// =====================================================================
#define LCH 8
__global__ void k_conv(const float* __restrict__ cw_fw, const float* __restrict__ cb_fw,
                       const float* __restrict__ cw_bw, const float* __restrict__ cb_bw)
{
    const int ch  = blockIdx.x * 128 + threadIdx.x;
    const int l0  = blockIdx.y * LCH;
    const int b   = blockIdx.z & 31;
    const int dir = blockIdx.z >> 5;

    const float* cw = (dir ? cw_bw : cw_fw) + ch * 4;
    const float W0 = dir ? cw[3] : cw[0];
    const float W1 = dir ? cw[2] : cw[1];
    const float W2 = dir ? cw[1] : cw[2];
    const float W3 = dir ? cw[0] : cw[3];
    const float bias = (dir ? cb_bw : cb_fw)[ch];

    const size_t rbase = (size_t)b * Lseq;
    const float* __restrict__ src = &g_xz[dir][rbase][0];
    float*       __restrict__ dst = &g_xc[dir][rbase][0];
    __nv_bfloat16* __restrict__ dsth = &g_xch[dir][rbase][0];
    __nv_bfloat16* __restrict__ dstl = &g_xcl[dir][rbase][0];

    const int poff = dir ? 0 : -3;
    const int coff = dir ? 3 : 0;
    float x0 = 0.f, x1 = 0.f, x2 = 0.f;
    {
        int p0 = l0 + poff, p1 = p0 + 1, p2 = p0 + 2;
        if (p0 >= 0 && p0 < Lseq) x0 = src[(size_t)p0 * (2*DIn) + ch];
        if (p1 >= 0 && p1 < Lseq) x1 = src[(size_t)p1 * (2*DIn) + ch];
        if (p2 >= 0 && p2 < Lseq) x2 = src[(size_t)p2 * (2*DIn) + ch];
    }

    #pragma unroll
    for (int i = 0; i < LCH; i++) {
        int l = l0 + i;
        int q = l + coff;
        float x3 = (q < Lseq) ? src[(size_t)q * (2*DIn) + ch] : 0.f;
        float v = fmaf(W0, x0, fmaf(W1, x1, fmaf(W2, x2, fmaf(W3, x3, bias))));
        v = v / (1.f + __expf(-v));
        if (l < Lseq) {
            size_t o = (size_t)l * DIn + ch;
            dst[o] = v;
            __nv_bfloat16 h = __float2bfloat16(v);
            dsth[o] = h;
            dstl[o] = __float2bfloat16(v - __bfloat162float(h));
        }
        x0 = x1; x1 = x2; x2 = x3;
    }
}

// =====================================================================
// K3a: x_proj GEMM (N=28 pad 32); epilogue: dtp hi/lo + tanh -> g_bc.
// =====================================================================
__global__ void __launch_bounds__(256)
k_gemm_xp()
{
    __shared__ __align__(16) __nv_bfloat16 Ah[128*KP], Al[128*KP], Bh[32*KP], Bl[32*KP];

    const int m0  = blockIdx.x * 128;
    const int dir = blockIdx.y;

    const int tid = threadIdx.x;
    const int warp = tid >> 5, lane = tid & 31;

    float acc[4][4];
    #pragma unroll
    for (int j = 0; j < 4; j++)
        #pragma unroll
        for (int r = 0; r < 4; r++) acc[j][r] = 0.f;

    const unsigned sAh = smem_u32(Ah), sAl = smem_u32(Al);
    const unsigned sBh = smem_u32(Bh), sBl = smem_u32(Bl);

    for (int kc = 0; kc < DIn; kc += 32) {
        #pragma unroll
        for (int i = 0; i < 2; i++) {
            int s = tid + i * 256;
            int r = s >> 2, c8 = (s & 3) * 8;
            int m = m0 + r;
            uint4 vh = make_uint4(0,0,0,0), vl = make_uint4(0,0,0,0);
            if (m < Mrows) {
                vh = *(const uint4*)&g_xch[dir][m][kc + c8];
                vl = *(const uint4*)&g_xcl[dir][m][kc + c8];
            }
            *(uint4*)&Ah[r*KP + c8] = vh;
            *(uint4*)&Al[r*KP + c8] = vl;
        }
        if (tid < 128) {
            int r = tid >> 2, c8 = (tid & 3) * 8;
            *(uint4*)&Bh[r*KP + c8] = *(const uint4*)&g_xph[dir][r][kc + c8];
            *(uint4*)&Bl[r*KP + c8] = *(const uint4*)&g_xpl[dir][r][kc + c8];
        }
        __syncthreads();

        #pragma unroll
        for (int kk = 0; kk < 32; kk += 16) {
            unsigned bh[4][2], bl[4][2];
            #pragma unroll
            for (int ni = 0; ni < 4; ni++) {
                int row  = ni*8 + (lane & 7);
                int kcol = kk + ((lane >> 3) & 1) * 8;
                unsigned off = (unsigned)(row * KP + kcol) * 2;
                ldsm_x2(bh[ni][0], bh[ni][1], sBh + off);
                ldsm_x2(bl[ni][0], bl[ni][1], sBl + off);
            }
            {
                int row  = warp*16 + (lane & 7) + ((lane >> 3) & 1) * 8;
                int kcol = kk + (lane >> 4) * 8;
                unsigned off = (unsigned)(row * KP + kcol) * 2;
                unsigned ah[4], al[4];
                ldsm_x4(ah[0], ah[1], ah[2], ah[3], sAh + off);
                ldsm_x4(al[0], al[1], al[2], al[3], sAl + off);
                #pragma unroll
                for (int ni = 0; ni < 4; ni++) {
                    mma_bf16(acc[ni], ah, bh[ni]);
                    mma_bf16(acc[ni], al, bh[ni]);
                    mma_bf16(acc[ni], ah, bl[ni]);
                }
            }
        }
        __syncthreads();
    }

    const int g = lane >> 2, t4 = lane & 3;
    #pragma unroll
    for (int ni = 0; ni < 4; ni++) {
        int col = ni*8 + t4*2;
        #pragma unroll
        for (int half = 0; half < 2; half++) {
            int mr = m0 + warp*16 + g + half*8;
            if (mr >= Mrows) continue;
            float v0 = acc[ni][half*2], v1 = acc[ni][half*2 + 1];
            if (col < RK) {
                unsigned h, l;
                cvt_hilo(v0, v1, h, l);
                *(unsigned*)&g_dtph[dir][mr][col] = h;
                *(unsigned*)&g_dtpl[dir][mr][col] = l;
            } else if (col < NPJ) {
                *(float2*)&g_bc[dir][mr][col - RK] = make_float2(tanhf(v0), tanhf(v1));
            }
        }
    }
}

// =====================================================================
// K3b: dt GEMM: dt = softplus(dtp @ dt_w.T + dt_b) + 1e-4  (K=12 pad 16)
// =====================================================================
__device__ __forceinline__ float softplus_stable(float v) {
    return v > 20.f ? v : log1pf(expf(v));
}

__global__ void __launch_bounds__(256)
k_gemm_dt(const float* __restrict__ db_fw, const float* __restrict__ db_bw)
{
    __shared__ __align__(16) __nv_bfloat16 Ah[128*KP2], Al[128*KP2], Bh[128*KP2], Bl[128*KP2];

    const int m0  = blockIdx.x * 128;
    const int n0  = blockIdx.y * 128;
    const int dir = blockIdx.z;
    const float* __restrict__ db = dir ? db_bw : db_fw;

    const int tid = threadIdx.x;
    const int warp = tid >> 5, lane = tid & 31;
    const int wm = warp >> 2, wn = warp & 3;

    float acc[4][4][4];
    #pragma unroll
    for (int i = 0; i < 4; i++)
        #pragma unroll
        for (int j = 0; j < 4; j++)
            #pragma unroll
            for (int r = 0; r < 4; r++) acc[i][j][r] = 0.f;

    const unsigned sAh = smem_u32(Ah), sAl = smem_u32(Al);
    const unsigned sBh = smem_u32(Bh), sBl = smem_u32(Bl);

    {
        int r = tid >> 1, c8 = (tid & 1) * 8;
        int m = m0 + r;
        uint4 vh = make_uint4(0,0,0,0), vl = make_uint4(0,0,0,0);
        if (m < Mrows) {
            vh = *(const uint4*)&g_dtph[dir][m][c8];
            vl = *(const uint4*)&g_dtpl[dir][m][c8];
        }
        *(uint4*)&Ah[r*KP2 + c8] = vh;
        *(uint4*)&Al[r*KP2 + c8] = vl;
        *(uint4*)&Bh[r*KP2 + c8] = *(const uint4*)&g_dwh[dir][n0 + r][c8];
        *(uint4*)&Bl[r*KP2 + c8] = *(const uint4*)&g_dwl[dir][n0 + r][c8];
    }
    __syncthreads();

    {
        unsigned bh[4][2], bl[4][2];
        #pragma unroll
        for (int ni = 0; ni < 4; ni++) {
            int row  = wn*32 + ni*8 + (lane & 7);
            int kcol = ((lane >> 3) & 1) * 8;
            unsigned off = (unsigned)(row * KP2 + kcol) * 2;
            ldsm_x2(bh[ni][0], bh[ni][1], sBh + off);
            ldsm_x2(bl[ni][0], bl[ni][1], sBl + off);
        }
        #pragma unroll
        for (int mi = 0; mi < 4; mi++) {
            int row  = wm*64 + mi*16 + (lane & 7) + ((lane >> 3) & 1) * 8;
            int kcol = (lane >> 4) * 8;
            unsigned off = (unsigned)(row * KP2 + kcol) * 2;
            unsigned ah[4], al[4];
            ldsm_x4(ah[0], ah[1], ah[2], ah[3], sAh + off);
            ldsm_x4(al[0], al[1], al[2], al[3], sAl + off);
            #pragma unroll
            for (int ni = 0; ni < 4; ni++) {
                mma_bf16(acc[mi][ni], ah, bh[ni]);
                mma_bf16(acc[mi][ni], al, bh[ni]);
                mma_bf16(acc[mi][ni], ah, bl[ni]);
            }
        }
    }

    const int g = lane >> 2, t4 = lane & 3;
    #pragma unroll
    for (int mi = 0; mi < 4; mi++) {
        #pragma unroll
        for (int ni = 0; ni < 4; ni++) {
            int col = n0 + wn*32 + ni*8 + t4*2;
            float2 bb = *(const float2*)&db[col];
            #pragma unroll
            for (int half = 0; half < 2; half++) {
                int mr = m0 + wm*64 + mi*16 + g + half*8;
                if (mr >= Mrows) continue;
                float v0 = softplus_stable(acc[mi][ni][half*2]     + bb.x) + 1e-4f;
                float v1 = softplus_stable(acc[mi][ni][half*2 + 1] + bb.y) + 1e-4f;
                *(float2*)&g_dt[dir][mr][col] = make_float2(v0, v1);
            }
        }
    }
}

// =====================================================================
// K4a: scan phase 1 — chunk transfer (Aprod, Bacc), packed f32x2.
// =====================================================================
__global__ void k_scan1(const float* __restrict__ Al_fw, const float* __restrict__ Al_bw)
{
    const int ch    = blockIdx.x * 128 + threadIdx.x;
    const int chunk = blockIdx.y;
    const int b     = blockIdx.z & 31;
    const int dir   = blockIdx.z >> 5;

    const float* Alog = (dir ? Al_bw : Al_fw) + (size_t)ch * DSt;
    ull a2[4];   // -exp(Alog)*log2(e), packed pairs
    #pragma unroll
    for (int i = 0; i < 4; i++)
        a2[i] = pk2(-expf(Alog[2*i]) * 1.4426950408889634f,
                    -expf(Alog[2*i+1]) * 1.4426950408889634f);

    const size_t rbase = (size_t)b * Lseq;
    const float* __restrict__ dtp = &g_dt[dir][rbase][0];
    const float* __restrict__ xcp = &g_xc[dir][rbase][0];
    const ulonglong2* __restrict__ bcq = (const ulonglong2*)&g_bc[dir][rbase][0];

    const int l0 = chunk * CLEN;
    const int l1 = min(l0 + CLEN, Lseq);

    ull st2[4], Ap2[4];
    const ull ONE2 = pk2c(1.0f);
    #pragma unroll
    for (int i = 0; i < 4; i++) { st2[i] = 0ULL; Ap2[i] = ONE2; }

    for (int l = l0; l < l1; l++) {
        const int pl = dir ? (Lseq - 1 - l) : l;
        const size_t off = (size_t)pl * DIn + ch;
        const float dt = dtp[off];
        const float xx = xcp[off];
        const ull dt2 = pk2(dt, dt);
        const ull xx2 = pk2(xx, xx);
        ulonglong2 bq0 = bcq[(size_t)pl*4 + 0];   // bv[0..3]
        ulonglong2 bq1 = bcq[(size_t)pl*4 + 1];   // bv[4..7]
        ull bv2[4] = {bq0.x, bq0.y, bq1.x, bq1.y};

        #pragma unroll
        for (int i = 0; i < 4; i++) {
            ull z2; MUL2(z2, dt2, a2[i]);
            ull da2 = fexp2z(z2);
            ull bx2; MUL2(bx2, bv2[i], xx2);
            ull nb2 = bx2 ^ SGN2;
            ull t2; ADD2(t2, st2[i], nb2);
            FMA2(st2[i], da2, t2, bx2);
            MUL2(Ap2[i], Ap2[i], da2);
        }
    }

    ull* tr = (ull*)&g_tr[dir][b][ch][chunk][0];
    #pragma unroll
    for (int i = 0; i < 4; i++) { tr[i] = Ap2[i]; tr[4 + i] = st2[i]; }
}

// =====================================================================
// K4b: scan phase 2+3 — compose init, replay with y*silu(z), packed.
// =====================================================================
__global__ void k_scan2(const float* __restrict__ Al_fw, const float* __restrict__ Dk_fw,
                        const float* __restrict__ Al_bw, const float* __restrict__ Dk_bw)
{
    const int ch    = blockIdx.x * 128 + threadIdx.x;
    const int chunk = blockIdx.y;
    const int b     = blockIdx.z & 31;
    const int dir   = blockIdx.z >> 5;

    const float* Alog = (dir ? Al_bw : Al_fw) + (size_t)ch * DSt;
    ull a2[4];
    #pragma unroll
    for (int i = 0; i < 4; i++)
        a2[i] = pk2(-expf(Alog[2*i]) * 1.4426950408889634f,
                    -expf(Alog[2*i+1]) * 1.4426950408889634f);
    const float Dsk = (dir ? Dk_bw : Dk_fw)[ch];

    ull st2[4];
    #pragma unroll
    for (int i = 0; i < 4; i++) st2[i] = 0ULL;
    {
        const ull* tr = (const ull*)&g_tr[dir][b][ch][0][0];
        for (int c = 0; c < chunk; c++) {
            const ull* t = tr + c * 8;
            #pragma unroll
            for (int i = 0; i < 4; i++)
                FMA2(st2[i], t[i], st2[i], t[4 + i]);
        }
    }

    const size_t rbase = (size_t)b * Lseq;
    const float* __restrict__ dtp = &g_dt[dir][rbase][0];
    const float* __restrict__ xcp = &g_xc[dir][rbase][0];
    const float* __restrict__ zp  = &g_xz[dir][rbase][DIn];
    const ulonglong2* __restrict__ bcq = (const ulonglong2*)&g_bc[dir][rbase][0];
    __nv_bfloat16* __restrict__ ysh = &g_ysh[dir][rbase][0];
    __nv_bfloat16* __restrict__ ysl = &g_ysl[dir][rbase][0];

    const int l0 = chunk * CLEN;
    const int l1 = min(l0 + CLEN, Lseq);

    for (int l = l0; l < l1; l++) {
        const int pl = dir ? (Lseq - 1 - l) : l;
        const size_t off = (size_t)pl * DIn + ch;
        const float dt = dtp[off];
        const float xx = xcp[off];
        const ull dt2 = pk2(dt, dt);
        const ull xx2 = pk2(xx, xx);
        ulonglong2 bq0 = bcq[(size_t)pl*4 + 0];
        ulonglong2 bq1 = bcq[(size_t)pl*4 + 1];
        ulonglong2 cq0 = bcq[(size_t)pl*4 + 2];
        ulonglong2 cq1 = bcq[(size_t)pl*4 + 3];
        ull bv2[4] = {bq0.x, bq0.y, bq1.x, bq1.y};
        ull cv2[4] = {cq0.x, cq0.y, cq1.x, cq1.y};

        ull acc2 = 0ULL;
        #pragma unroll
        for (int i = 0; i < 4; i++) {
            ull z2; MUL2(z2, dt2, a2[i]);
            ull da2 = fexp2z(z2);
            ull bx2; MUL2(bx2, bv2[i], xx2);
            ull nb2 = bx2 ^ SGN2;
            ull t2; ADD2(t2, st2[i], nb2);
            FMA2(st2[i], da2, t2, bx2);
            FMA2(acc2, st2[i], cv2[i], acc2);
        }
        float ax, ay; upk2(acc2, ax, ay);
        float y = fmaf(Dsk, xx, ax + ay);
        float z = zp[(size_t)pl * (2*DIn) + ch];
        float sz = z / (1.f + __expf(-z));
        float v = y * sz;
        __nv_bfloat16 h = __float2bfloat16(v);
        ysh[off] = h;
        ysl[off] = __float2bfloat16(v - __bfloat162float(h));
    }
}

// =====================================================================
// K5: out = 0.5*( ys_fw @ ow_fw.T + ys_bw @ ow_bw.T )  (fused K=768)
// =====================================================================
__global__ void __launch_bounds__(256)
k_gemm_out(float* __restrict__ out)
{
    __shared__ __align__(16) __nv_bfloat16 Ah[128*KP], Al[128*KP], Bh[64*KP], Bl[64*KP];

    const int m0 = blockIdx.x * 128;
    const int n0 = blockIdx.y * 64;

    const int tid = threadIdx.x;
    const int warp = tid >> 5, lane = tid & 31;
    const int wm = warp >> 1, wn = warp & 1;

    float acc[2][4][4];
    #pragma unroll
    for (int i = 0; i < 2; i++)
        #pragma unroll
        for (int j = 0; j < 4; j++)
            #pragma unroll
            for (int r = 0; r < 4; r++) acc[i][j][r] = 0.f;

    const unsigned sAh = smem_u32(Ah), sAl = smem_u32(Al);
    const unsigned sBh = smem_u32(Bh), sBl = smem_u32(Bl);

    for (int kc = 0; kc < 2*DIn; kc += 32) {
        const int dirk = kc >= DIn;
        const int kcl  = kc - DIn * dirk;

        #pragma unroll
        for (int i = 0; i < 2; i++) {
            int s = tid + i * 256;
            int r = s >> 2, c8 = (s & 3) * 8;
            int m = m0 + r;
            uint4 vh = make_uint4(0,0,0,0), vl = make_uint4(0,0,0,0);
            if (m < Mrows) {
                vh = *(const uint4*)&g_ysh[dirk][m][kcl + c8];
                vl = *(const uint4*)&g_ysl[dirk][m][kcl + c8];
            }
            *(uint4*)&Ah[r*KP + c8] = vh;
            *(uint4*)&Al[r*KP + c8] = vl;
        }
        {
            int r = tid >> 2, c8 = (tid & 3) * 8;
            *(uint4*)&Bh[r*KP + c8] = *(const uint4*)&g_woh[dirk][n0 + r][kcl + c8];
            *(uint4*)&Bl[r*KP + c8] = *(const uint4*)&g_wol[dirk][n0 + r][kcl + c8];
        }
        __syncthreads();

        #pragma unroll
        for (int kk = 0; kk < 32; kk += 16) {
            unsigned bh[4][2], bl[4][2];
            #pragma unroll
            for (int ni = 0; ni < 4; ni++) {
                int row  = wn*32 + ni*8 + (lane & 7);
                int kcol = kk + ((lane >> 3) & 1) * 8;
                unsigned off = (unsigned)(row * KP + kcol) * 2;
                ldsm_x2(bh[ni][0], bh[ni][1], sBh + off);
                ldsm_x2(bl[ni][0], bl[ni][1], sBl + off);
            }
            #pragma unroll
            for (int mi = 0; mi < 2; mi++) {
                int row  = wm*32 + mi*16 + (lane & 7) + ((lane >> 3) & 1) * 8;
                int kcol = kk + (lane >> 4) * 8;
                unsigned off = (unsigned)(row * KP + kcol) * 2;
                unsigned ah[4], al[4];
                ldsm_x4(ah[0], ah[1], ah[2], ah[3], sAh + off);
                ldsm_x4(al[0], al[1], al[2], al[3], sAl + off);
                #pragma unroll
                for (int ni = 0; ni < 4; ni++) {
                    mma_bf16(acc[mi][ni], ah, bh[ni]);
                    mma_bf16(acc[mi][ni], al, bh[ni]);
                    mma_bf16(acc[mi][ni], ah, bl[ni]);
                }
            }
        }
        __syncthreads();
    }

    const int g = lane >> 2, t4 = lane & 3;
    #pragma unroll
    for (int mi = 0; mi < 2; mi++) {
        #pragma unroll
        for (int ni = 0; ni < 4; ni++) {
            int col = n0 + wn*32 + ni*8 + t4*2;
            int mr  = m0 + wm*32 + mi*16 + g;
            if (mr < Mrows)
                *(float2*)&out[(size_t)mr * Dm + col] =
                    make_float2(0.5f*acc[mi][ni][0], 0.5f*acc[mi][ni][1]);
            if (mr + 8 < Mrows)
                *(float2*)&out[(size_t)(mr+8) * Dm + col] =
                    make_float2(0.5f*acc[mi][ni][2], 0.5f*acc[mi][ni][3]);
        }
    }
}

// =====================================================================
extern "C" void kernel_launch(void* const* d_in, const int* in_sizes, int n_in,
                              void* d_out, int out_size)
{
    const float* x        = (const float*)d_in[0];
    const float* fw_in_w  = (const float*)d_in[1];
    const float* fw_cw    = (const float*)d_in[2];
    const float* fw_cb    = (const float*)d_in[3];
    const float* fw_xpw   = (const float*)d_in[4];
    const float* fw_dtw   = (const float*)d_in[5];
    const float* fw_dtb   = (const float*)d_in[6];
    const float* fw_Alog  = (const float*)d_in[7];
    const float* fw_D     = (const float*)d_in[8];
    const float* fw_ow    = (const float*)d_in[9];
    const float* bw_in_w  = (const float*)d_in[10];
    const float* bw_cw    = (const float*)d_in[11];
    const float* bw_cb    = (const float*)d_in[12];
    const float* bw_xpw   = (const float*)d_in[13];
    const float* bw_dtw   = (const float*)d_in[14];
    const float* bw_dtb   = (const float*)d_in[15];
    const float* bw_Alog  = (const float*)d_in[16];
    const float* bw_D     = (const float*)d_in[17];
    const float* bw_ow    = (const float*)d_in[18];
    float* out = (float*)d_out;

    k_cvt_x<<<(unsigned)((XPn + 255) / 256), 256>>>(x);
    k_cvt_wi<<<(unsigned)((2*WIPn + 255) / 256), 256>>>(fw_in_w, bw_in_w);
    k_cvt_w2<<<(unsigned)((2*WOPn + 2*XPPn + 2*DWPn + 255) / 256), 256>>>(
        fw_ow, bw_ow, fw_xpw, bw_xpw, fw_dtw, bw_dtw);

    dim3 g1((Mrows + 127) / 128, 12, 1);
    k_gemm_in<<<g1, 256>>>();                           // launch index 3 (profiled)

    dim3 g2(DIn / 128, (Lseq + LCH - 1) / LCH, 2 * Bsz);
    k_conv<<<g2, 128>>>(fw_cw, fw_cb, bw_cw, bw_cb);

    dim3 g3((Mrows + 127) / 128, 2, 1);
    k_gemm_xp<<<g3, 256>>>();

    dim3 g3b((Mrows + 127) / 128, DIn / 128, 2);
    k_gemm_dt<<<g3b, 256>>>(fw_dtb, bw_dtb);

    dim3 g4(DIn / 128, NCH, 2 * Bsz);
    k_scan1<<<g4, 128>>>(fw_Alog, bw_Alog);
    k_scan2<<<g4, 128>>>(fw_Alog, fw_D, bw_Alog, bw_D);

    dim3 g5((Mrows + 127) / 128, Dm / 64, 1);
    k_gemm_out<<<g5, 256>>>(out);
}